// round 2
// baseline (speedup 1.0000x reference)
#include <cuda_runtime.h>
#include <math.h>

#define BATCH 8
#define CDIM  256
#define NQD   1024
#define NKD   4096
#define SKEYS 16
#define HEADS 8
#define FFDIM 2048
#define DHD   32
#define BQTOT (BATCH*NQD)
#define CP    257   // padded smem stride

// ---------------- scratch (device globals; no allocation allowed) ----------------
__device__ float g_keyT[BATCH*NKD*CDIM];   // key transposed (B, NK, C)
__device__ float g_qtok[BQTOT*CDIM];       // transposed query tokens
__device__ float g_qin [BQTOT*CDIM];       // qtok + qpe
__device__ float g_qh  [BQTOT*CDIM];       // q projection
__device__ int   g_sidx[BQTOT*SKEYS];      // gathered key indices (-1 = masked)
__device__ float g_vwT [CDIM*CDIM];        // v_w transposed
__device__ float g_ao  [BQTOT*CDIM];       // attention output (pre o-proj)
__device__ float g_res1[BQTOT*CDIM];       // o-proj output
__device__ float g_x   [BQTOT*CDIM];       // after LN1
__device__ float g_ff  [BQTOT*FFDIM];      // FFN hidden
__device__ float g_y   [BQTOT*CDIM];       // FFN out

// ---------------- transpose key (B,C,NK) -> (B,NK,C) ----------------
__global__ void k_transpose_key(const float* __restrict__ key) {
    __shared__ float tile[32][33];
    int b = blockIdx.z;
    int c0 = blockIdx.y * 32, n0 = blockIdx.x * 32;
    int tx = threadIdx.x, ty = threadIdx.y;
#pragma unroll
    for (int j = 0; j < 4; j++)
        tile[ty + 8*j][tx] = key[(b*CDIM + c0 + ty + 8*j)*NKD + n0 + tx];
    __syncthreads();
#pragma unroll
    for (int j = 0; j < 4; j++)
        g_keyT[(b*NKD + n0 + ty + 8*j)*CDIM + c0 + tx] = tile[tx][ty + 8*j];
}

// ---------------- build qtok + qin (query transpose + qpe) ----------------
__global__ void k_build_q(const float* __restrict__ query,
                          const float* __restrict__ query_pos,
                          const float* __restrict__ qpe_w,
                          const float* __restrict__ qpe_b) {
    __shared__ float tile[32][33];
    int b = blockIdx.z;
    int c0 = blockIdx.y * 32, n0 = blockIdx.x * 32;
    int tx = threadIdx.x, ty = threadIdx.y;
#pragma unroll
    for (int j = 0; j < 4; j++)
        tile[ty + 8*j][tx] = query[(b*CDIM + c0 + ty + 8*j)*NQD + n0 + tx];
    __syncthreads();
#pragma unroll
    for (int j = 0; j < 4; j++) {
        int nq = n0 + ty + 8*j, c = c0 + tx;
        int bq = b*NQD + nq;
        float qt = tile[tx][ty + 8*j];
        const float* qp = query_pos + (size_t)bq*6;
        float pe = qpe_b[c];
#pragma unroll
        for (int jj = 0; jj < 6; jj++) pe += qp[jj] * qpe_w[c*6 + jj];
        g_qtok[bq*CDIM + c] = qt;
        g_qin [bq*CDIM + c] = qt + pe;
    }
}

// ---------------- transpose v_w (256x256) ----------------
__global__ void k_transpose_vw(const float* __restrict__ v_w) {
    __shared__ float tile[32][33];
    int n0 = blockIdx.y * 32, c0 = blockIdx.x * 32;
    int tx = threadIdx.x, ty = threadIdx.y;
#pragma unroll
    for (int j = 0; j < 4; j++)
        tile[ty + 8*j][tx] = v_w[(n0 + ty + 8*j)*CDIM + c0 + tx];
    __syncthreads();
#pragma unroll
    for (int j = 0; j < 4; j++)
        g_vwT[(c0 + ty + 8*j)*CDIM + n0 + tx] = tile[tx][ty + 8*j];
}

// ---------------- box query: first 16 inside-box keys, in index order ----------------
__global__ void k_boxquery(const float* __restrict__ key_pos,
                           const float* __restrict__ query_pos) {
    __shared__ float kp[NKD*3];   // exactly 48KB
    int b = blockIdx.y;
    int t = threadIdx.x;
#pragma unroll
    for (int i = 0; i < 48; i++)
        kp[t + 256*i] = key_pos[(size_t)b*NKD*3 + t + 256*i];
    __syncthreads();

    int w = t >> 5, lane = t & 31;
    int q = blockIdx.x * 8 + w;
    int bq = b*NQD + q;
    const float* qp = query_pos + (size_t)bq*6;
    float cx = qp[0], cy = qp[1], cz = qp[2];
    float hx = 0.5f*qp[3], hy = 0.5f*qp[4], hz = 0.5f*qp[5];

    int count = 0;
    for (int base = 0; base < NKD && count < SKEYS; base += 32) {
        int k = base + lane;
        float dx = fabsf(kp[k*3+0]-cx);
        float dy = fabsf(kp[k*3+1]-cy);
        float dz = fabsf(kp[k*3+2]-cz);
        bool inside = (dx <= hx) && (dy <= hy) && (dz <= hz);
        unsigned bal = __ballot_sync(0xffffffffu, inside);
        int nb = __popc(bal);
        if (inside) {
            int rank = __popc(bal & ((1u << lane) - 1u));
            if (count + rank < SKEYS) g_sidx[bq*SKEYS + count + rank] = k;
        }
        count += nb;
        if (count > SKEYS) count = SKEYS;
    }
    if (lane < SKEYS && lane >= count)
        g_sidx[bq*SKEYS + lane] = (lane == 0) ? 0 : -1;
}

// ---------------- generic GEMM: C = A(M,K) * W(N,K)^T + bias, optional relu ----------
template<int RELU>
__global__ void k_gemm(const float* __restrict__ A, const float* __restrict__ W,
                       const float* __restrict__ bias, float* __restrict__ Cout,
                       int M, int N, int K) {
    __shared__ float As[16][128];
    __shared__ float Ws[16][128];
    int t = threadIdx.x;
    int tx = t & 15, ty = t >> 4;
    int bm = blockIdx.y * 128, bn = blockIdx.x * 128;
    float acc[8][8];
#pragma unroll
    for (int i = 0; i < 8; i++)
#pragma unroll
        for (int j = 0; j < 8; j++) acc[i][j] = 0.f;

    for (int k0 = 0; k0 < K; k0 += 16) {
#pragma unroll
        for (int i = 0; i < 8; i++) {
            int lin = t + 256*i;
            int m = lin >> 4, k = lin & 15;
            As[k][m] = A[(size_t)(bm + m)*K + k0 + k];
            Ws[k][m] = W[(size_t)(bn + m)*K + k0 + k];
        }
        __syncthreads();
#pragma unroll
        for (int kk = 0; kk < 16; kk++) {
            float a[8], bb[8];
#pragma unroll
            for (int i = 0; i < 8; i++) a[i]  = As[kk][ty*8 + i];
#pragma unroll
            for (int j = 0; j < 8; j++) bb[j] = Ws[kk][tx*8 + j];
#pragma unroll
            for (int i = 0; i < 8; i++)
#pragma unroll
                for (int j = 0; j < 8; j++) acc[i][j] += a[i]*bb[j];
        }
        __syncthreads();
    }
#pragma unroll
    for (int i = 0; i < 8; i++)
#pragma unroll
        for (int j = 0; j < 8; j++) {
            int m = bm + ty*8 + i, n = bn + tx*8 + j;
            float v = acc[i][j] + bias[n];
            if (RELU) v = fmaxf(v, 0.f);
            Cout[(size_t)m*N + n] = v;
        }
}

// ---------------- fused gather + attention (8 queries per block) ----------------
__global__ void k_attn(const float* __restrict__ key_pos,
                       const float* __restrict__ query_pos,
                       const float* __restrict__ kpe_w,
                       const float* __restrict__ kpe_b,
                       const float* __restrict__ k_w,
                       const float* __restrict__ v_b) {
    extern __shared__ float sm[];
    float* kv = sm;                     // [8][16][CP]
    float* mb = kv + 8*16*CP;           // [8][8][CP]   (m, later wkv)
    float* qs = mb + 8*8*CP;            // [8][256]
    float* at = qs + 8*256;             // [8][8][16]   (scores, then attn)
    float* qc = at + 8*128;             // [8][4]
    int*  sid = (int*)(qc + 32);        // [8][16]

    int t = threadIdx.x, lane = t & 31, w = t >> 5;
    int bq0 = blockIdx.x * 8;
    int b = bq0 >> 10;   // NQ=1024

    if (t < 128) sid[t] = g_sidx[bq0*SKEYS + t];
    if (t < 24) { int g = t/3, j = t%3; qc[g*4 + j] = query_pos[(size_t)(bq0+g)*6 + j]; }
#pragma unroll
    for (int i = 0; i < 8; i++) qs[t + 256*i] = g_qh[(size_t)bq0*CDIM + t + 256*i];
    __syncthreads();

    // phase 1: gather kv = keyT[idx] + kpe(gxyz)
    {
        int g = w;
        float qcx = qc[g*4+0], qcy = qc[g*4+1], qcz = qc[g*4+2];
        for (int s = 0; s < SKEYS; s++) {
            int v = sid[g*16 + s];
            int kidx = v < 0 ? 0 : v;
            int base = b*NKD + kidx;
            float gx = key_pos[base*3+0] - qcx;
            float gy = key_pos[base*3+1] - qcy;
            float gz = key_pos[base*3+2] - qcz;
            const float* krow = g_keyT + (size_t)base*CDIM;
            float* kvrow = kv + (g*16 + s)*CP;
#pragma unroll
            for (int i = 0; i < 8; i++) {
                int c = lane + 32*i;
                float pe = kpe_b[c] + gx*kpe_w[c*3] + gy*kpe_w[c*3+1] + gz*kpe_w[c*3+2];
                kvrow[c] = krow[c] + pe;
            }
        }
    }
    __syncthreads();

    // phase 2: m[g][h][c] = sum_d k_w[h*32+d, c] * qh[g][h*32+d]
    {
        int h = w;
        float acc[8][8];   // [cc][g]
#pragma unroll
        for (int i = 0; i < 8; i++)
#pragma unroll
            for (int j = 0; j < 8; j++) acc[i][j] = 0.f;
        for (int d = 0; d < 32; d++) {
            float qv[8];
#pragma unroll
            for (int g = 0; g < 8; g++) qv[g] = qs[g*256 + h*32 + d];
            const float* wr = k_w + (size_t)(h*32 + d)*CDIM;
#pragma unroll
            for (int cc = 0; cc < 8; cc++) {
                float wv = wr[lane + 32*cc];
#pragma unroll
                for (int g = 0; g < 8; g++) acc[cc][g] += wv * qv[g];
            }
        }
#pragma unroll
        for (int cc = 0; cc < 8; cc++)
#pragma unroll
            for (int g = 0; g < 8; g++)
                mb[(g*8 + h)*CP + lane + 32*cc] = acc[cc][g];
    }
    __syncthreads();

    // phase 3: scores[g][h][s] = m[g][h] . kv[g][s]
    {
        int g = w, h = lane >> 2, s0 = lane & 3;
        float sc[4] = {0.f, 0.f, 0.f, 0.f};
        const float* mrow = mb + (g*8 + h)*CP;
        for (int c = 0; c < 256; c++) {
            float mv = mrow[c];
#pragma unroll
            for (int j = 0; j < 4; j++)
                sc[j] += mv * kv[(g*16 + s0 + 4*j)*CP + c];
        }
#pragma unroll
        for (int j = 0; j < 4; j++) at[(g*8 + h)*16 + s0 + 4*j] = sc[j];
    }
    __syncthreads();

    // phase 4: masked softmax (one thread per (g,h))
    if (t < 64) {
        int g = t >> 3, h = t & 7;
        float* row = at + (g*8 + h)*16;
        const int* sg = sid + g*16;
        const float scl = 0.17677669529663687f;   // 1/sqrt(32)
        float sv[16];
        float mx = -3.0e38f;
#pragma unroll
        for (int s = 0; s < 16; s++) {
            sv[s] = (sg[s] < 0) ? -3.0e38f : row[s]*scl;
            mx = fmaxf(mx, sv[s]);
        }
        float sum = 0.f;
#pragma unroll
        for (int s = 0; s < 16; s++) {
            float e = (sg[s] < 0) ? 0.f : expf(sv[s] - mx);
            sv[s] = e; sum += e;
        }
        float inv = 1.f/sum;
#pragma unroll
        for (int s = 0; s < 16; s++) row[s] = sv[s]*inv;
    }
    __syncthreads();

    // phase 5: wkv[g][h][c] = sum_s attn[g][h][s] * kv[g][s][c]  (into mb)
    {
        int g = w;
        float acc[8][8];   // [cc][h]
#pragma unroll
        for (int i = 0; i < 8; i++)
#pragma unroll
            for (int j = 0; j < 8; j++) acc[i][j] = 0.f;
        for (int s = 0; s < 16; s++) {
            float av[8];
#pragma unroll
            for (int h = 0; h < 8; h++) av[h] = at[(g*8 + h)*16 + s];
            const float* kvrow = kv + (g*16 + s)*CP;
#pragma unroll
            for (int cc = 0; cc < 8; cc++) {
                float kvv = kvrow[lane + 32*cc];
#pragma unroll
                for (int h = 0; h < 8; h++) acc[cc][h] += av[h]*kvv;
            }
        }
#pragma unroll
        for (int cc = 0; cc < 8; cc++)
#pragma unroll
            for (int h = 0; h < 8; h++)
                mb[(g*8 + h)*CP + lane + 32*cc] = acc[cc][h];
    }
    __syncthreads();

    // phase 6: ao[g][h*32+d] = sum_c wkv[g][h][c] * v_wT[c][h*32+d] + v_b
    {
        int h = w, d = lane;
        float acc[8];
#pragma unroll
        for (int g = 0; g < 8; g++) acc[g] = 0.f;
        const float* wcol = g_vwT + h*32 + d;
        for (int c = 0; c < 256; c++) {
            float wv = wcol[(size_t)c*CDIM];
#pragma unroll
            for (int g = 0; g < 8; g++) acc[g] += wv * mb[(g*8 + h)*CP + c];
        }
        float vb = v_b[h*32 + d];
#pragma unroll
        for (int g = 0; g < 8; g++)
            g_ao[(size_t)(bq0 + g)*CDIM + h*32 + d] = acc[g] + vb;
    }
}

// ---------------- layernorm of (ra + rb) ----------------
__global__ void k_ln(const float* __restrict__ ra, const float* __restrict__ rb,
                     const float* __restrict__ gamma, const float* __restrict__ beta,
                     float* __restrict__ out) {
    int bq = blockIdx.x * 8 + (threadIdx.x >> 5);
    int lane = threadIdx.x & 31;
    float v[8];
    float s = 0.f;
#pragma unroll
    for (int i = 0; i < 8; i++) {
        int c = lane + 32*i;
        v[i] = ra[(size_t)bq*CDIM + c] + rb[(size_t)bq*CDIM + c];
        s += v[i];
    }
#pragma unroll
    for (int o = 16; o; o >>= 1) s += __shfl_xor_sync(0xffffffffu, s, o);
    float mean = s * (1.f/256.f);
    float vs = 0.f;
#pragma unroll
    for (int i = 0; i < 8; i++) { float d = v[i]-mean; vs += d*d; }
#pragma unroll
    for (int o = 16; o; o >>= 1) vs += __shfl_xor_sync(0xffffffffu, vs, o);
    float rstd = rsqrtf(vs*(1.f/256.f) + 1e-5f);
#pragma unroll
    for (int i = 0; i < 8; i++) {
        int c = lane + 32*i;
        out[(size_t)bq*CDIM + c] = (v[i]-mean)*rstd*gamma[c] + beta[c];
    }
}

// ---------------- final LN2 + transpose to (B, C, NQ) ----------------
__global__ void k_ln_out(const float* __restrict__ ra, const float* __restrict__ rb,
                         const float* __restrict__ gamma, const float* __restrict__ beta,
                         float* __restrict__ out) {
    int bq = blockIdx.x * 8 + (threadIdx.x >> 5);
    int lane = threadIdx.x & 31;
    int b = bq >> 10, nq = bq & 1023;
    float v[8];
    float s = 0.f;
#pragma unroll
    for (int i = 0; i < 8; i++) {
        int c = lane + 32*i;
        v[i] = ra[(size_t)bq*CDIM + c] + rb[(size_t)bq*CDIM + c];
        s += v[i];
    }
#pragma unroll
    for (int o = 16; o; o >>= 1) s += __shfl_xor_sync(0xffffffffu, s, o);
    float mean = s * (1.f/256.f);
    float vs = 0.f;
#pragma unroll
    for (int i = 0; i < 8; i++) { float d = v[i]-mean; vs += d*d; }
#pragma unroll
    for (int o = 16; o; o >>= 1) vs += __shfl_xor_sync(0xffffffffu, vs, o);
    float rstd = rsqrtf(vs*(1.f/256.f) + 1e-5f);
#pragma unroll
    for (int i = 0; i < 8; i++) {
        int c = lane + 32*i;
        out[((size_t)b*CDIM + c)*NQD + nq] = (v[i]-mean)*rstd*gamma[c] + beta[c];
    }
}

// ---------------- launch ----------------
extern "C" void kernel_launch(void* const* d_in, const int* in_sizes, int n_in,
                              void* d_out, int out_size) {
    const float* query     = (const float*)d_in[0];
    const float* key       = (const float*)d_in[1];
    const float* query_pos = (const float*)d_in[2];
    const float* key_pos   = (const float*)d_in[3];
    const float* q_w   = (const float*)d_in[4];
    const float* q_b   = (const float*)d_in[5];
    const float* k_w   = (const float*)d_in[6];
    // d_in[7] = k_b: provably cancels in softmax (uniform shift per (bq,h))
    const float* v_w   = (const float*)d_in[8];
    const float* v_b   = (const float*)d_in[9];
    const float* o_w   = (const float*)d_in[10];
    const float* o_b   = (const float*)d_in[11];
    const float* lin1_w = (const float*)d_in[12];
    const float* lin1_b = (const float*)d_in[13];
    const float* lin2_w = (const float*)d_in[14];
    const float* lin2_b = (const float*)d_in[15];
    const float* n1_g = (const float*)d_in[16];
    const float* n1_b = (const float*)d_in[17];
    const float* n2_g = (const float*)d_in[18];
    const float* n2_b = (const float*)d_in[19];
    const float* qpe_w = (const float*)d_in[20];
    const float* qpe_b = (const float*)d_in[21];
    const float* kpe_w = (const float*)d_in[22];
    const float* kpe_b = (const float*)d_in[23];

    void *p_qin, *p_qh, *p_ao, *p_res1, *p_qtok, *p_x, *p_ff, *p_y;
    cudaGetSymbolAddress(&p_qin,  g_qin);
    cudaGetSymbolAddress(&p_qh,   g_qh);
    cudaGetSymbolAddress(&p_ao,   g_ao);
    cudaGetSymbolAddress(&p_res1, g_res1);
    cudaGetSymbolAddress(&p_qtok, g_qtok);
    cudaGetSymbolAddress(&p_x,    g_x);
    cudaGetSymbolAddress(&p_ff,   g_ff);
    cudaGetSymbolAddress(&p_y,    g_y);

    const int attn_smem = (8*16*CP + 8*8*CP + 8*256 + 8*128 + 32)*4 + 128*4;
    cudaFuncSetAttribute(k_attn, cudaFuncAttributeMaxDynamicSharedMemorySize, attn_smem);

    // preprocessing
    k_transpose_key<<<dim3(NKD/32, CDIM/32, BATCH), dim3(32,8)>>>(key);
    k_build_q<<<dim3(NQD/32, CDIM/32, BATCH), dim3(32,8)>>>(query, query_pos, qpe_w, qpe_b);
    k_transpose_vw<<<dim3(CDIM/32, CDIM/32), dim3(32,8)>>>(v_w);
    k_boxquery<<<dim3(NQD/8, BATCH), 256>>>(key_pos, query_pos);

    // q projection: qh = qin @ q_w^T + q_b
    k_gemm<0><<<dim3(CDIM/128, BQTOT/128), 256>>>((const float*)p_qin, q_w, q_b,
                                                  (float*)p_qh, BQTOT, CDIM, CDIM);
    // fused gather + attention -> ao
    k_attn<<<BQTOT/8, 256, attn_smem>>>(key_pos, query_pos, kpe_w, kpe_b, k_w, v_b);

    // o projection
    k_gemm<0><<<dim3(CDIM/128, BQTOT/128), 256>>>((const float*)p_ao, o_w, o_b,
                                                  (float*)p_res1, BQTOT, CDIM, CDIM);
    // LN1(qtok + oproj)
    k_ln<<<BQTOT/8, 256>>>((const float*)p_qtok, (const float*)p_res1, n1_g, n1_b, (float*)p_x);

    // FFN
    k_gemm<1><<<dim3(FFDIM/128, BQTOT/128), 256>>>((const float*)p_x, lin1_w, lin1_b,
                                                   (float*)p_ff, BQTOT, FFDIM, CDIM);
    k_gemm<0><<<dim3(CDIM/128, BQTOT/128), 256>>>((const float*)p_ff, lin2_w, lin2_b,
                                                  (float*)p_y, BQTOT, CDIM, FFDIM);

    // LN2(x + ffn) + transpose out
    k_ln_out<<<BQTOT/8, 256>>>((const float*)p_x, (const float*)p_y, n2_g, n2_b, (float*)d_out);
}

// round 4
// speedup vs baseline: 1.9271x; 1.9271x over previous
#include <cuda_runtime.h>
#include <math.h>
#include <stdint.h>

#define BATCH 8
#define CDIM  256
#define NQD   1024
#define NKD   4096
#define SKEYS 16
#define HEADS 8
#define FFDIM 2048
#define DHD   32
#define BQTOT (BATCH*NQD)
#define CP    257   // padded smem stride (attn kernel)

// ---------------- scratch (device globals; no allocation allowed) ----------------
__device__ float g_keyT[BATCH*NKD*CDIM];   // key transposed (B, NK, C)
__device__ float g_qtok[BQTOT*CDIM];       // transposed query tokens (full fp32, residual)
__device__ float g_qin [BQTOT*CDIM];       // qtok + qpe (tf32-rounded, GEMM A)
__device__ float g_qh  [BQTOT*CDIM];       // q projection
__device__ int   g_sidx[BQTOT*SKEYS];      // gathered key indices (-1 = masked)
__device__ float g_vwT [CDIM*CDIM];        // v_w transposed
__device__ float g_ao  [BQTOT*CDIM];       // attention output (tf32-rounded, GEMM A)
__device__ float g_res1[BQTOT*CDIM];       // o-proj output
__device__ float g_x   [BQTOT*CDIM];       // after LN1 (full fp32, residual)
__device__ float g_xr  [BQTOT*CDIM];       // after LN1 (tf32-rounded, GEMM A)
__device__ float g_ff  [BQTOT*FFDIM];      // FFN hidden (tf32-rounded in epilogue)
__device__ float g_y   [BQTOT*CDIM];       // FFN out
// tf32-rounded weight copies
__device__ float g_qwr [CDIM*CDIM];
__device__ float g_owr [CDIM*CDIM];
__device__ float g_l1r [FFDIM*CDIM];
__device__ float g_l2r [CDIM*FFDIM];

// ---------------- small PTX helpers ----------------
__device__ __forceinline__ float to_tf32(float x) {
    unsigned u;
    asm("cvt.rna.tf32.f32 %0, %1;" : "=r"(u) : "f"(x));
    return __uint_as_float(u);
}
__device__ __forceinline__ uint32_t smem_u32(const void* p) {
    uint32_t a;
    asm("{ .reg .u64 t; cvta.to.shared.u64 t, %1; cvt.u32.u64 %0, t; }" : "=r"(a) : "l"(p));
    return a;
}
__device__ __forceinline__ void cp16(uint32_t s, const void* g) {
    asm volatile("cp.async.cg.shared.global [%0], [%1], 16;" :: "r"(s), "l"(g));
}
#define CP_COMMIT() asm volatile("cp.async.commit_group;" ::: "memory")
#define CP_WAIT1()  asm volatile("cp.async.wait_group 1;" ::: "memory")

__device__ __forceinline__ void mma_tf32(float* d,
                                         uint32_t a0, uint32_t a1, uint32_t a2, uint32_t a3,
                                         uint32_t b0, uint32_t b1) {
    asm volatile(
        "mma.sync.aligned.m16n8k8.row.col.f32.tf32.tf32.f32 "
        "{%0,%1,%2,%3}, {%4,%5,%6,%7}, {%8,%9}, {%0,%1,%2,%3};"
        : "+f"(d[0]), "+f"(d[1]), "+f"(d[2]), "+f"(d[3])
        : "r"(a0), "r"(a1), "r"(a2), "r"(a3), "r"(b0), "r"(b1));
}

// ---------------- tf32 mma.sync GEMM: C = A(M,K) @ W(N,K)^T + bias ----------------
// 128x128 tile, BK=32, 8 warps (4x2), warp tile 32x64, double-buffered cp.async.
#define PADK 36
#define STAGE_F (2*128*PADK)    // floats per stage (A + B)

template<int RELU, int ROUND>
__global__ void __launch_bounds__(256)
k_gemm_mma(const float* __restrict__ A, const float* __restrict__ W,
           const float* __restrict__ bias, float* __restrict__ Cout,
           int N, int K) {
    extern __shared__ float sm[];
    int t = threadIdx.x, lane = t & 31, wid = t >> 5;
    int wm = wid >> 1, wn = wid & 1;          // warp tile origin (wm*32, wn*64)
    int bm = blockIdx.y * 128, bn = blockIdx.x * 128;
    const int NC = K >> 5;
    int qr = lane >> 2, qc = lane & 3;        // quad row / quad col

    float acc[2][8][4];
#pragma unroll
    for (int mi = 0; mi < 2; mi++)
#pragma unroll
        for (int ni = 0; ni < 8; ni++)
#pragma unroll
            for (int j = 0; j < 4; j++) acc[mi][ni][j] = 0.f;

    uint32_t smb = smem_u32(sm);

    // stage 0 prologue
    {
        float* As = sm; float* Bs = sm + 128*PADK;
        for (int u = t; u < 1024; u += 256) {
            int row = u >> 3, seg = u & 7;
            cp16(smem_u32(As + row*PADK + seg*4), A + (size_t)(bm + row)*K + seg*4);
            cp16(smem_u32(Bs + row*PADK + seg*4), W + (size_t)(bn + row)*K + seg*4);
        }
    }
    CP_COMMIT();

    for (int c = 0; c < NC; c++) {
        __syncthreads();                       // stage (c+1)&1 free (compute c-1 done)
        if (c + 1 < NC) {
            float* As = sm + ((c+1)&1)*STAGE_F;
            float* Bs = As + 128*PADK;
            int k0 = (c+1)*32;
            for (int u = t; u < 1024; u += 256) {
                int row = u >> 3, seg = u & 7;
                cp16(smem_u32(As + row*PADK + seg*4), A + (size_t)(bm + row)*K + k0 + seg*4);
                cp16(smem_u32(Bs + row*PADK + seg*4), W + (size_t)(bn + row)*K + k0 + seg*4);
            }
        }
        CP_COMMIT();
        CP_WAIT1();                            // stage c copies done (this thread)
        __syncthreads();                       // all threads' stage-c copies visible

        const float* As = sm + (c&1)*STAGE_F;
        const float* Bs = As + 128*PADK;
#pragma unroll
        for (int kk = 0; kk < 4; kk++) {
            int k0 = kk*8;
            uint32_t bf[8][2];
#pragma unroll
            for (int ni = 0; ni < 8; ni++) {
                int n = wn*64 + ni*8 + qr;
                bf[ni][0] = __float_as_uint(Bs[n*PADK + k0 + qc]);
                bf[ni][1] = __float_as_uint(Bs[n*PADK + k0 + 4 + qc]);
            }
#pragma unroll
            for (int mi = 0; mi < 2; mi++) {
                int r = wm*32 + mi*16 + qr;
                uint32_t a0 = __float_as_uint(As[r*PADK + k0 + qc]);
                uint32_t a1 = __float_as_uint(As[(r+8)*PADK + k0 + qc]);
                uint32_t a2 = __float_as_uint(As[r*PADK + k0 + 4 + qc]);
                uint32_t a3 = __float_as_uint(As[(r+8)*PADK + k0 + 4 + qc]);
#pragma unroll
                for (int ni = 0; ni < 8; ni++)
                    mma_tf32(acc[mi][ni], a0, a1, a2, a3, bf[ni][0], bf[ni][1]);
            }
        }
    }

    // epilogue: direct stores (float2), bias/relu/round in regs
#pragma unroll
    for (int mi = 0; mi < 2; mi++) {
        int r0 = bm + wm*32 + mi*16 + qr;
#pragma unroll
        for (int ni = 0; ni < 8; ni++) {
            int cn = bn + wn*64 + ni*8 + qc*2;
            float b0 = bias[cn], b1 = bias[cn+1];
            float v0 = acc[mi][ni][0] + b0, v1 = acc[mi][ni][1] + b1;
            float v2 = acc[mi][ni][2] + b0, v3 = acc[mi][ni][3] + b1;
            if (RELU) { v0=fmaxf(v0,0.f); v1=fmaxf(v1,0.f); v2=fmaxf(v2,0.f); v3=fmaxf(v3,0.f); }
            if (ROUND){ v0=to_tf32(v0); v1=to_tf32(v1); v2=to_tf32(v2); v3=to_tf32(v3); }
            *(float2*)&Cout[(size_t)r0*N + cn]     = make_float2(v0, v1);
            *(float2*)&Cout[(size_t)(r0+8)*N + cn] = make_float2(v2, v3);
        }
    }
}

// ---------------- elementwise tf32 round ----------------
__global__ void k_round(const float* __restrict__ in, float* __restrict__ out, int n) {
    int i = blockIdx.x * 256 + threadIdx.x;
    if (i < n) out[i] = to_tf32(in[i]);
}

// ---------------- transpose key (B,C,NK) -> (B,NK,C) ----------------
__global__ void k_transpose_key(const float* __restrict__ key) {
    __shared__ float tile[32][33];
    int b = blockIdx.z;
    int c0 = blockIdx.y * 32, n0 = blockIdx.x * 32;
    int tx = threadIdx.x, ty = threadIdx.y;
#pragma unroll
    for (int j = 0; j < 4; j++)
        tile[ty + 8*j][tx] = key[(b*CDIM + c0 + ty + 8*j)*NKD + n0 + tx];
    __syncthreads();
#pragma unroll
    for (int j = 0; j < 4; j++)
        g_keyT[(b*NKD + n0 + ty + 8*j)*CDIM + c0 + tx] = tile[tx][ty + 8*j];
}

// ---------------- build qtok + qin (query transpose + qpe) ----------------
__global__ void k_build_q(const float* __restrict__ query,
                          const float* __restrict__ query_pos,
                          const float* __restrict__ qpe_w,
                          const float* __restrict__ qpe_b) {
    __shared__ float tile[32][33];
    int b = blockIdx.z;
    int c0 = blockIdx.y * 32, n0 = blockIdx.x * 32;
    int tx = threadIdx.x, ty = threadIdx.y;
#pragma unroll
    for (int j = 0; j < 4; j++)
        tile[ty + 8*j][tx] = query[(b*CDIM + c0 + ty + 8*j)*NQD + n0 + tx];
    __syncthreads();
#pragma unroll
    for (int j = 0; j < 4; j++) {
        int nq = n0 + ty + 8*j, c = c0 + tx;
        int bq = b*NQD + nq;
        float qt = tile[tx][ty + 8*j];
        const float* qp = query_pos + (size_t)bq*6;
        float pe = qpe_b[c];
#pragma unroll
        for (int jj = 0; jj < 6; jj++) pe += qp[jj] * qpe_w[c*6 + jj];
        g_qtok[bq*CDIM + c] = qt;
        g_qin [bq*CDIM + c] = to_tf32(qt + pe);
    }
}

// ---------------- transpose v_w (256x256) ----------------
__global__ void k_transpose_vw(const float* __restrict__ v_w) {
    __shared__ float tile[32][33];
    int n0 = blockIdx.y * 32, c0 = blockIdx.x * 32;
    int tx = threadIdx.x, ty = threadIdx.y;
#pragma unroll
    for (int j = 0; j < 4; j++)
        tile[ty + 8*j][tx] = v_w[(n0 + ty + 8*j)*CDIM + c0 + tx];
    __syncthreads();
#pragma unroll
    for (int j = 0; j < 4; j++)
        g_vwT[(c0 + ty + 8*j)*CDIM + n0 + tx] = tile[tx][ty + 8*j];
}

// ---------------- box query: first 16 inside-box keys, in index order ----------------
__global__ void k_boxquery(const float* __restrict__ key_pos,
                           const float* __restrict__ query_pos) {
    __shared__ float kp[NKD*3];   // exactly 48KB
    int b = blockIdx.y;
    int t = threadIdx.x;
#pragma unroll
    for (int i = 0; i < 48; i++)
        kp[t + 256*i] = key_pos[(size_t)b*NKD*3 + t + 256*i];
    __syncthreads();

    int w = t >> 5, lane = t & 31;
    int q = blockIdx.x * 8 + w;
    int bq = b*NQD + q;
    const float* qp = query_pos + (size_t)bq*6;
    float cx = qp[0], cy = qp[1], cz = qp[2];
    float hx = 0.5f*qp[3], hy = 0.5f*qp[4], hz = 0.5f*qp[5];

    int count = 0;
    for (int base = 0; base < NKD && count < SKEYS; base += 32) {
        int k = base + lane;
        float dx = fabsf(kp[k*3+0]-cx);
        float dy = fabsf(kp[k*3+1]-cy);
        float dz = fabsf(kp[k*3+2]-cz);
        bool inside = (dx <= hx) && (dy <= hy) && (dz <= hz);
        unsigned bal = __ballot_sync(0xffffffffu, inside);
        int nb = __popc(bal);
        if (inside) {
            int rank = __popc(bal & ((1u << lane) - 1u));
            if (count + rank < SKEYS) g_sidx[bq*SKEYS + count + rank] = k;
        }
        count += nb;
        if (count > SKEYS) count = SKEYS;
    }
    if (lane < SKEYS && lane >= count)
        g_sidx[bq*SKEYS + lane] = (lane == 0) ? 0 : -1;
}

// ---------------- fused gather + attention (8 queries per block) ----------------
__global__ void k_attn(const float* __restrict__ key_pos,
                       const float* __restrict__ query_pos,
                       const float* __restrict__ kpe_w,
                       const float* __restrict__ kpe_b,
                       const float* __restrict__ k_w,
                       const float* __restrict__ v_b) {
    extern __shared__ float sm[];
    float* kv = sm;                     // [8][16][CP]
    float* mb = kv + 8*16*CP;           // [8][8][CP]   (m, later wkv)
    float* qs = mb + 8*8*CP;            // [8][256]
    float* at = qs + 8*256;             // [8][8][16]   (scores, then attn)
    float* qc = at + 8*128;             // [8][4]
    int*  sid = (int*)(qc + 32);        // [8][16]

    int t = threadIdx.x, lane = t & 31, w = t >> 5;
    int bq0 = blockIdx.x * 8;
    int b = bq0 >> 10;   // NQ=1024

    if (t < 128) sid[t] = g_sidx[bq0*SKEYS + t];
    if (t < 24) { int g = t/3, j = t%3; qc[g*4 + j] = query_pos[(size_t)(bq0+g)*6 + j]; }
#pragma unroll
    for (int i = 0; i < 8; i++) qs[t + 256*i] = g_qh[(size_t)bq0*CDIM + t + 256*i];
    __syncthreads();

    // phase 1: gather kv = keyT[idx] + kpe(gxyz)
    {
        int g = w;
        float qcx = qc[g*4+0], qcy = qc[g*4+1], qcz = qc[g*4+2];
        for (int s = 0; s < SKEYS; s++) {
            int v = sid[g*16 + s];
            int kidx = v < 0 ? 0 : v;
            int base = b*NKD + kidx;
            float gx = key_pos[base*3+0] - qcx;
            float gy = key_pos[base*3+1] - qcy;
            float gz = key_pos[base*3+2] - qcz;
            const float* krow = g_keyT + (size_t)base*CDIM;
            float* kvrow = kv + (g*16 + s)*CP;
#pragma unroll
            for (int i = 0; i < 8; i++) {
                int c = lane + 32*i;
                float pe = kpe_b[c] + gx*kpe_w[c*3] + gy*kpe_w[c*3+1] + gz*kpe_w[c*3+2];
                kvrow[c] = krow[c] + pe;
            }
        }
    }
    __syncthreads();

    // phase 2: m[g][h][c] = sum_d k_w[h*32+d, c] * qh[g][h*32+d]
    {
        int h = w;
        float acc[8][8];   // [cc][g]
#pragma unroll
        for (int i = 0; i < 8; i++)
#pragma unroll
            for (int j = 0; j < 8; j++) acc[i][j] = 0.f;
        for (int d = 0; d < 32; d++) {
            float qv[8];
#pragma unroll
            for (int g = 0; g < 8; g++) qv[g] = qs[g*256 + h*32 + d];
            const float* wr = k_w + (size_t)(h*32 + d)*CDIM;
#pragma unroll
            for (int cc = 0; cc < 8; cc++) {
                float wv = wr[lane + 32*cc];
#pragma unroll
                for (int g = 0; g < 8; g++) acc[cc][g] += wv * qv[g];
            }
        }
#pragma unroll
        for (int cc = 0; cc < 8; cc++)
#pragma unroll
            for (int g = 0; g < 8; g++)
                mb[(g*8 + h)*CP + lane + 32*cc] = acc[cc][g];
    }
    __syncthreads();

    // phase 3: scores[g][h][s] = m[g][h] . kv[g][s]
    {
        int g = w, h = lane >> 2, s0 = lane & 3;
        float sc[4] = {0.f, 0.f, 0.f, 0.f};
        const float* mrow = mb + (g*8 + h)*CP;
        for (int c = 0; c < 256; c++) {
            float mv = mrow[c];
#pragma unroll
            for (int j = 0; j < 4; j++)
                sc[j] += mv * kv[(g*16 + s0 + 4*j)*CP + c];
        }
#pragma unroll
        for (int j = 0; j < 4; j++) at[(g*8 + h)*16 + s0 + 4*j] = sc[j];
    }
    __syncthreads();

    // phase 4: masked softmax (one thread per (g,h))
    if (t < 64) {
        int g = t >> 3, h = t & 7;
        float* row = at + (g*8 + h)*16;
        const int* sg = sid + g*16;
        const float scl = 0.17677669529663687f;   // 1/sqrt(32)
        float sv[16];
        float mx = -3.0e38f;
#pragma unroll
        for (int s = 0; s < 16; s++) {
            sv[s] = (sg[s] < 0) ? -3.0e38f : row[s]*scl;
            mx = fmaxf(mx, sv[s]);
        }
        float sum = 0.f;
#pragma unroll
        for (int s = 0; s < 16; s++) {
            float e = (sg[s] < 0) ? 0.f : expf(sv[s] - mx);
            sv[s] = e; sum += e;
        }
        float inv = 1.f/sum;
#pragma unroll
        for (int s = 0; s < 16; s++) row[s] = sv[s]*inv;
    }
    __syncthreads();

    // phase 5: wkv[g][h][c] = sum_s attn[g][h][s] * kv[g][s][c]  (into mb)
    {
        int g = w;
        float acc[8][8];   // [cc][h]
#pragma unroll
        for (int i = 0; i < 8; i++)
#pragma unroll
            for (int j = 0; j < 8; j++) acc[i][j] = 0.f;
        for (int s = 0; s < 16; s++) {
            float av[8];
#pragma unroll
            for (int h = 0; h < 8; h++) av[h] = at[(g*8 + h)*16 + s];
            const float* kvrow = kv + (g*16 + s)*CP;
#pragma unroll
            for (int cc = 0; cc < 8; cc++) {
                float kvv = kvrow[lane + 32*cc];
#pragma unroll
                for (int h = 0; h < 8; h++) acc[cc][h] += av[h]*kvv;
            }
        }
#pragma unroll
        for (int cc = 0; cc < 8; cc++)
#pragma unroll
            for (int h = 0; h < 8; h++)
                mb[(g*8 + h)*CP + lane + 32*cc] = acc[cc][h];
    }
    __syncthreads();

    // phase 6: ao[g][h*32+d] = sum_c wkv[g][h][c] * v_wT[c][h*32+d] + v_b  (tf32-rounded)
    {
        int h = w, d = lane;
        float acc[8];
#pragma unroll
        for (int g = 0; g < 8; g++) acc[g] = 0.f;
        const float* wcol = g_vwT + h*32 + d;
        for (int c = 0; c < 256; c++) {
            float wv = wcol[(size_t)c*CDIM];
#pragma unroll
            for (int g = 0; g < 8; g++) acc[g] += wv * mb[(g*8 + h)*CP + c];
        }
        float vb = v_b[h*32 + d];
#pragma unroll
        for (int g = 0; g < 8; g++)
            g_ao[(size_t)(bq0 + g)*CDIM + h*32 + d] = to_tf32(acc[g] + vb);
    }
}

// ---------------- layernorm of (ra + rb), writes full + tf32-rounded ----------------
__global__ void k_ln(const float* __restrict__ ra, const float* __restrict__ rb,
                     const float* __restrict__ gamma, const float* __restrict__ beta,
                     float* __restrict__ out, float* __restrict__ outr) {
    int bq = blockIdx.x * 8 + (threadIdx.x >> 5);
    int lane = threadIdx.x & 31;
    float v[8];
    float s = 0.f;
#pragma unroll
    for (int i = 0; i < 8; i++) {
        int c = lane + 32*i;
        v[i] = ra[(size_t)bq*CDIM + c] + rb[(size_t)bq*CDIM + c];
        s += v[i];
    }
#pragma unroll
    for (int o = 16; o; o >>= 1) s += __shfl_xor_sync(0xffffffffu, s, o);
    float mean = s * (1.f/256.f);
    float vs = 0.f;
#pragma unroll
    for (int i = 0; i < 8; i++) { float d = v[i]-mean; vs += d*d; }
#pragma unroll
    for (int o = 16; o; o >>= 1) vs += __shfl_xor_sync(0xffffffffu, vs, o);
    float rstd = rsqrtf(vs*(1.f/256.f) + 1e-5f);
#pragma unroll
    for (int i = 0; i < 8; i++) {
        int c = lane + 32*i;
        float r = (v[i]-mean)*rstd*gamma[c] + beta[c];
        out [(size_t)bq*CDIM + c] = r;
        outr[(size_t)bq*CDIM + c] = to_tf32(r);
    }
}

// ---------------- final LN2 + transpose to (B, C, NQ) ----------------
__global__ void k_ln_out(const float* __restrict__ ra, const float* __restrict__ rb,
                         const float* __restrict__ gamma, const float* __restrict__ beta,
                         float* __restrict__ out) {
    int bq = blockIdx.x * 8 + (threadIdx.x >> 5);
    int lane = threadIdx.x & 31;
    int b = bq >> 10, nq = bq & 1023;
    float v[8];
    float s = 0.f;
#pragma unroll
    for (int i = 0; i < 8; i++) {
        int c = lane + 32*i;
        v[i] = ra[(size_t)bq*CDIM + c] + rb[(size_t)bq*CDIM + c];
        s += v[i];
    }
#pragma unroll
    for (int o = 16; o; o >>= 1) s += __shfl_xor_sync(0xffffffffu, s, o);
    float mean = s * (1.f/256.f);
    float vs = 0.f;
#pragma unroll
    for (int i = 0; i < 8; i++) { float d = v[i]-mean; vs += d*d; }
#pragma unroll
    for (int o = 16; o; o >>= 1) vs += __shfl_xor_sync(0xffffffffu, vs, o);
    float rstd = rsqrtf(vs*(1.f/256.f) + 1e-5f);
#pragma unroll
    for (int i = 0; i < 8; i++) {
        int c = lane + 32*i;
        out[((size_t)b*CDIM + c)*NQD + nq] = (v[i]-mean)*rstd*gamma[c] + beta[c];
    }
}

// ---------------- launch ----------------
extern "C" void kernel_launch(void* const* d_in, const int* in_sizes, int n_in,
                              void* d_out, int out_size) {
    const float* query     = (const float*)d_in[0];
    const float* key       = (const float*)d_in[1];
    const float* query_pos = (const float*)d_in[2];
    const float* key_pos   = (const float*)d_in[3];
    const float* q_w   = (const float*)d_in[4];
    const float* q_b   = (const float*)d_in[5];
    const float* k_w   = (const float*)d_in[6];
    // d_in[7] = k_b: cancels in softmax (uniform shift per (bq,h))
    const float* v_w   = (const float*)d_in[8];
    const float* v_b   = (const float*)d_in[9];
    const float* o_w   = (const float*)d_in[10];
    const float* o_b   = (const float*)d_in[11];
    const float* lin1_w = (const float*)d_in[12];
    const float* lin1_b = (const float*)d_in[13];
    const float* lin2_w = (const float*)d_in[14];
    const float* lin2_b = (const float*)d_in[15];
    const float* n1_g = (const float*)d_in[16];
    const float* n1_b = (const float*)d_in[17];
    const float* n2_g = (const float*)d_in[18];
    const float* n2_b = (const float*)d_in[19];
    const float* qpe_w = (const float*)d_in[20];
    const float* qpe_b = (const float*)d_in[21];
    const float* kpe_w = (const float*)d_in[22];
    const float* kpe_b = (const float*)d_in[23];

    void *p_qin, *p_qh, *p_ao, *p_res1, *p_qtok, *p_x, *p_xr, *p_ff, *p_y;
    void *p_qwr, *p_owr, *p_l1r, *p_l2r;
    cudaGetSymbolAddress(&p_qin,  g_qin);
    cudaGetSymbolAddress(&p_qh,   g_qh);
    cudaGetSymbolAddress(&p_ao,   g_ao);
    cudaGetSymbolAddress(&p_res1, g_res1);
    cudaGetSymbolAddress(&p_qtok, g_qtok);
    cudaGetSymbolAddress(&p_x,    g_x);
    cudaGetSymbolAddress(&p_xr,   g_xr);
    cudaGetSymbolAddress(&p_ff,   g_ff);
    cudaGetSymbolAddress(&p_y,    g_y);
    cudaGetSymbolAddress(&p_qwr,  g_qwr);
    cudaGetSymbolAddress(&p_owr,  g_owr);
    cudaGetSymbolAddress(&p_l1r,  g_l1r);
    cudaGetSymbolAddress(&p_l2r,  g_l2r);

    const int attn_smem = (8*16*CP + 8*8*CP + 8*256 + 8*128 + 32)*4 + 128*4;
    cudaFuncSetAttribute(k_attn, cudaFuncAttributeMaxDynamicSharedMemorySize, attn_smem);

    const int gemm_smem = 2 * STAGE_F * 4;    // 73,728 bytes (2 stages)
    cudaFuncSetAttribute(k_gemm_mma<0,0>, cudaFuncAttributeMaxDynamicSharedMemorySize, gemm_smem);
    cudaFuncSetAttribute(k_gemm_mma<1,1>, cudaFuncAttributeMaxDynamicSharedMemorySize, gemm_smem);

    // preprocessing
    k_transpose_key<<<dim3(NKD/32, CDIM/32, BATCH), dim3(32,8)>>>(key);
    k_build_q<<<dim3(NQD/32, CDIM/32, BATCH), dim3(32,8)>>>(query, query_pos, qpe_w, qpe_b);
    k_transpose_vw<<<dim3(CDIM/32, CDIM/32), dim3(32,8)>>>(v_w);
    k_boxquery<<<dim3(NQD/8, BATCH), 256>>>(key_pos, query_pos);

    // tf32-round the GEMM weights (round-to-nearest, unbiased)
    k_round<<<CDIM*CDIM/256, 256>>>(q_w,    (float*)p_qwr, CDIM*CDIM);
    k_round<<<CDIM*CDIM/256, 256>>>(o_w,    (float*)p_owr, CDIM*CDIM);
    k_round<<<FFDIM*CDIM/256, 256>>>(lin1_w, (float*)p_l1r, FFDIM*CDIM);
    k_round<<<CDIM*FFDIM/256, 256>>>(lin2_w, (float*)p_l2r, CDIM*FFDIM);

    // q projection: qh = qin @ q_w^T + q_b
    k_gemm_mma<0,0><<<dim3(CDIM/128, BQTOT/128), 256, gemm_smem>>>(
        (const float*)p_qin, (const float*)p_qwr, q_b, (float*)p_qh, CDIM, CDIM);

    // fused gather + attention -> ao
    k_attn<<<BQTOT/8, 256, attn_smem>>>(key_pos, query_pos, kpe_w, kpe_b, k_w, v_b);

    // o projection
    k_gemm_mma<0,0><<<dim3(CDIM/128, BQTOT/128), 256, gemm_smem>>>(
        (const float*)p_ao, (const float*)p_owr, o_b, (float*)p_res1, CDIM, CDIM);

    // LN1(qtok + oproj) -> x (full) + xr (rounded)
    k_ln<<<BQTOT/8, 256>>>((const float*)p_qtok, (const float*)p_res1, n1_g, n1_b,
                           (float*)p_x, (float*)p_xr);

    // FFN
    k_gemm_mma<1,1><<<dim3(FFDIM/128, BQTOT/128), 256, gemm_smem>>>(
        (const float*)p_xr, (const float*)p_l1r, lin1_b, (float*)p_ff, FFDIM, CDIM);
    k_gemm_mma<0,0><<<dim3(CDIM/128, BQTOT/128), 256, gemm_smem>>>(
        (const float*)p_ff, (const float*)p_l2r, lin2_b, (float*)p_y, CDIM, FFDIM);

    // LN2(x + ffn) + transpose out
    k_ln_out<<<BQTOT/8, 256>>>((const float*)p_x, (const float*)p_y, n2_g, n2_b, (float*)d_out);
}

// round 5
// speedup vs baseline: 3.1330x; 1.6257x over previous
#include <cuda_runtime.h>
#include <math.h>
#include <stdint.h>

#define BATCH 8
#define CDIM  256
#define NQD   1024
#define NKD   4096
#define SKEYS 16
#define HEADS 8
#define FFDIM 2048
#define DHD   32
#define BQTOT (BATCH*NQD)
#define CP    260   // padded smem stride (attn kernel; 16B-aligned rows)

// ---------------- scratch (device globals; no allocation allowed) ----------------
__device__ float g_keyT[BATCH*NKD*CDIM];     // key transposed (B, NK, C)
__device__ float g_qtok[BQTOT*CDIM];         // transposed query tokens (residual)
__device__ float g_qin [BQTOT*CDIM];         // qtok + qpe (tf32-rounded)
__device__ float g_qh  [2*BQTOT*CDIM];       // q projection (2 split-K slices)
__device__ int   g_sidx[BQTOT*SKEYS];        // gathered key indices (-1 = masked)
__device__ float g_vwT [CDIM*CDIM];          // v_w transposed
__device__ float g_ao  [BQTOT*CDIM];         // attention output (tf32-rounded)
__device__ float g_res1[2*BQTOT*CDIM];       // o-proj output (2 slices)
__device__ float g_x   [BQTOT*CDIM];         // after LN1 (residual)
__device__ float g_xr  [BQTOT*CDIM];         // after LN1 (tf32-rounded)
__device__ float g_ff  [BQTOT*FFDIM];        // FFN hidden (rounded in epilogue)
__device__ float g_y   [2*BQTOT*CDIM];       // FFN out (2 slices)
// tf32-rounded weight copies
__device__ float g_qwr [CDIM*CDIM];
__device__ float g_owr [CDIM*CDIM];
__device__ float g_l1r [FFDIM*CDIM];
__device__ float g_l2r [CDIM*FFDIM];

// ---------------- small PTX helpers ----------------
__device__ __forceinline__ float to_tf32(float x) {
    unsigned u;
    asm("cvt.rna.tf32.f32 %0, %1;" : "=r"(u) : "f"(x));
    return __uint_as_float(u);
}
__device__ __forceinline__ uint32_t smem_u32(const void* p) {
    uint32_t a;
    asm("{ .reg .u64 t; cvta.to.shared.u64 t, %1; cvt.u32.u64 %0, t; }" : "=r"(a) : "l"(p));
    return a;
}
__device__ __forceinline__ void cp16(uint32_t s, const void* g) {
    asm volatile("cp.async.cg.shared.global [%0], [%1], 16;" :: "r"(s), "l"(g));
}
#define CP_COMMIT() asm volatile("cp.async.commit_group;" ::: "memory")
#define CP_WAIT1()  asm volatile("cp.async.wait_group 1;" ::: "memory")

__device__ __forceinline__ void mma_tf32(float* d,
                                         uint32_t a0, uint32_t a1, uint32_t a2, uint32_t a3,
                                         uint32_t b0, uint32_t b1) {
    asm volatile(
        "mma.sync.aligned.m16n8k8.row.col.f32.tf32.tf32.f32 "
        "{%0,%1,%2,%3}, {%4,%5,%6,%7}, {%8,%9}, {%0,%1,%2,%3};"
        : "+f"(d[0]), "+f"(d[1]), "+f"(d[2]), "+f"(d[3])
        : "r"(a0), "r"(a1), "r"(a2), "r"(a3), "r"(b0), "r"(b1));
}

// ---------------- tf32 mma.sync GEMM: C = A(M,Klda) @ W(N,Klda)^T (+ bias on z=0) ----
// 128x128 tile, BK=32, 8 warps (4x2), warp tile 32x64, double-buffered cp.async.
// Split-K: blockIdx.z selects K-slice [z*KS, (z+1)*KS), writes to Cout + z*outStride.
#define PADK 36
#define STAGE_F (2*128*PADK)    // floats per stage (A + B)

template<int RELU, int ROUND>
__global__ void __launch_bounds__(256)
k_gemm_mma(const float* __restrict__ A, const float* __restrict__ W,
           const float* __restrict__ bias, float* __restrict__ Cout,
           int N, int lda, int KS, size_t outStride) {
    extern __shared__ float sm[];
    int t = threadIdx.x, lane = t & 31, wid = t >> 5;
    int wm = wid >> 1, wn = wid & 1;          // warp tile origin (wm*32, wn*64)
    int bm = blockIdx.y * 128, bn = blockIdx.x * 128;
    int kb = blockIdx.z * KS;
    float* Cz = Cout + (size_t)blockIdx.z * outStride;
    const int NC = KS >> 5;
    int qr = lane >> 2, qc = lane & 3;        // quad row / quad col

    float acc[2][8][4];
#pragma unroll
    for (int mi = 0; mi < 2; mi++)
#pragma unroll
        for (int ni = 0; ni < 8; ni++)
#pragma unroll
            for (int j = 0; j < 4; j++) acc[mi][ni][j] = 0.f;

    // stage 0 prologue
    {
        float* As = sm; float* Bs = sm + 128*PADK;
        for (int u = t; u < 1024; u += 256) {
            int row = u >> 3, seg = u & 7;
            cp16(smem_u32(As + row*PADK + seg*4), A + (size_t)(bm + row)*lda + kb + seg*4);
            cp16(smem_u32(Bs + row*PADK + seg*4), W + (size_t)(bn + row)*lda + kb + seg*4);
        }
    }
    CP_COMMIT();

    for (int c = 0; c < NC; c++) {
        __syncthreads();                       // stage (c+1)&1 free (compute c-1 done)
        if (c + 1 < NC) {
            float* As = sm + ((c+1)&1)*STAGE_F;
            float* Bs = As + 128*PADK;
            int k0 = kb + (c+1)*32;
            for (int u = t; u < 1024; u += 256) {
                int row = u >> 3, seg = u & 7;
                cp16(smem_u32(As + row*PADK + seg*4), A + (size_t)(bm + row)*lda + k0 + seg*4);
                cp16(smem_u32(Bs + row*PADK + seg*4), W + (size_t)(bn + row)*lda + k0 + seg*4);
            }
        }
        CP_COMMIT();
        CP_WAIT1();                            // stage c copies done (this thread)
        __syncthreads();                       // all threads' stage-c copies visible

        const float* As = sm + (c&1)*STAGE_F;
        const float* Bs = As + 128*PADK;
#pragma unroll
        for (int kk = 0; kk < 4; kk++) {
            int k0 = kk*8;
            uint32_t bf[8][2];
#pragma unroll
            for (int ni = 0; ni < 8; ni++) {
                int n = wn*64 + ni*8 + qr;
                bf[ni][0] = __float_as_uint(Bs[n*PADK + k0 + qc]);
                bf[ni][1] = __float_as_uint(Bs[n*PADK + k0 + 4 + qc]);
            }
#pragma unroll
            for (int mi = 0; mi < 2; mi++) {
                int r = wm*32 + mi*16 + qr;
                uint32_t a0 = __float_as_uint(As[r*PADK + k0 + qc]);
                uint32_t a1 = __float_as_uint(As[(r+8)*PADK + k0 + qc]);
                uint32_t a2 = __float_as_uint(As[r*PADK + k0 + 4 + qc]);
                uint32_t a3 = __float_as_uint(As[(r+8)*PADK + k0 + 4 + qc]);
#pragma unroll
                for (int ni = 0; ni < 8; ni++)
                    mma_tf32(acc[mi][ni], a0, a1, a2, a3, bf[ni][0], bf[ni][1]);
            }
        }
    }

    // epilogue: direct stores (float2); bias only on z=0
    bool addb = (blockIdx.z == 0);
#pragma unroll
    for (int mi = 0; mi < 2; mi++) {
        int r0 = bm + wm*32 + mi*16 + qr;
#pragma unroll
        for (int ni = 0; ni < 8; ni++) {
            int cn = bn + wn*64 + ni*8 + qc*2;
            float b0 = addb ? bias[cn] : 0.f, b1 = addb ? bias[cn+1] : 0.f;
            float v0 = acc[mi][ni][0] + b0, v1 = acc[mi][ni][1] + b1;
            float v2 = acc[mi][ni][2] + b0, v3 = acc[mi][ni][3] + b1;
            if (RELU) { v0=fmaxf(v0,0.f); v1=fmaxf(v1,0.f); v2=fmaxf(v2,0.f); v3=fmaxf(v3,0.f); }
            if (ROUND){ v0=to_tf32(v0); v1=to_tf32(v1); v2=to_tf32(v2); v3=to_tf32(v3); }
            *(float2*)&Cz[(size_t)r0*N + cn]     = make_float2(v0, v1);
            *(float2*)&Cz[(size_t)(r0+8)*N + cn] = make_float2(v2, v3);
        }
    }
}

// ---------------- elementwise tf32 round ----------------
__global__ void k_round(const float* __restrict__ in, float* __restrict__ out, int n) {
    int i = blockIdx.x * 256 + threadIdx.x;
    if (i < n) out[i] = to_tf32(in[i]);
}

// ---------------- transpose key (B,C,NK) -> (B,NK,C) ----------------
__global__ void k_transpose_key(const float* __restrict__ key) {
    __shared__ float tile[32][33];
    int b = blockIdx.z;
    int c0 = blockIdx.y * 32, n0 = blockIdx.x * 32;
    int tx = threadIdx.x, ty = threadIdx.y;
#pragma unroll
    for (int j = 0; j < 4; j++)
        tile[ty + 8*j][tx] = key[(b*CDIM + c0 + ty + 8*j)*NKD + n0 + tx];
    __syncthreads();
#pragma unroll
    for (int j = 0; j < 4; j++)
        g_keyT[(b*NKD + n0 + ty + 8*j)*CDIM + c0 + tx] = tile[tx][ty + 8*j];
}

// ---------------- build qtok + qin (query transpose + qpe) ----------------
__global__ void k_build_q(const float* __restrict__ query,
                          const float* __restrict__ query_pos,
                          const float* __restrict__ qpe_w,
                          const float* __restrict__ qpe_b) {
    __shared__ float tile[32][33];
    int b = blockIdx.z;
    int c0 = blockIdx.y * 32, n0 = blockIdx.x * 32;
    int tx = threadIdx.x, ty = threadIdx.y;
#pragma unroll
    for (int j = 0; j < 4; j++)
        tile[ty + 8*j][tx] = query[(b*CDIM + c0 + ty + 8*j)*NQD + n0 + tx];
    __syncthreads();
#pragma unroll
    for (int j = 0; j < 4; j++) {
        int nq = n0 + ty + 8*j, c = c0 + tx;
        int bq = b*NQD + nq;
        float qt = tile[tx][ty + 8*j];
        const float* qp = query_pos + (size_t)bq*6;
        float pe = qpe_b[c];
#pragma unroll
        for (int jj = 0; jj < 6; jj++) pe += qp[jj] * qpe_w[c*6 + jj];
        g_qtok[bq*CDIM + c] = qt;
        g_qin [bq*CDIM + c] = to_tf32(qt + pe);
    }
}

// ---------------- transpose v_w (256x256) ----------------
__global__ void k_transpose_vw(const float* __restrict__ v_w) {
    __shared__ float tile[32][33];
    int n0 = blockIdx.y * 32, c0 = blockIdx.x * 32;
    int tx = threadIdx.x, ty = threadIdx.y;
#pragma unroll
    for (int j = 0; j < 4; j++)
        tile[ty + 8*j][tx] = v_w[(n0 + ty + 8*j)*CDIM + c0 + tx];
    __syncthreads();
#pragma unroll
    for (int j = 0; j < 4; j++)
        g_vwT[(c0 + ty + 8*j)*CDIM + n0 + tx] = tile[tx][ty + 8*j];
}

// ---------------- box query: first 16 inside-box keys, in index order ----------------
__global__ void k_boxquery(const float* __restrict__ key_pos,
                           const float* __restrict__ query_pos) {
    __shared__ float kp[NKD*3];   // exactly 48KB
    int b = blockIdx.y;
    int t = threadIdx.x;
#pragma unroll
    for (int i = 0; i < 48; i++)
        kp[t + 256*i] = key_pos[(size_t)b*NKD*3 + t + 256*i];
    __syncthreads();

    int w = t >> 5, lane = t & 31;
    int q = blockIdx.x * 8 + w;
    int bq = b*NQD + q;
    const float* qp = query_pos + (size_t)bq*6;
    float cx = qp[0], cy = qp[1], cz = qp[2];
    float hx = 0.5f*qp[3], hy = 0.5f*qp[4], hz = 0.5f*qp[5];

    int count = 0;
    for (int base = 0; base < NKD && count < SKEYS; base += 32) {
        int k = base + lane;
        float dx = fabsf(kp[k*3+0]-cx);
        float dy = fabsf(kp[k*3+1]-cy);
        float dz = fabsf(kp[k*3+2]-cz);
        bool inside = (dx <= hx) && (dy <= hy) && (dz <= hz);
        unsigned bal = __ballot_sync(0xffffffffu, inside);
        int nb = __popc(bal);
        if (inside) {
            int rank = __popc(bal & ((1u << lane) - 1u));
            if (count + rank < SKEYS) g_sidx[bq*SKEYS + count + rank] = k;
        }
        count += nb;
        if (count > SKEYS) count = SKEYS;
    }
    if (lane < SKEYS && lane >= count)
        g_sidx[bq*SKEYS + lane] = (lane == 0) ? 0 : -1;
}

// ---------------- fused gather + attention (8 queries per block, vectorized) -------
__global__ void k_attn(const float* __restrict__ key_pos,
                       const float* __restrict__ query_pos,
                       const float* __restrict__ kpe_w,
                       const float* __restrict__ kpe_b,
                       const float* __restrict__ k_w,
                       const float* __restrict__ v_b) {
    extern __shared__ float sm[];
    float* kv = sm;                     // [8][16][CP]
    float* mb = kv + 8*16*CP;           // [8][8][CP]   (m, later wkv)
    float* qs = mb + 8*8*CP;            // [8][256]
    float* at = qs + 8*256;             // [8][8][16]   (scores, then attn)
    float* pes = at + 8*128;            // [4][256]  kpe SoA: w0,w1,w2,b
    float* qc = pes + 4*256;            // [8][4]
    int*  sid = (int*)(qc + 32);        // [8][16]

    int t = threadIdx.x, lane = t & 31, w = t >> 5;
    int bq0 = blockIdx.x * 8;
    int b = bq0 >> 10;   // NQ=1024

    if (t < 128) sid[t] = g_sidx[bq0*SKEYS + t];
    if (t < 24) { int g = t/3, j = t%3; qc[g*4 + j] = query_pos[(size_t)(bq0+g)*6 + j]; }
    {   // kpe SoA staging
        pes[0*256 + t] = kpe_w[t*3 + 0];
        pes[1*256 + t] = kpe_w[t*3 + 1];
        pes[2*256 + t] = kpe_w[t*3 + 2];
        pes[3*256 + t] = kpe_b[t];
    }
#pragma unroll
    for (int i = 0; i < 8; i++)
        qs[t + 256*i] = g_qh[(size_t)bq0*CDIM + t + 256*i]
                      + g_qh[(size_t)BQTOT*CDIM + (size_t)bq0*CDIM + t + 256*i];
    __syncthreads();

    // phase 1: gather kv = keyT[idx] + kpe(gxyz)   (float4)
    {
        int g = w;
        float qcx = qc[g*4+0], qcy = qc[g*4+1], qcz = qc[g*4+2];
        for (int s = 0; s < SKEYS; s++) {
            int v = sid[g*16 + s];
            int kidx = v < 0 ? 0 : v;
            int base = b*NKD + kidx;
            float gx = key_pos[base*3+0] - qcx;
            float gy = key_pos[base*3+1] - qcy;
            float gz = key_pos[base*3+2] - qcz;
            const float4* krow4 = (const float4*)(g_keyT + (size_t)base*CDIM);
            float* kvrow = kv + (g*16 + s)*CP;
#pragma unroll
            for (int i = 0; i < 2; i++) {
                int c4 = lane + 32*i;
                float4 kr = krow4[c4];
                float4 w0 = *(const float4*)&pes[0*256 + 4*c4];
                float4 w1 = *(const float4*)&pes[1*256 + 4*c4];
                float4 w2 = *(const float4*)&pes[2*256 + 4*c4];
                float4 bb = *(const float4*)&pes[3*256 + 4*c4];
                float4 r;
                r.x = kr.x + bb.x + gx*w0.x + gy*w1.x + gz*w2.x;
                r.y = kr.y + bb.y + gx*w0.y + gy*w1.y + gz*w2.y;
                r.z = kr.z + bb.z + gx*w0.z + gy*w1.z + gz*w2.z;
                r.w = kr.w + bb.w + gx*w0.w + gy*w1.w + gz*w2.w;
                *(float4*)&kvrow[4*c4] = r;
            }
        }
    }
    __syncthreads();

    // phase 2: m[g][h][c] = sum_d k_w[h*32+d, c] * qh[g][h*32+d]
    {
        int h = w;
        float acc[8][8];   // [cc][g]
#pragma unroll
        for (int i = 0; i < 8; i++)
#pragma unroll
            for (int j = 0; j < 8; j++) acc[i][j] = 0.f;
        for (int d = 0; d < 32; d++) {
            float qv[8];
#pragma unroll
            for (int g = 0; g < 8; g++) qv[g] = qs[g*256 + h*32 + d];
            const float* wr = k_w + (size_t)(h*32 + d)*CDIM;
#pragma unroll
            for (int cc = 0; cc < 8; cc++) {
                float wv = __ldg(wr + lane + 32*cc);
#pragma unroll
                for (int g = 0; g < 8; g++) acc[cc][g] += wv * qv[g];
            }
        }
#pragma unroll
        for (int cc = 0; cc < 8; cc++)
#pragma unroll
            for (int g = 0; g < 8; g++)
                mb[(g*8 + h)*CP + lane + 32*cc] = acc[cc][g];
    }
    __syncthreads();

    // phase 3: scores[g][h][s] = m[g][h] . kv[g][s]   (float4)
    {
        int g = w, h = lane >> 2, s0 = lane & 3;
        float sc[4] = {0.f, 0.f, 0.f, 0.f};
        const float4* m4 = (const float4*)(mb + (g*8 + h)*CP);
        const float4* kv0 = (const float4*)(kv + (g*16 + s0 + 0)*CP);
        const float4* kv1 = (const float4*)(kv + (g*16 + s0 + 4)*CP);
        const float4* kv2 = (const float4*)(kv + (g*16 + s0 + 8)*CP);
        const float4* kv3 = (const float4*)(kv + (g*16 + s0 + 12)*CP);
        for (int c4 = 0; c4 < 64; c4++) {
            float4 mv = m4[c4];
            float4 k0 = kv0[c4], k1 = kv1[c4], k2 = kv2[c4], k3 = kv3[c4];
            sc[0] += mv.x*k0.x + mv.y*k0.y + mv.z*k0.z + mv.w*k0.w;
            sc[1] += mv.x*k1.x + mv.y*k1.y + mv.z*k1.z + mv.w*k1.w;
            sc[2] += mv.x*k2.x + mv.y*k2.y + mv.z*k2.z + mv.w*k2.w;
            sc[3] += mv.x*k3.x + mv.y*k3.y + mv.z*k3.z + mv.w*k3.w;
        }
#pragma unroll
        for (int j = 0; j < 4; j++) at[(g*8 + h)*16 + s0 + 4*j] = sc[j];
    }
    __syncthreads();

    // phase 4: masked softmax (one thread per (g,h))
    if (t < 64) {
        int g = t >> 3, h = t & 7;
        float* row = at + (g*8 + h)*16;
        const int* sg = sid + g*16;
        const float scl = 0.17677669529663687f;   // 1/sqrt(32)
        float sv[16];
        float mx = -3.0e38f;
#pragma unroll
        for (int s = 0; s < 16; s++) {
            sv[s] = (sg[s] < 0) ? -3.0e38f : row[s]*scl;
            mx = fmaxf(mx, sv[s]);
        }
        float sum = 0.f;
#pragma unroll
        for (int s = 0; s < 16; s++) {
            float e = (sg[s] < 0) ? 0.f : expf(sv[s] - mx);
            sv[s] = e; sum += e;
        }
        float inv = 1.f/sum;
#pragma unroll
        for (int s = 0; s < 16; s++) row[s] = sv[s]*inv;
    }
    __syncthreads();

    // phase 5: wkv[g][h][c] = sum_s attn[g][h][s] * kv[g][s][c]  (consecutive-c, v4)
    {
        int g = w;
        float acc[8][8];   // [h][cc], c = lane*8 + cc
#pragma unroll
        for (int i = 0; i < 8; i++)
#pragma unroll
            for (int j = 0; j < 8; j++) acc[i][j] = 0.f;
        for (int s = 0; s < 16; s++) {
            float av[8];
#pragma unroll
            for (int h = 0; h < 8; h++) av[h] = at[(g*8 + h)*16 + s];
            const float* kvrow = kv + (g*16 + s)*CP + lane*8;
            float4 kA = *(const float4*)(kvrow);
            float4 kB = *(const float4*)(kvrow + 4);
            float kk[8] = {kA.x,kA.y,kA.z,kA.w,kB.x,kB.y,kB.z,kB.w};
#pragma unroll
            for (int h = 0; h < 8; h++)
#pragma unroll
                for (int cc = 0; cc < 8; cc++) acc[h][cc] += av[h]*kk[cc];
        }
#pragma unroll
        for (int h = 0; h < 8; h++) {
            float* dst = mb + (g*8 + h)*CP + lane*8;
            *(float4*)(dst)     = make_float4(acc[h][0], acc[h][1], acc[h][2], acc[h][3]);
            *(float4*)(dst + 4) = make_float4(acc[h][4], acc[h][5], acc[h][6], acc[h][7]);
        }
    }
    __syncthreads();

    // phase 6: ao[g][h*32+d] = sum_c wkv[g][h][c] * v_wT[c][h*32+d] + v_b  (v4 mb reads)
    {
        int h = w, d = lane;
        float acc[8];
#pragma unroll
        for (int g = 0; g < 8; g++) acc[g] = 0.f;
        const float* wcol = g_vwT + h*32 + d;
        for (int c4 = 0; c4 < 64; c4++) {
            float w0 = __ldg(wcol + (size_t)(4*c4+0)*CDIM);
            float w1 = __ldg(wcol + (size_t)(4*c4+1)*CDIM);
            float w2 = __ldg(wcol + (size_t)(4*c4+2)*CDIM);
            float w3 = __ldg(wcol + (size_t)(4*c4+3)*CDIM);
#pragma unroll
            for (int g = 0; g < 8; g++) {
                float4 mv = *(const float4*)&mb[(g*8 + h)*CP + 4*c4];
                acc[g] += mv.x*w0 + mv.y*w1 + mv.z*w2 + mv.w*w3;
            }
        }
        float vb = v_b[h*32 + d];
#pragma unroll
        for (int g = 0; g < 8; g++)
            g_ao[(size_t)(bq0 + g)*CDIM + h*32 + d] = to_tf32(acc[g] + vb);
    }
}

// ---------------- layernorm of (ra + rb + rc), writes full + tf32-rounded ----------
__global__ void k_ln(const float* __restrict__ ra, const float* __restrict__ rb,
                     const float* __restrict__ rc,
                     const float* __restrict__ gamma, const float* __restrict__ beta,
                     float* __restrict__ out, float* __restrict__ outr) {
    int bq = blockIdx.x * 8 + (threadIdx.x >> 5);
    int lane = threadIdx.x & 31;
    float v[8];
    float s = 0.f;
#pragma unroll
    for (int i = 0; i < 8; i++) {
        int c = lane + 32*i;
        v[i] = ra[(size_t)bq*CDIM + c] + rb[(size_t)bq*CDIM + c] + rc[(size_t)bq*CDIM + c];
        s += v[i];
    }
#pragma unroll
    for (int o = 16; o; o >>= 1) s += __shfl_xor_sync(0xffffffffu, s, o);
    float mean = s * (1.f/256.f);
    float vs = 0.f;
#pragma unroll
    for (int i = 0; i < 8; i++) { float d = v[i]-mean; vs += d*d; }
#pragma unroll
    for (int o = 16; o; o >>= 1) vs += __shfl_xor_sync(0xffffffffu, vs, o);
    float rstd = rsqrtf(vs*(1.f/256.f) + 1e-5f);
#pragma unroll
    for (int i = 0; i < 8; i++) {
        int c = lane + 32*i;
        float r = (v[i]-mean)*rstd*gamma[c] + beta[c];
        out [(size_t)bq*CDIM + c] = r;
        outr[(size_t)bq*CDIM + c] = to_tf32(r);
    }
}

// ---------------- final LN2 of (ra+rb+rc) + transpose to (B, C, NQ) ----------------
__global__ void k_ln_out(const float* __restrict__ ra, const float* __restrict__ rb,
                         const float* __restrict__ rc,
                         const float* __restrict__ gamma, const float* __restrict__ beta,
                         float* __restrict__ out) {
    int bq = blockIdx.x * 8 + (threadIdx.x >> 5);
    int lane = threadIdx.x & 31;
    int b = bq >> 10, nq = bq & 1023;
    float v[8];
    float s = 0.f;
#pragma unroll
    for (int i = 0; i < 8; i++) {
        int c = lane + 32*i;
        v[i] = ra[(size_t)bq*CDIM + c] + rb[(size_t)bq*CDIM + c] + rc[(size_t)bq*CDIM + c];
        s += v[i];
    }
#pragma unroll
    for (int o = 16; o; o >>= 1) s += __shfl_xor_sync(0xffffffffu, s, o);
    float mean = s * (1.f/256.f);
    float vs = 0.f;
#pragma unroll
    for (int i = 0; i < 8; i++) { float d = v[i]-mean; vs += d*d; }
#pragma unroll
    for (int o = 16; o; o >>= 1) vs += __shfl_xor_sync(0xffffffffu, vs, o);
    float rstd = rsqrtf(vs*(1.f/256.f) + 1e-5f);
#pragma unroll
    for (int i = 0; i < 8; i++) {
        int c = lane + 32*i;
        out[((size_t)b*CDIM + c)*NQD + nq] = (v[i]-mean)*rstd*gamma[c] + beta[c];
    }
}

// ---------------- launch ----------------
extern "C" void kernel_launch(void* const* d_in, const int* in_sizes, int n_in,
                              void* d_out, int out_size) {
    const float* query     = (const float*)d_in[0];
    const float* key       = (const float*)d_in[1];
    const float* query_pos = (const float*)d_in[2];
    const float* key_pos   = (const float*)d_in[3];
    const float* q_w   = (const float*)d_in[4];
    const float* q_b   = (const float*)d_in[5];
    const float* k_w   = (const float*)d_in[6];
    // d_in[7] = k_b: cancels in softmax (uniform shift per (bq,h))
    const float* v_w   = (const float*)d_in[8];
    const float* v_b   = (const float*)d_in[9];
    const float* o_w   = (const float*)d_in[10];
    const float* o_b   = (const float*)d_in[11];
    const float* lin1_w = (const float*)d_in[12];
    const float* lin1_b = (const float*)d_in[13];
    const float* lin2_w = (const float*)d_in[14];
    const float* lin2_b = (const float*)d_in[15];
    const float* n1_g = (const float*)d_in[16];
    const float* n1_b = (const float*)d_in[17];
    const float* n2_g = (const float*)d_in[18];
    const float* n2_b = (const float*)d_in[19];
    const float* qpe_w = (const float*)d_in[20];
    const float* qpe_b = (const float*)d_in[21];
    const float* kpe_w = (const float*)d_in[22];
    const float* kpe_b = (const float*)d_in[23];

    void *p_qin, *p_qh, *p_ao, *p_res1, *p_qtok, *p_x, *p_xr, *p_ff, *p_y;
    void *p_qwr, *p_owr, *p_l1r, *p_l2r;
    cudaGetSymbolAddress(&p_qin,  g_qin);
    cudaGetSymbolAddress(&p_qh,   g_qh);
    cudaGetSymbolAddress(&p_ao,   g_ao);
    cudaGetSymbolAddress(&p_res1, g_res1);
    cudaGetSymbolAddress(&p_qtok, g_qtok);
    cudaGetSymbolAddress(&p_x,    g_x);
    cudaGetSymbolAddress(&p_xr,   g_xr);
    cudaGetSymbolAddress(&p_ff,   g_ff);
    cudaGetSymbolAddress(&p_y,    g_y);
    cudaGetSymbolAddress(&p_qwr,  g_qwr);
    cudaGetSymbolAddress(&p_owr,  g_owr);
    cudaGetSymbolAddress(&p_l1r,  g_l1r);
    cudaGetSymbolAddress(&p_l2r,  g_l2r);

    const size_t SLICE = (size_t)BQTOT * CDIM;

    const int attn_smem = (8*16*CP + 8*8*CP + 8*256 + 8*128 + 4*256 + 32)*4 + 128*4;
    cudaFuncSetAttribute(k_attn, cudaFuncAttributeMaxDynamicSharedMemorySize, attn_smem);

    const int gemm_smem = 2 * STAGE_F * 4;    // 73,728 bytes (2 stages)
    cudaFuncSetAttribute(k_gemm_mma<0,0>, cudaFuncAttributeMaxDynamicSharedMemorySize, gemm_smem);
    cudaFuncSetAttribute(k_gemm_mma<1,1>, cudaFuncAttributeMaxDynamicSharedMemorySize, gemm_smem);

    // preprocessing
    k_transpose_key<<<dim3(NKD/32, CDIM/32, BATCH), dim3(32,8)>>>(key);
    k_build_q<<<dim3(NQD/32, CDIM/32, BATCH), dim3(32,8)>>>(query, query_pos, qpe_w, qpe_b);
    k_transpose_vw<<<dim3(CDIM/32, CDIM/32), dim3(32,8)>>>(v_w);
    k_boxquery<<<dim3(NQD/8, BATCH), 256>>>(key_pos, query_pos);

    // tf32-round the GEMM weights (round-to-nearest, unbiased)
    k_round<<<CDIM*CDIM/256, 256>>>(q_w,    (float*)p_qwr, CDIM*CDIM);
    k_round<<<CDIM*CDIM/256, 256>>>(o_w,    (float*)p_owr, CDIM*CDIM);
    k_round<<<FFDIM*CDIM/256, 256>>>(lin1_w, (float*)p_l1r, FFDIM*CDIM);
    k_round<<<CDIM*FFDIM/256, 256>>>(lin2_w, (float*)p_l2r, CDIM*FFDIM);

    // q projection: qh = qin @ q_w^T + q_b   (split-K x2, 256 CTAs)
    k_gemm_mma<0,0><<<dim3(CDIM/128, BQTOT/128, 2), 256, gemm_smem>>>(
        (const float*)p_qin, (const float*)p_qwr, q_b, (float*)p_qh,
        CDIM, CDIM, 128, SLICE);

    // fused gather + attention -> ao (sums the two qh slices internally)
    k_attn<<<BQTOT/8, 256, attn_smem>>>(key_pos, query_pos, kpe_w, kpe_b, k_w, v_b);

    // o projection (split-K x2)
    k_gemm_mma<0,0><<<dim3(CDIM/128, BQTOT/128, 2), 256, gemm_smem>>>(
        (const float*)p_ao, (const float*)p_owr, o_b, (float*)p_res1,
        CDIM, CDIM, 128, SLICE);

    // LN1(qtok + res1a + res1b) -> x (full) + xr (rounded)
    k_ln<<<BQTOT/8, 256>>>((const float*)p_qtok, (const float*)p_res1,
                           (const float*)p_res1 + SLICE, n1_g, n1_b,
                           (float*)p_x, (float*)p_xr);

    // FFN
    k_gemm_mma<1,1><<<dim3(FFDIM/128, BQTOT/128, 1), 256, gemm_smem>>>(
        (const float*)p_xr, (const float*)p_l1r, lin1_b, (float*)p_ff,
        FFDIM, CDIM, 256, 0);
    k_gemm_mma<0,0><<<dim3(CDIM/128, BQTOT/128, 2), 256, gemm_smem>>>(
        (const float*)p_ff, (const float*)p_l2r, lin2_b, (float*)p_y,
        CDIM, FFDIM, 1024, SLICE);

    // LN2(x + y0 + y1) + transpose out
    k_ln_out<<<BQTOT/8, 256>>>((const float*)p_x, (const float*)p_y,
                               (const float*)p_y + SLICE, n2_g, n2_b, (float*)d_out);
}

// round 6
// speedup vs baseline: 3.6645x; 1.1696x over previous
#include <cuda_runtime.h>
#include <cuda_bf16.h>
#include <math.h>
#include <stdint.h>

#define BATCH 8
#define CDIM  256
#define NQD   1024
#define NKD   4096
#define SKEYS 16
#define HEADS 8
#define FFDIM 2048
#define DHD   32
#define BQTOT (BATCH*NQD)
#define CP    260   // padded smem stride (attn kernel; 16B-aligned rows)

typedef __nv_bfloat16 bf16;

// ---------------- scratch (device globals; no allocation allowed) ----------------
__device__ float g_keyT[BATCH*NKD*CDIM];     // key transposed (B, NK, C)
__device__ float g_qtok[BQTOT*CDIM];         // transposed query tokens (residual)
__device__ bf16  g_qin [BQTOT*CDIM];         // qtok + qpe (bf16, GEMM A)
__device__ float g_qh  [2*BQTOT*CDIM];       // q projection (2 split-K slices)
__device__ int   g_sidx[BQTOT*SKEYS];        // gathered key indices (-1 = masked)
__device__ float g_vwT [CDIM*CDIM];          // v_w transposed
__device__ bf16  g_ao  [BQTOT*CDIM];         // attention output (bf16, GEMM A)
__device__ float g_res1[2*BQTOT*CDIM];       // o-proj output (2 slices)
__device__ float g_x   [BQTOT*CDIM];         // after LN1 (residual)
__device__ bf16  g_xr  [BQTOT*CDIM];         // after LN1 (bf16, GEMM A)
__device__ bf16  g_ff  [BQTOT*FFDIM];        // FFN hidden (bf16, GEMM A)
__device__ float g_y   [2*BQTOT*CDIM];       // FFN out (2 slices)
// bf16 weight copies
__device__ bf16  g_qwr [CDIM*CDIM];
__device__ bf16  g_owr [CDIM*CDIM];
__device__ bf16  g_l1r [FFDIM*CDIM];
__device__ bf16  g_l2r [CDIM*FFDIM];

// ---------------- small PTX helpers ----------------
__device__ __forceinline__ uint32_t smem_u32(const void* p) {
    uint32_t a;
    asm("{ .reg .u64 t; cvta.to.shared.u64 t, %1; cvt.u32.u64 %0, t; }" : "=r"(a) : "l"(p));
    return a;
}
__device__ __forceinline__ void cp16(uint32_t s, const void* g) {
    asm volatile("cp.async.cg.shared.global [%0], [%1], 16;" :: "r"(s), "l"(g));
}
#define CP_COMMIT() asm volatile("cp.async.commit_group;" ::: "memory")
#define CP_WAIT1()  asm volatile("cp.async.wait_group 1;" ::: "memory")

__device__ __forceinline__ void mma_bf16(float* d,
                                         uint32_t a0, uint32_t a1, uint32_t a2, uint32_t a3,
                                         uint32_t b0, uint32_t b1) {
    asm volatile(
        "mma.sync.aligned.m16n8k16.row.col.f32.bf16.bf16.f32 "
        "{%0,%1,%2,%3}, {%4,%5,%6,%7}, {%8,%9}, {%0,%1,%2,%3};"
        : "+f"(d[0]), "+f"(d[1]), "+f"(d[2]), "+f"(d[3])
        : "r"(a0), "r"(a1), "r"(a2), "r"(a3), "r"(b0), "r"(b1));
}

// ---------------- bf16 mma.sync GEMM: C = A(M,lda) @ W(N,lda)^T (+ bias on z=0) ----
// 128x128 tile, BK=64 (bf16), 8 warps (4x2), warp tile 32x64, double-buffered cp.async.
// Split-K: blockIdx.z selects K-slice [z*KS, (z+1)*KS), writes to Cout + z*outStride.
#define PADB 72                  // bf16 elems per smem row (144B, conflict-free)
#define STAGE_H (2*128*PADB)     // bf16 elems per stage (A + B)

template<int RELU, int OUTBF>
__global__ void __launch_bounds__(256)
k_gemm_bf(const bf16* __restrict__ A, const bf16* __restrict__ W,
          const float* __restrict__ bias, void* __restrict__ Cout,
          int N, int lda, int KS, size_t outStride) {
    extern __shared__ bf16 smh[];
    int t = threadIdx.x, lane = t & 31, wid = t >> 5;
    int wm = wid >> 1, wn = wid & 1;          // warp tile origin (wm*32, wn*64)
    int bm = blockIdx.y * 128, bn = blockIdx.x * 128;
    int kb = blockIdx.z * KS;
    const int NC = KS >> 6;
    int qr = lane >> 2, qc = lane & 3;        // quad row / quad col

    float acc[2][8][4];
#pragma unroll
    for (int mi = 0; mi < 2; mi++)
#pragma unroll
        for (int ni = 0; ni < 8; ni++)
#pragma unroll
            for (int j = 0; j < 4; j++) acc[mi][ni][j] = 0.f;

    // stage 0 prologue: chunk 0 (64 bf16 per row = 8 segs of 8)
    {
        bf16* As = smh; bf16* Bs = smh + 128*PADB;
        for (int u = t; u < 1024; u += 256) {
            int row = u >> 3, seg = u & 7;
            cp16(smem_u32(As + row*PADB + seg*8), A + (size_t)(bm + row)*lda + kb + seg*8);
            cp16(smem_u32(Bs + row*PADB + seg*8), W + (size_t)(bn + row)*lda + kb + seg*8);
        }
    }
    CP_COMMIT();

    for (int c = 0; c < NC; c++) {
        __syncthreads();                       // stage (c+1)&1 free (compute c-1 done)
        if (c + 1 < NC) {
            bf16* As = smh + ((c+1)&1)*STAGE_H;
            bf16* Bs = As + 128*PADB;
            int k0 = kb + (c+1)*64;
            for (int u = t; u < 1024; u += 256) {
                int row = u >> 3, seg = u & 7;
                cp16(smem_u32(As + row*PADB + seg*8), A + (size_t)(bm + row)*lda + k0 + seg*8);
                cp16(smem_u32(Bs + row*PADB + seg*8), W + (size_t)(bn + row)*lda + k0 + seg*8);
            }
        }
        CP_COMMIT();
        CP_WAIT1();                            // stage c copies done (this thread)
        __syncthreads();                       // all threads' stage-c copies visible

        const bf16* As = smh + (c&1)*STAGE_H;
        const bf16* Bs = As + 128*PADB;
#pragma unroll
        for (int kk = 0; kk < 4; kk++) {
            int k0 = kk*16;
            uint32_t bf[8][2];
#pragma unroll
            for (int ni = 0; ni < 8; ni++) {
                int n = wn*64 + ni*8 + qr;
                bf[ni][0] = *(const uint32_t*)&Bs[n*PADB + k0 + 2*qc];
                bf[ni][1] = *(const uint32_t*)&Bs[n*PADB + k0 + 8 + 2*qc];
            }
#pragma unroll
            for (int mi = 0; mi < 2; mi++) {
                int r = wm*32 + mi*16 + qr;
                uint32_t a0 = *(const uint32_t*)&As[r*PADB + k0 + 2*qc];
                uint32_t a1 = *(const uint32_t*)&As[(r+8)*PADB + k0 + 2*qc];
                uint32_t a2 = *(const uint32_t*)&As[r*PADB + k0 + 8 + 2*qc];
                uint32_t a3 = *(const uint32_t*)&As[(r+8)*PADB + k0 + 8 + 2*qc];
#pragma unroll
                for (int ni = 0; ni < 8; ni++)
                    mma_bf16(acc[mi][ni], a0, a1, a2, a3, bf[ni][0], bf[ni][1]);
            }
        }
    }

    // epilogue: direct stores; bias only on z=0
    bool addb = (blockIdx.z == 0);
#pragma unroll
    for (int mi = 0; mi < 2; mi++) {
        int r0 = bm + wm*32 + mi*16 + qr;
#pragma unroll
        for (int ni = 0; ni < 8; ni++) {
            int cn = bn + wn*64 + ni*8 + qc*2;
            float b0 = addb ? bias[cn] : 0.f, b1 = addb ? bias[cn+1] : 0.f;
            float v0 = acc[mi][ni][0] + b0, v1 = acc[mi][ni][1] + b1;
            float v2 = acc[mi][ni][2] + b0, v3 = acc[mi][ni][3] + b1;
            if (RELU) { v0=fmaxf(v0,0.f); v1=fmaxf(v1,0.f); v2=fmaxf(v2,0.f); v3=fmaxf(v3,0.f); }
            if (OUTBF) {
                bf16* C = (bf16*)Cout;
                *(__nv_bfloat162*)&C[(size_t)r0*N + cn]     = __floats2bfloat162_rn(v0, v1);
                *(__nv_bfloat162*)&C[(size_t)(r0+8)*N + cn] = __floats2bfloat162_rn(v2, v3);
            } else {
                float* C = (float*)Cout + (size_t)blockIdx.z * outStride;
                *(float2*)&C[(size_t)r0*N + cn]     = make_float2(v0, v1);
                *(float2*)&C[(size_t)(r0+8)*N + cn] = make_float2(v2, v3);
            }
        }
    }
}

// ---------------- elementwise f32 -> bf16 ----------------
__global__ void k_round(const float* __restrict__ in, bf16* __restrict__ out, int n) {
    int i = blockIdx.x * 256 + threadIdx.x;
    if (i < n) out[i] = __float2bfloat16_rn(in[i]);
}

// ---------------- transpose key (B,C,NK) -> (B,NK,C) ----------------
__global__ void k_transpose_key(const float* __restrict__ key) {
    __shared__ float tile[32][33];
    int b = blockIdx.z;
    int c0 = blockIdx.y * 32, n0 = blockIdx.x * 32;
    int tx = threadIdx.x, ty = threadIdx.y;
#pragma unroll
    for (int j = 0; j < 4; j++)
        tile[ty + 8*j][tx] = key[(b*CDIM + c0 + ty + 8*j)*NKD + n0 + tx];
    __syncthreads();
#pragma unroll
    for (int j = 0; j < 4; j++)
        g_keyT[(b*NKD + n0 + ty + 8*j)*CDIM + c0 + tx] = tile[tx][ty + 8*j];
}

// ---------------- build qtok + qin (query transpose + qpe) ----------------
__global__ void k_build_q(const float* __restrict__ query,
                          const float* __restrict__ query_pos,
                          const float* __restrict__ qpe_w,
                          const float* __restrict__ qpe_b) {
    __shared__ float tile[32][33];
    int b = blockIdx.z;
    int c0 = blockIdx.y * 32, n0 = blockIdx.x * 32;
    int tx = threadIdx.x, ty = threadIdx.y;
#pragma unroll
    for (int j = 0; j < 4; j++)
        tile[ty + 8*j][tx] = query[(b*CDIM + c0 + ty + 8*j)*NQD + n0 + tx];
    __syncthreads();
#pragma unroll
    for (int j = 0; j < 4; j++) {
        int nq = n0 + ty + 8*j, c = c0 + tx;
        int bq = b*NQD + nq;
        float qt = tile[tx][ty + 8*j];
        const float* qp = query_pos + (size_t)bq*6;
        float pe = qpe_b[c];
#pragma unroll
        for (int jj = 0; jj < 6; jj++) pe += qp[jj] * qpe_w[c*6 + jj];
        g_qtok[bq*CDIM + c] = qt;
        g_qin [bq*CDIM + c] = __float2bfloat16_rn(qt + pe);
    }
}

// ---------------- transpose v_w (256x256) ----------------
__global__ void k_transpose_vw(const float* __restrict__ v_w) {
    __shared__ float tile[32][33];
    int n0 = blockIdx.y * 32, c0 = blockIdx.x * 32;
    int tx = threadIdx.x, ty = threadIdx.y;
#pragma unroll
    for (int j = 0; j < 4; j++)
        tile[ty + 8*j][tx] = v_w[(n0 + ty + 8*j)*CDIM + c0 + tx];
    __syncthreads();
#pragma unroll
    for (int j = 0; j < 4; j++)
        g_vwT[(c0 + ty + 8*j)*CDIM + n0 + tx] = tile[tx][ty + 8*j];
}

// ---------------- box query: first 16 inside-box keys, in index order ----------------
__global__ void k_boxquery(const float* __restrict__ key_pos,
                           const float* __restrict__ query_pos) {
    __shared__ float kp[NKD*3];   // exactly 48KB
    int b = blockIdx.y;
    int t = threadIdx.x;
#pragma unroll
    for (int i = 0; i < 48; i++)
        kp[t + 256*i] = key_pos[(size_t)b*NKD*3 + t + 256*i];
    __syncthreads();

    int w = t >> 5, lane = t & 31;
    int q = blockIdx.x * 8 + w;
    int bq = b*NQD + q;
    const float* qp = query_pos + (size_t)bq*6;
    float cx = qp[0], cy = qp[1], cz = qp[2];
    float hx = 0.5f*qp[3], hy = 0.5f*qp[4], hz = 0.5f*qp[5];

    int count = 0;
    for (int base = 0; base < NKD && count < SKEYS; base += 32) {
        int k = base + lane;
        float dx = fabsf(kp[k*3+0]-cx);
        float dy = fabsf(kp[k*3+1]-cy);
        float dz = fabsf(kp[k*3+2]-cz);
        bool inside = (dx <= hx) && (dy <= hy) && (dz <= hz);
        unsigned bal = __ballot_sync(0xffffffffu, inside);
        int nb = __popc(bal);
        if (inside) {
            int rank = __popc(bal & ((1u << lane) - 1u));
            if (count + rank < SKEYS) g_sidx[bq*SKEYS + count + rank] = k;
        }
        count += nb;
        if (count > SKEYS) count = SKEYS;
    }
    if (lane < SKEYS && lane >= count)
        g_sidx[bq*SKEYS + lane] = (lane == 0) ? 0 : -1;
}

// ---------------- fused gather + attention (8 queries per block, vectorized) -------
__global__ void k_attn(const float* __restrict__ key_pos,
                       const float* __restrict__ query_pos,
                       const float* __restrict__ kpe_w,
                       const float* __restrict__ kpe_b,
                       const float* __restrict__ k_w,
                       const float* __restrict__ v_b) {
    extern __shared__ float sm[];
    float* kv = sm;                     // [8][16][CP]
    float* mb = kv + 8*16*CP;           // [8][8][CP]   (m, later wkv)
    float* qs = mb + 8*8*CP;            // [8][256]
    float* at = qs + 8*256;             // [8][8][16]   (scores, then attn)
    float* pes = at + 8*128;            // [4][256]  kpe SoA: w0,w1,w2,b
    float* qc = pes + 4*256;            // [8][4]
    int*  sid = (int*)(qc + 32);        // [8][16]

    int t = threadIdx.x, lane = t & 31, w = t >> 5;
    int bq0 = blockIdx.x * 8;
    int b = bq0 >> 10;   // NQ=1024

    if (t < 128) sid[t] = g_sidx[bq0*SKEYS + t];
    if (t < 24) { int g = t/3, j = t%3; qc[g*4 + j] = query_pos[(size_t)(bq0+g)*6 + j]; }
    {   // kpe SoA staging
        pes[0*256 + t] = kpe_w[t*3 + 0];
        pes[1*256 + t] = kpe_w[t*3 + 1];
        pes[2*256 + t] = kpe_w[t*3 + 2];
        pes[3*256 + t] = kpe_b[t];
    }
#pragma unroll
    for (int i = 0; i < 8; i++)
        qs[t + 256*i] = g_qh[(size_t)bq0*CDIM + t + 256*i]
                      + g_qh[(size_t)BQTOT*CDIM + (size_t)bq0*CDIM + t + 256*i];
    __syncthreads();

    // phase 1: gather kv = keyT[idx] + kpe(gxyz)   (float4)
    {
        int g = w;
        float qcx = qc[g*4+0], qcy = qc[g*4+1], qcz = qc[g*4+2];
        for (int s = 0; s < SKEYS; s++) {
            int v = sid[g*16 + s];
            int kidx = v < 0 ? 0 : v;
            int base = b*NKD + kidx;
            float gx = key_pos[base*3+0] - qcx;
            float gy = key_pos[base*3+1] - qcy;
            float gz = key_pos[base*3+2] - qcz;
            const float4* krow4 = (const float4*)(g_keyT + (size_t)base*CDIM);
            float* kvrow = kv + (g*16 + s)*CP;
#pragma unroll
            for (int i = 0; i < 2; i++) {
                int c4 = lane + 32*i;
                float4 kr = krow4[c4];
                float4 w0 = *(const float4*)&pes[0*256 + 4*c4];
                float4 w1 = *(const float4*)&pes[1*256 + 4*c4];
                float4 w2 = *(const float4*)&pes[2*256 + 4*c4];
                float4 bb = *(const float4*)&pes[3*256 + 4*c4];
                float4 r;
                r.x = kr.x + bb.x + gx*w0.x + gy*w1.x + gz*w2.x;
                r.y = kr.y + bb.y + gx*w0.y + gy*w1.y + gz*w2.y;
                r.z = kr.z + bb.z + gx*w0.z + gy*w1.z + gz*w2.z;
                r.w = kr.w + bb.w + gx*w0.w + gy*w1.w + gz*w2.w;
                *(float4*)&kvrow[4*c4] = r;
            }
        }
    }
    __syncthreads();

    // phase 2: m[g][h][c] = sum_d k_w[h*32+d, c] * qh[g][h*32+d]
    {
        int h = w;
        float acc[8][8];   // [cc][g]
#pragma unroll
        for (int i = 0; i < 8; i++)
#pragma unroll
            for (int j = 0; j < 8; j++) acc[i][j] = 0.f;
        for (int d = 0; d < 32; d++) {
            float qv[8];
#pragma unroll
            for (int g = 0; g < 8; g++) qv[g] = qs[g*256 + h*32 + d];
            const float* wr = k_w + (size_t)(h*32 + d)*CDIM;
#pragma unroll
            for (int cc = 0; cc < 8; cc++) {
                float wv = __ldg(wr + lane + 32*cc);
#pragma unroll
                for (int g = 0; g < 8; g++) acc[cc][g] += wv * qv[g];
            }
        }
#pragma unroll
        for (int cc = 0; cc < 8; cc++)
#pragma unroll
            for (int g = 0; g < 8; g++)
                mb[(g*8 + h)*CP + lane + 32*cc] = acc[cc][g];
    }
    __syncthreads();

    // phase 3: scores[g][h][s] = m[g][h] . kv[g][s]   (float4)
    {
        int g = w, h = lane >> 2, s0 = lane & 3;
        float sc[4] = {0.f, 0.f, 0.f, 0.f};
        const float4* m4 = (const float4*)(mb + (g*8 + h)*CP);
        const float4* kv0 = (const float4*)(kv + (g*16 + s0 + 0)*CP);
        const float4* kv1 = (const float4*)(kv + (g*16 + s0 + 4)*CP);
        const float4* kv2 = (const float4*)(kv + (g*16 + s0 + 8)*CP);
        const float4* kv3 = (const float4*)(kv + (g*16 + s0 + 12)*CP);
        for (int c4 = 0; c4 < 64; c4++) {
            float4 mv = m4[c4];
            float4 k0 = kv0[c4], k1 = kv1[c4], k2 = kv2[c4], k3 = kv3[c4];
            sc[0] += mv.x*k0.x + mv.y*k0.y + mv.z*k0.z + mv.w*k0.w;
            sc[1] += mv.x*k1.x + mv.y*k1.y + mv.z*k1.z + mv.w*k1.w;
            sc[2] += mv.x*k2.x + mv.y*k2.y + mv.z*k2.z + mv.w*k2.w;
            sc[3] += mv.x*k3.x + mv.y*k3.y + mv.z*k3.z + mv.w*k3.w;
        }
#pragma unroll
        for (int j = 0; j < 4; j++) at[(g*8 + h)*16 + s0 + 4*j] = sc[j];
    }
    __syncthreads();

    // phase 4: masked softmax (one thread per (g,h))
    if (t < 64) {
        int g = t >> 3, h = t & 7;
        float* row = at + (g*8 + h)*16;
        const int* sg = sid + g*16;
        const float scl = 0.17677669529663687f;   // 1/sqrt(32)
        float sv[16];
        float mx = -3.0e38f;
#pragma unroll
        for (int s = 0; s < 16; s++) {
            sv[s] = (sg[s] < 0) ? -3.0e38f : row[s]*scl;
            mx = fmaxf(mx, sv[s]);
        }
        float sum = 0.f;
#pragma unroll
        for (int s = 0; s < 16; s++) {
            float e = (sg[s] < 0) ? 0.f : expf(sv[s] - mx);
            sv[s] = e; sum += e;
        }
        float inv = 1.f/sum;
#pragma unroll
        for (int s = 0; s < 16; s++) row[s] = sv[s]*inv;
    }
    __syncthreads();

    // phase 5: wkv[g][h][c] = sum_s attn[g][h][s] * kv[g][s][c]  (consecutive-c, v4)
    {
        int g = w;
        float acc[8][8];   // [h][cc], c = lane*8 + cc
#pragma unroll
        for (int i = 0; i < 8; i++)
#pragma unroll
            for (int j = 0; j < 8; j++) acc[i][j] = 0.f;
        for (int s = 0; s < 16; s++) {
            float av[8];
#pragma unroll
            for (int h = 0; h < 8; h++) av[h] = at[(g*8 + h)*16 + s];
            const float* kvrow = kv + (g*16 + s)*CP + lane*8;
            float4 kA = *(const float4*)(kvrow);
            float4 kB = *(const float4*)(kvrow + 4);
            float kk[8] = {kA.x,kA.y,kA.z,kA.w,kB.x,kB.y,kB.z,kB.w};
#pragma unroll
            for (int h = 0; h < 8; h++)
#pragma unroll
                for (int cc = 0; cc < 8; cc++) acc[h][cc] += av[h]*kk[cc];
        }
#pragma unroll
        for (int h = 0; h < 8; h++) {
            float* dst = mb + (g*8 + h)*CP + lane*8;
            *(float4*)(dst)     = make_float4(acc[h][0], acc[h][1], acc[h][2], acc[h][3]);
            *(float4*)(dst + 4) = make_float4(acc[h][4], acc[h][5], acc[h][6], acc[h][7]);
        }
    }
    __syncthreads();

    // phase 6: ao[g][h*32+d] = sum_c wkv[g][h][c] * v_wT[c][h*32+d] + v_b  (bf16 out)
    {
        int h = w, d = lane;
        float acc[8];
#pragma unroll
        for (int g = 0; g < 8; g++) acc[g] = 0.f;
        const float* wcol = g_vwT + h*32 + d;
        for (int c4 = 0; c4 < 64; c4++) {
            float w0 = __ldg(wcol + (size_t)(4*c4+0)*CDIM);
            float w1 = __ldg(wcol + (size_t)(4*c4+1)*CDIM);
            float w2 = __ldg(wcol + (size_t)(4*c4+2)*CDIM);
            float w3 = __ldg(wcol + (size_t)(4*c4+3)*CDIM);
#pragma unroll
            for (int g = 0; g < 8; g++) {
                float4 mv = *(const float4*)&mb[(g*8 + h)*CP + 4*c4];
                acc[g] += mv.x*w0 + mv.y*w1 + mv.z*w2 + mv.w*w3;
            }
        }
        float vb = v_b[h*32 + d];
#pragma unroll
        for (int g = 0; g < 8; g++)
            g_ao[(size_t)(bq0 + g)*CDIM + h*32 + d] = __float2bfloat16_rn(acc[g] + vb);
    }
}

// ---------------- layernorm of (ra + rb + rc), writes full f32 + bf16 ----------
__global__ void k_ln(const float* __restrict__ ra, const float* __restrict__ rb,
                     const float* __restrict__ rc,
                     const float* __restrict__ gamma, const float* __restrict__ beta,
                     float* __restrict__ out, bf16* __restrict__ outr) {
    int bq = blockIdx.x * 8 + (threadIdx.x >> 5);
    int lane = threadIdx.x & 31;
    float v[8];
    float s = 0.f;
#pragma unroll
    for (int i = 0; i < 8; i++) {
        int c = lane + 32*i;
        v[i] = ra[(size_t)bq*CDIM + c] + rb[(size_t)bq*CDIM + c] + rc[(size_t)bq*CDIM + c];
        s += v[i];
    }
#pragma unroll
    for (int o = 16; o; o >>= 1) s += __shfl_xor_sync(0xffffffffu, s, o);
    float mean = s * (1.f/256.f);
    float vs = 0.f;
#pragma unroll
    for (int i = 0; i < 8; i++) { float d = v[i]-mean; vs += d*d; }
#pragma unroll
    for (int o = 16; o; o >>= 1) vs += __shfl_xor_sync(0xffffffffu, vs, o);
    float rstd = rsqrtf(vs*(1.f/256.f) + 1e-5f);
#pragma unroll
    for (int i = 0; i < 8; i++) {
        int c = lane + 32*i;
        float r = (v[i]-mean)*rstd*gamma[c] + beta[c];
        out [(size_t)bq*CDIM + c] = r;
        outr[(size_t)bq*CDIM + c] = __float2bfloat16_rn(r);
    }
}

// ---------------- final LN2 of (ra+rb+rc) + transpose to (B, C, NQ) ----------------
__global__ void k_ln_out(const float* __restrict__ ra, const float* __restrict__ rb,
                         const float* __restrict__ rc,
                         const float* __restrict__ gamma, const float* __restrict__ beta,
                         float* __restrict__ out) {
    int bq = blockIdx.x * 8 + (threadIdx.x >> 5);
    int lane = threadIdx.x & 31;
    int b = bq >> 10, nq = bq & 1023;
    float v[8];
    float s = 0.f;
#pragma unroll
    for (int i = 0; i < 8; i++) {
        int c = lane + 32*i;
        v[i] = ra[(size_t)bq*CDIM + c] + rb[(size_t)bq*CDIM + c] + rc[(size_t)bq*CDIM + c];
        s += v[i];
    }
#pragma unroll
    for (int o = 16; o; o >>= 1) s += __shfl_xor_sync(0xffffffffu, s, o);
    float mean = s * (1.f/256.f);
    float vs = 0.f;
#pragma unroll
    for (int i = 0; i < 8; i++) { float d = v[i]-mean; vs += d*d; }
#pragma unroll
    for (int o = 16; o; o >>= 1) vs += __shfl_xor_sync(0xffffffffu, vs, o);
    float rstd = rsqrtf(vs*(1.f/256.f) + 1e-5f);
#pragma unroll
    for (int i = 0; i < 8; i++) {
        int c = lane + 32*i;
        out[((size_t)b*CDIM + c)*NQD + nq] = (v[i]-mean)*rstd*gamma[c] + beta[c];
    }
}

// ---------------- launch ----------------
extern "C" void kernel_launch(void* const* d_in, const int* in_sizes, int n_in,
                              void* d_out, int out_size) {
    const float* query     = (const float*)d_in[0];
    const float* key       = (const float*)d_in[1];
    const float* query_pos = (const float*)d_in[2];
    const float* key_pos   = (const float*)d_in[3];
    const float* q_w   = (const float*)d_in[4];
    const float* q_b   = (const float*)d_in[5];
    const float* k_w   = (const float*)d_in[6];
    // d_in[7] = k_b: cancels in softmax (uniform shift per (bq,h))
    const float* v_w   = (const float*)d_in[8];
    const float* v_b   = (const float*)d_in[9];
    const float* o_w   = (const float*)d_in[10];
    const float* o_b   = (const float*)d_in[11];
    const float* lin1_w = (const float*)d_in[12];
    const float* lin1_b = (const float*)d_in[13];
    const float* lin2_w = (const float*)d_in[14];
    const float* lin2_b = (const float*)d_in[15];
    const float* n1_g = (const float*)d_in[16];
    const float* n1_b = (const float*)d_in[17];
    const float* n2_g = (const float*)d_in[18];
    const float* n2_b = (const float*)d_in[19];
    const float* qpe_w = (const float*)d_in[20];
    const float* qpe_b = (const float*)d_in[21];
    const float* kpe_w = (const float*)d_in[22];
    const float* kpe_b = (const float*)d_in[23];

    void *p_qin, *p_qh, *p_ao, *p_res1, *p_qtok, *p_x, *p_xr, *p_ff, *p_y;
    void *p_qwr, *p_owr, *p_l1r, *p_l2r;
    cudaGetSymbolAddress(&p_qin,  g_qin);
    cudaGetSymbolAddress(&p_qh,   g_qh);
    cudaGetSymbolAddress(&p_ao,   g_ao);
    cudaGetSymbolAddress(&p_res1, g_res1);
    cudaGetSymbolAddress(&p_qtok, g_qtok);
    cudaGetSymbolAddress(&p_x,    g_x);
    cudaGetSymbolAddress(&p_xr,   g_xr);
    cudaGetSymbolAddress(&p_ff,   g_ff);
    cudaGetSymbolAddress(&p_y,    g_y);
    cudaGetSymbolAddress(&p_qwr,  g_qwr);
    cudaGetSymbolAddress(&p_owr,  g_owr);
    cudaGetSymbolAddress(&p_l1r,  g_l1r);
    cudaGetSymbolAddress(&p_l2r,  g_l2r);

    const size_t SLICE = (size_t)BQTOT * CDIM;

    const int attn_smem = (8*16*CP + 8*8*CP + 8*256 + 8*128 + 4*256 + 32)*4 + 128*4;
    cudaFuncSetAttribute(k_attn, cudaFuncAttributeMaxDynamicSharedMemorySize, attn_smem);

    const int gemm_smem = 2 * STAGE_H * 2;    // 73,728 bytes (2 stages, bf16)
    cudaFuncSetAttribute(k_gemm_bf<0,0>, cudaFuncAttributeMaxDynamicSharedMemorySize, gemm_smem);
    cudaFuncSetAttribute(k_gemm_bf<1,1>, cudaFuncAttributeMaxDynamicSharedMemorySize, gemm_smem);

    // preprocessing
    k_transpose_key<<<dim3(NKD/32, CDIM/32, BATCH), dim3(32,8)>>>(key);
    k_build_q<<<dim3(NQD/32, CDIM/32, BATCH), dim3(32,8)>>>(query, query_pos, qpe_w, qpe_b);
    k_transpose_vw<<<dim3(CDIM/32, CDIM/32), dim3(32,8)>>>(v_w);
    k_boxquery<<<dim3(NQD/8, BATCH), 256>>>(key_pos, query_pos);

    // bf16 weight copies (round-to-nearest)
    k_round<<<CDIM*CDIM/256, 256>>>(q_w,    (bf16*)p_qwr, CDIM*CDIM);
    k_round<<<CDIM*CDIM/256, 256>>>(o_w,    (bf16*)p_owr, CDIM*CDIM);
    k_round<<<FFDIM*CDIM/256, 256>>>(lin1_w, (bf16*)p_l1r, FFDIM*CDIM);
    k_round<<<CDIM*FFDIM/256, 256>>>(lin2_w, (bf16*)p_l2r, CDIM*FFDIM);

    // q projection: qh = qin @ q_w^T + q_b   (split-K x2, 256 CTAs)
    k_gemm_bf<0,0><<<dim3(CDIM/128, BQTOT/128, 2), 256, gemm_smem>>>(
        (const bf16*)p_qin, (const bf16*)p_qwr, q_b, p_qh,
        CDIM, CDIM, 128, SLICE);

    // fused gather + attention -> ao (sums the two qh slices internally)
    k_attn<<<BQTOT/8, 256, attn_smem>>>(key_pos, query_pos, kpe_w, kpe_b, k_w, v_b);

    // o projection (split-K x2)
    k_gemm_bf<0,0><<<dim3(CDIM/128, BQTOT/128, 2), 256, gemm_smem>>>(
        (const bf16*)p_ao, (const bf16*)p_owr, o_b, p_res1,
        CDIM, CDIM, 128, SLICE);

    // LN1(qtok + res1a + res1b) -> x (f32) + xr (bf16)
    k_ln<<<BQTOT/8, 256>>>((const float*)p_qtok, (const float*)p_res1,
                           (const float*)p_res1 + SLICE, n1_g, n1_b,
                           (float*)p_x, (bf16*)p_xr);

    // FFN
    k_gemm_bf<1,1><<<dim3(FFDIM/128, BQTOT/128, 1), 256, gemm_smem>>>(
        (const bf16*)p_xr, (const bf16*)p_l1r, lin1_b, p_ff,
        FFDIM, CDIM, 256, 0);
    k_gemm_bf<0,0><<<dim3(CDIM/128, BQTOT/128, 2), 256, gemm_smem>>>(
        (const bf16*)p_ff, (const bf16*)p_l2r, lin2_b, p_y,
        CDIM, FFDIM, 1024, SLICE);

    // LN2(x + y0 + y1) + transpose out
    k_ln_out<<<BQTOT/8, 256>>>((const float*)p_x, (const float*)p_y,
                               (const float*)p_y + SLICE, n2_g, n2_b, (float*)d_out);
}

// round 7
// speedup vs baseline: 4.0351x; 1.1011x over previous
#include <cuda_runtime.h>
#include <cuda_bf16.h>
#include <math.h>
#include <stdint.h>

#define BATCH 8
#define CDIM  256
#define NQD   1024
#define NKD   4096
#define SKEYS 16
#define HEADS 8
#define FFDIM 2048
#define DHD   32
#define BQTOT (BATCH*NQD)
#define CP    260   // padded smem stride (attn kernel; 16B-aligned rows)

typedef __nv_bfloat16 bf16;

// ---------------- scratch (device globals; no allocation allowed) ----------------
__device__ float g_keyT[BATCH*NKD*CDIM];     // key transposed (B, NK, C)
__device__ float g_qtok[BQTOT*CDIM];         // transposed query tokens (residual)
__device__ bf16  g_qin [BQTOT*CDIM];         // qtok + qpe (bf16, GEMM A)
__device__ float g_qh  [2*BQTOT*CDIM];       // q projection (2 split-K slices)
__device__ int   g_sidx[BQTOT*SKEYS];        // gathered key indices (-1 = masked)
__device__ float g_vwT [CDIM*CDIM];          // v_w transposed
__device__ bf16  g_ao  [BQTOT*CDIM];         // attention output (bf16, GEMM A)
__device__ float g_res1[2*BQTOT*CDIM];       // o-proj output (2 slices)
__device__ float g_x   [BQTOT*CDIM];         // after LN1 (residual)
__device__ bf16  g_xr  [BQTOT*CDIM];         // after LN1 (bf16, GEMM A)
__device__ bf16  g_ff  [BQTOT*FFDIM];        // FFN hidden (bf16, GEMM A)
__device__ float g_y   [2*BQTOT*CDIM];       // FFN out (2 slices)
// bf16 weight copies
__device__ bf16  g_qwr [CDIM*CDIM];
__device__ bf16  g_owr [CDIM*CDIM];
__device__ bf16  g_l1r [FFDIM*CDIM];
__device__ bf16  g_l2r [CDIM*FFDIM];

// ---------------- small PTX helpers ----------------
__device__ __forceinline__ uint32_t smem_u32(const void* p) {
    uint32_t a;
    asm("{ .reg .u64 t; cvta.to.shared.u64 t, %1; cvt.u32.u64 %0, t; }" : "=r"(a) : "l"(p));
    return a;
}
__device__ __forceinline__ void cp16(uint32_t s, const void* g) {
    asm volatile("cp.async.cg.shared.global [%0], [%1], 16;" :: "r"(s), "l"(g));
}
#define CP_COMMIT() asm volatile("cp.async.commit_group;" ::: "memory")
#define CP_WAIT1()  asm volatile("cp.async.wait_group 1;" ::: "memory")

__device__ __forceinline__ void mma_bf16(float* d,
                                         uint32_t a0, uint32_t a1, uint32_t a2, uint32_t a3,
                                         uint32_t b0, uint32_t b1) {
    asm volatile(
        "mma.sync.aligned.m16n8k16.row.col.f32.bf16.bf16.f32 "
        "{%0,%1,%2,%3}, {%4,%5,%6,%7}, {%8,%9}, {%0,%1,%2,%3};"
        : "+f"(d[0]), "+f"(d[1]), "+f"(d[2]), "+f"(d[3])
        : "r"(a0), "r"(a1), "r"(a2), "r"(a3), "r"(b0), "r"(b1));
}

// ---------------- bf16 mma.sync GEMM: C = A(M,lda) @ W(N,lda)^T (+ bias on z=0) ----
#define PADB 72                  // bf16 elems per smem row (144B, conflict-free)
#define STAGE_H (2*128*PADB)     // bf16 elems per stage (A + B)

template<int RELU, int OUTBF>
__global__ void __launch_bounds__(256)
k_gemm_bf(const bf16* __restrict__ A, const bf16* __restrict__ W,
          const float* __restrict__ bias, void* __restrict__ Cout,
          int N, int lda, int KS, size_t outStride) {
    extern __shared__ bf16 smh[];
    int t = threadIdx.x, lane = t & 31, wid = t >> 5;
    int wm = wid >> 1, wn = wid & 1;          // warp tile origin (wm*32, wn*64)
    int bm = blockIdx.y * 128, bn = blockIdx.x * 128;
    int kb = blockIdx.z * KS;
    const int NC = KS >> 6;
    int qr = lane >> 2, qc = lane & 3;        // quad row / quad col

    float acc[2][8][4];
#pragma unroll
    for (int mi = 0; mi < 2; mi++)
#pragma unroll
        for (int ni = 0; ni < 8; ni++)
#pragma unroll
            for (int j = 0; j < 4; j++) acc[mi][ni][j] = 0.f;

    // stage 0 prologue: chunk 0 (64 bf16 per row = 8 segs of 8)
    {
        bf16* As = smh; bf16* Bs = smh + 128*PADB;
        for (int u = t; u < 1024; u += 256) {
            int row = u >> 3, seg = u & 7;
            cp16(smem_u32(As + row*PADB + seg*8), A + (size_t)(bm + row)*lda + kb + seg*8);
            cp16(smem_u32(Bs + row*PADB + seg*8), W + (size_t)(bn + row)*lda + kb + seg*8);
        }
    }
    CP_COMMIT();

    for (int c = 0; c < NC; c++) {
        __syncthreads();                       // stage (c+1)&1 free (compute c-1 done)
        if (c + 1 < NC) {
            bf16* As = smh + ((c+1)&1)*STAGE_H;
            bf16* Bs = As + 128*PADB;
            int k0 = kb + (c+1)*64;
            for (int u = t; u < 1024; u += 256) {
                int row = u >> 3, seg = u & 7;
                cp16(smem_u32(As + row*PADB + seg*8), A + (size_t)(bm + row)*lda + k0 + seg*8);
                cp16(smem_u32(Bs + row*PADB + seg*8), W + (size_t)(bn + row)*lda + k0 + seg*8);
            }
        }
        CP_COMMIT();
        CP_WAIT1();                            // stage c copies done (this thread)
        __syncthreads();                       // all threads' stage-c copies visible

        const bf16* As = smh + (c&1)*STAGE_H;
        const bf16* Bs = As + 128*PADB;
#pragma unroll
        for (int kk = 0; kk < 4; kk++) {
            int k0 = kk*16;
            uint32_t bf[8][2];
#pragma unroll
            for (int ni = 0; ni < 8; ni++) {
                int n = wn*64 + ni*8 + qr;
                bf[ni][0] = *(const uint32_t*)&Bs[n*PADB + k0 + 2*qc];
                bf[ni][1] = *(const uint32_t*)&Bs[n*PADB + k0 + 8 + 2*qc];
            }
#pragma unroll
            for (int mi = 0; mi < 2; mi++) {
                int r = wm*32 + mi*16 + qr;
                uint32_t a0 = *(const uint32_t*)&As[r*PADB + k0 + 2*qc];
                uint32_t a1 = *(const uint32_t*)&As[(r+8)*PADB + k0 + 2*qc];
                uint32_t a2 = *(const uint32_t*)&As[r*PADB + k0 + 8 + 2*qc];
                uint32_t a3 = *(const uint32_t*)&As[(r+8)*PADB + k0 + 8 + 2*qc];
#pragma unroll
                for (int ni = 0; ni < 8; ni++)
                    mma_bf16(acc[mi][ni], a0, a1, a2, a3, bf[ni][0], bf[ni][1]);
            }
        }
    }

    // epilogue: direct stores; bias only on z=0
    bool addb = (blockIdx.z == 0);
#pragma unroll
    for (int mi = 0; mi < 2; mi++) {
        int r0 = bm + wm*32 + mi*16 + qr;
#pragma unroll
        for (int ni = 0; ni < 8; ni++) {
            int cn = bn + wn*64 + ni*8 + qc*2;
            float b0 = addb ? bias[cn] : 0.f, b1 = addb ? bias[cn+1] : 0.f;
            float v0 = acc[mi][ni][0] + b0, v1 = acc[mi][ni][1] + b1;
            float v2 = acc[mi][ni][2] + b0, v3 = acc[mi][ni][3] + b1;
            if (RELU) { v0=fmaxf(v0,0.f); v1=fmaxf(v1,0.f); v2=fmaxf(v2,0.f); v3=fmaxf(v3,0.f); }
            if (OUTBF) {
                bf16* C = (bf16*)Cout;
                *(__nv_bfloat162*)&C[(size_t)r0*N + cn]     = __floats2bfloat162_rn(v0, v1);
                *(__nv_bfloat162*)&C[(size_t)(r0+8)*N + cn] = __floats2bfloat162_rn(v2, v3);
            } else {
                float* C = (float*)Cout + (size_t)blockIdx.z * outStride;
                *(float2*)&C[(size_t)r0*N + cn]     = make_float2(v0, v1);
                *(float2*)&C[(size_t)(r0+8)*N + cn] = make_float2(v2, v3);
            }
        }
    }
}

// ---------------- elementwise f32 -> bf16 ----------------
__global__ void k_round(const float* __restrict__ in, bf16* __restrict__ out, int n) {
    int i = blockIdx.x * 256 + threadIdx.x;
    if (i < n) out[i] = __float2bfloat16_rn(in[i]);
}

// ---------------- transpose key (B,C,NK) -> (B,NK,C) ----------------
__global__ void k_transpose_key(const float* __restrict__ key) {
    __shared__ float tile[32][33];
    int b = blockIdx.z;
    int c0 = blockIdx.y * 32, n0 = blockIdx.x * 32;
    int tx = threadIdx.x, ty = threadIdx.y;
#pragma unroll
    for (int j = 0; j < 4; j++)
        tile[ty + 8*j][tx] = key[(b*CDIM + c0 + ty + 8*j)*NKD + n0 + tx];
    __syncthreads();
#pragma unroll
    for (int j = 0; j < 4; j++)
        g_keyT[(b*NKD + n0 + ty + 8*j)*CDIM + c0 + tx] = tile[tx][ty + 8*j];
}

// ---------------- build qtok + qin (query transpose + qpe) ----------------
__global__ void k_build_q(const float* __restrict__ query,
                          const float* __restrict__ query_pos,
                          const float* __restrict__ qpe_w,
                          const float* __restrict__ qpe_b) {
    __shared__ float tile[32][33];
    int b = blockIdx.z;
    int c0 = blockIdx.y * 32, n0 = blockIdx.x * 32;
    int tx = threadIdx.x, ty = threadIdx.y;
#pragma unroll
    for (int j = 0; j < 4; j++)
        tile[ty + 8*j][tx] = query[(b*CDIM + c0 + ty + 8*j)*NQD + n0 + tx];
    __syncthreads();
#pragma unroll
    for (int j = 0; j < 4; j++) {
        int nq = n0 + ty + 8*j, c = c0 + tx;
        int bq = b*NQD + nq;
        float qt = tile[tx][ty + 8*j];
        const float* qp = query_pos + (size_t)bq*6;
        float pe = qpe_b[c];
#pragma unroll
        for (int jj = 0; jj < 6; jj++) pe += qp[jj] * qpe_w[c*6 + jj];
        g_qtok[bq*CDIM + c] = qt;
        g_qin [bq*CDIM + c] = __float2bfloat16_rn(qt + pe);
    }
}

// ---------------- transpose v_w (256x256) ----------------
__global__ void k_transpose_vw(const float* __restrict__ v_w) {
    __shared__ float tile[32][33];
    int n0 = blockIdx.y * 32, c0 = blockIdx.x * 32;
    int tx = threadIdx.x, ty = threadIdx.y;
#pragma unroll
    for (int j = 0; j < 4; j++)
        tile[ty + 8*j][tx] = v_w[(n0 + ty + 8*j)*CDIM + c0 + tx];
    __syncthreads();
#pragma unroll
    for (int j = 0; j < 4; j++)
        g_vwT[(c0 + ty + 8*j)*CDIM + n0 + tx] = tile[tx][ty + 8*j];
}

// ---------------- box query: first 16 inside-box keys, in index order ----------------
__global__ void k_boxquery(const float* __restrict__ key_pos,
                           const float* __restrict__ query_pos) {
    __shared__ float kp[NKD*3];   // exactly 48KB
    int b = blockIdx.y;
    int t = threadIdx.x;
#pragma unroll
    for (int i = 0; i < 48; i++)
        kp[t + 256*i] = key_pos[(size_t)b*NKD*3 + t + 256*i];
    __syncthreads();

    int w = t >> 5, lane = t & 31;
    int q = blockIdx.x * 8 + w;
    int bq = b*NQD + q;
    const float* qp = query_pos + (size_t)bq*6;
    float cx = qp[0], cy = qp[1], cz = qp[2];
    float hx = 0.5f*qp[3], hy = 0.5f*qp[4], hz = 0.5f*qp[5];

    int count = 0;
    for (int base = 0; base < NKD && count < SKEYS; base += 32) {
        int k = base + lane;
        float dx = fabsf(kp[k*3+0]-cx);
        float dy = fabsf(kp[k*3+1]-cy);
        float dz = fabsf(kp[k*3+2]-cz);
        bool inside = (dx <= hx) && (dy <= hy) && (dz <= hz);
        unsigned bal = __ballot_sync(0xffffffffu, inside);
        int nb = __popc(bal);
        if (inside) {
            int rank = __popc(bal & ((1u << lane) - 1u));
            if (count + rank < SKEYS) g_sidx[bq*SKEYS + count + rank] = k;
        }
        count += nb;
        if (count > SKEYS) count = SKEYS;
    }
    if (lane < SKEYS && lane >= count)
        g_sidx[bq*SKEYS + lane] = (lane == 0) ? 0 : -1;
}

// ---------------- fused gather + attention (8 queries, 512 threads) ----------------
__global__ void __launch_bounds__(512)
k_attn(const float* __restrict__ key_pos,
       const float* __restrict__ query_pos,
       const float* __restrict__ kpe_w,
       const float* __restrict__ kpe_b,
       const float* __restrict__ k_w,
       const float* __restrict__ v_b) {
    extern __shared__ float sm[];
    float* kv = sm;                     // [8][16][CP]
    float* mb = kv + 8*16*CP;           // [8][8][CP]   (m, later wkv)
    float* qs = mb + 8*8*CP;            // [8][256]
    float* at = qs + 8*256;             // [8][8][16]   (scores, then attn)
    float* pes = at + 8*128;            // [4][256]  kpe SoA: w0,w1,w2,b
    float* qc = pes + 4*256;            // [8][4]
    int*  sid = (int*)(qc + 32);        // [8][16]

    int t = threadIdx.x, lane = t & 31, w = t >> 5;   // 16 warps
    int bq0 = blockIdx.x * 8;
    int b = bq0 >> 10;   // NQ=1024

    if (t < 128) sid[t] = g_sidx[bq0*SKEYS + t];
    if (t < 24) { int g = t/3, j = t%3; qc[g*4 + j] = query_pos[(size_t)(bq0+g)*6 + j]; }
    if (t < 256) {   // kpe SoA staging
        pes[0*256 + t] = kpe_w[t*3 + 0];
        pes[1*256 + t] = kpe_w[t*3 + 1];
        pes[2*256 + t] = kpe_w[t*3 + 2];
        pes[3*256 + t] = kpe_b[t];
    }
#pragma unroll
    for (int i = 0; i < 4; i++)
        qs[t + 512*i] = g_qh[(size_t)bq0*CDIM + t + 512*i]
                      + g_qh[(size_t)BQTOT*CDIM + (size_t)bq0*CDIM + t + 512*i];
    __syncthreads();

    // phase 1: gather kv = keyT[idx] + kpe(gxyz)   (warp = (g, s-half))
    {
        int g = w >> 1, sh = w & 1;
        float qcx = qc[g*4+0], qcy = qc[g*4+1], qcz = qc[g*4+2];
        for (int si = 0; si < 8; si++) {
            int s = sh*8 + si;
            int v = sid[g*16 + s];
            int kidx = v < 0 ? 0 : v;
            int base = b*NKD + kidx;
            float gx = key_pos[base*3+0] - qcx;
            float gy = key_pos[base*3+1] - qcy;
            float gz = key_pos[base*3+2] - qcz;
            const float4* krow4 = (const float4*)(g_keyT + (size_t)base*CDIM);
            float* kvrow = kv + (g*16 + s)*CP;
#pragma unroll
            for (int i = 0; i < 2; i++) {
                int c4 = lane + 32*i;
                float4 kr = krow4[c4];
                float4 w0 = *(const float4*)&pes[0*256 + 4*c4];
                float4 w1 = *(const float4*)&pes[1*256 + 4*c4];
                float4 w2 = *(const float4*)&pes[2*256 + 4*c4];
                float4 bb = *(const float4*)&pes[3*256 + 4*c4];
                float4 r;
                r.x = kr.x + bb.x + gx*w0.x + gy*w1.x + gz*w2.x;
                r.y = kr.y + bb.y + gx*w0.y + gy*w1.y + gz*w2.y;
                r.z = kr.z + bb.z + gx*w0.z + gy*w1.z + gz*w2.z;
                r.w = kr.w + bb.w + gx*w0.w + gy*w1.w + gz*w2.w;
                *(float4*)&kvrow[4*c4] = r;
            }
        }
    }
    __syncthreads();

    // phase 2: m[g][h][c] = sum_d k_w[h*32+d, c] * qh[g][h*32+d]   (warp = (h, c-half))
    {
        int h = w >> 1, ch = w & 1;
        float acc[4][8];   // [cc][g]
#pragma unroll
        for (int i = 0; i < 4; i++)
#pragma unroll
            for (int j = 0; j < 8; j++) acc[i][j] = 0.f;
        for (int d = 0; d < 32; d++) {
            float qv[8];
#pragma unroll
            for (int g = 0; g < 8; g++) qv[g] = qs[g*256 + h*32 + d];
            const float* wr = k_w + (size_t)(h*32 + d)*CDIM;
#pragma unroll
            for (int cc = 0; cc < 4; cc++) {
                float wv = __ldg(wr + lane + 32*(ch*4 + cc));
#pragma unroll
                for (int g = 0; g < 8; g++) acc[cc][g] += wv * qv[g];
            }
        }
#pragma unroll
        for (int cc = 0; cc < 4; cc++)
#pragma unroll
            for (int g = 0; g < 8; g++)
                mb[(g*8 + h)*CP + lane + 32*(ch*4 + cc)] = acc[cc][g];
    }
    __syncthreads();

    // phase 3: scores[g][h][s] = m[g][h] . kv[g][s]  (warp = (g, h-half); lane = (h4, s0))
    {
        int g = w >> 1, hh = w & 1;
        int h = hh*4 + (lane >> 3), s0 = lane & 7;
        float sc[2] = {0.f, 0.f};
        const float4* m4 = (const float4*)(mb + (g*8 + h)*CP);
        const float4* kv0 = (const float4*)(kv + (g*16 + s0)*CP);
        const float4* kv1 = (const float4*)(kv + (g*16 + s0 + 8)*CP);
        for (int c4 = 0; c4 < 64; c4++) {
            float4 mv = m4[c4];
            float4 k0 = kv0[c4], k1 = kv1[c4];
            sc[0] += mv.x*k0.x + mv.y*k0.y + mv.z*k0.z + mv.w*k0.w;
            sc[1] += mv.x*k1.x + mv.y*k1.y + mv.z*k1.z + mv.w*k1.w;
        }
        at[(g*8 + h)*16 + s0]     = sc[0];
        at[(g*8 + h)*16 + s0 + 8] = sc[1];
    }
    __syncthreads();

    // phase 4: masked softmax (one thread per (g,h))
    if (t < 64) {
        int g = t >> 3, h = t & 7;
        float* row = at + (g*8 + h)*16;
        const int* sg = sid + g*16;
        const float scl = 0.17677669529663687f;   // 1/sqrt(32)
        float sv[16];
        float mx = -3.0e38f;
#pragma unroll
        for (int s = 0; s < 16; s++) {
            sv[s] = (sg[s] < 0) ? -3.0e38f : row[s]*scl;
            mx = fmaxf(mx, sv[s]);
        }
        float sum = 0.f;
#pragma unroll
        for (int s = 0; s < 16; s++) {
            float e = (sg[s] < 0) ? 0.f : expf(sv[s] - mx);
            sv[s] = e; sum += e;
        }
        float inv = 1.f/sum;
#pragma unroll
        for (int s = 0; s < 16; s++) row[s] = sv[s]*inv;
    }
    __syncthreads();

    // phase 5: wkv[g][h][c] = sum_s attn[g][h][s]*kv[g][s][c]  (warp = (g, c-half), v4)
    {
        int g = w >> 1, ch = w & 1;
        int cb = ch*128 + lane*4;
        float acc[8][4];   // [h][cc]
#pragma unroll
        for (int i = 0; i < 8; i++)
#pragma unroll
            for (int j = 0; j < 4; j++) acc[i][j] = 0.f;
        for (int s = 0; s < 16; s++) {
            float av[8];
#pragma unroll
            for (int h = 0; h < 8; h++) av[h] = at[(g*8 + h)*16 + s];
            float4 kk = *(const float4*)(kv + (g*16 + s)*CP + cb);
#pragma unroll
            for (int h = 0; h < 8; h++) {
                acc[h][0] += av[h]*kk.x; acc[h][1] += av[h]*kk.y;
                acc[h][2] += av[h]*kk.z; acc[h][3] += av[h]*kk.w;
            }
        }
#pragma unroll
        for (int h = 0; h < 8; h++)
            *(float4*)(mb + (g*8 + h)*CP + cb) =
                make_float4(acc[h][0], acc[h][1], acc[h][2], acc[h][3]);
    }
    __syncthreads();

    // phase 6: ao[g][h*32+d] = sum_c wkv[g][h][c]*v_wT[c][h*32+d] + v_b  (warp=(h,g-half))
    {
        int h = w >> 1, gh = w & 1, d = lane;
        float acc[4];
#pragma unroll
        for (int g = 0; g < 4; g++) acc[g] = 0.f;
        const float* wcol = g_vwT + h*32 + d;
        for (int c4 = 0; c4 < 64; c4++) {
            float w0 = __ldg(wcol + (size_t)(4*c4+0)*CDIM);
            float w1 = __ldg(wcol + (size_t)(4*c4+1)*CDIM);
            float w2 = __ldg(wcol + (size_t)(4*c4+2)*CDIM);
            float w3 = __ldg(wcol + (size_t)(4*c4+3)*CDIM);
#pragma unroll
            for (int g = 0; g < 4; g++) {
                float4 mv = *(const float4*)&mb[((gh*4 + g)*8 + h)*CP + 4*c4];
                acc[g] += mv.x*w0 + mv.y*w1 + mv.z*w2 + mv.w*w3;
            }
        }
        float vb = v_b[h*32 + d];
#pragma unroll
        for (int g = 0; g < 4; g++)
            g_ao[(size_t)(bq0 + gh*4 + g)*CDIM + h*32 + d] = __float2bfloat16_rn(acc[g] + vb);
    }
}

// ---------------- layernorm of (ra + rb + rc), writes full f32 + bf16 ----------
__global__ void k_ln(const float* __restrict__ ra, const float* __restrict__ rb,
                     const float* __restrict__ rc,
                     const float* __restrict__ gamma, const float* __restrict__ beta,
                     float* __restrict__ out, bf16* __restrict__ outr) {
    int bq = blockIdx.x * 8 + (threadIdx.x >> 5);
    int lane = threadIdx.x & 31;
    float v[8];
    float s = 0.f;
#pragma unroll
    for (int i = 0; i < 8; i++) {
        int c = lane + 32*i;
        v[i] = ra[(size_t)bq*CDIM + c] + rb[(size_t)bq*CDIM + c] + rc[(size_t)bq*CDIM + c];
        s += v[i];
    }
#pragma unroll
    for (int o = 16; o; o >>= 1) s += __shfl_xor_sync(0xffffffffu, s, o);
    float mean = s * (1.f/256.f);
    float vs = 0.f;
#pragma unroll
    for (int i = 0; i < 8; i++) { float d = v[i]-mean; vs += d*d; }
#pragma unroll
    for (int o = 16; o; o >>= 1) vs += __shfl_xor_sync(0xffffffffu, vs, o);
    float rstd = rsqrtf(vs*(1.f/256.f) + 1e-5f);
#pragma unroll
    for (int i = 0; i < 8; i++) {
        int c = lane + 32*i;
        float r = (v[i]-mean)*rstd*gamma[c] + beta[c];
        out [(size_t)bq*CDIM + c] = r;
        outr[(size_t)bq*CDIM + c] = __float2bfloat16_rn(r);
    }
}

// ---------------- final LN2 + coalesced transpose to (B, C, NQ): 32 bq/block ------
__global__ void __launch_bounds__(256)
k_ln_out(const float* __restrict__ ra, const float* __restrict__ rb,
         const float* __restrict__ rc,
         const float* __restrict__ gamma, const float* __restrict__ beta,
         float* __restrict__ out) {
    __shared__ float tile[256][33];
    int t = threadIdx.x, lane = t & 31, w = t >> 5;
    int bq0 = blockIdx.x * 32;
    int b = bq0 >> 10, nq0 = bq0 & 1023;

    // LN phase: warp w handles bq_local = w*4 .. w*4+3
    for (int rep = 0; rep < 4; rep++) {
        int bqL = w*4 + rep;
        size_t base = (size_t)(bq0 + bqL)*CDIM;
        float v[8];
        float s = 0.f;
#pragma unroll
        for (int i = 0; i < 8; i++) {
            int c = lane + 32*i;
            v[i] = ra[base + c] + rb[base + c] + rc[base + c];
            s += v[i];
        }
#pragma unroll
        for (int o = 16; o; o >>= 1) s += __shfl_xor_sync(0xffffffffu, s, o);
        float mean = s * (1.f/256.f);
        float vs = 0.f;
#pragma unroll
        for (int i = 0; i < 8; i++) { float d = v[i]-mean; vs += d*d; }
#pragma unroll
        for (int o = 16; o; o >>= 1) vs += __shfl_xor_sync(0xffffffffu, vs, o);
        float rstd = rsqrtf(vs*(1.f/256.f) + 1e-5f);
#pragma unroll
        for (int i = 0; i < 8; i++) {
            int c = lane + 32*i;
            tile[c][bqL] = (v[i]-mean)*rstd*gamma[c] + beta[c];
        }
    }
    __syncthreads();

    // write phase: warp w writes channels [w*32, w*32+32), 128B coalesced over nq
#pragma unroll
    for (int i = 0; i < 32; i++) {
        int c = w*32 + i;
        out[((size_t)b*CDIM + c)*NQD + nq0 + lane] = tile[c][lane];
    }
}

// ---------------- launch ----------------
extern "C" void kernel_launch(void* const* d_in, const int* in_sizes, int n_in,
                              void* d_out, int out_size) {
    const float* query     = (const float*)d_in[0];
    const float* key       = (const float*)d_in[1];
    const float* query_pos = (const float*)d_in[2];
    const float* key_pos   = (const float*)d_in[3];
    const float* q_w   = (const float*)d_in[4];
    const float* q_b   = (const float*)d_in[5];
    const float* k_w   = (const float*)d_in[6];
    // d_in[7] = k_b: cancels in softmax (uniform shift per (bq,h))
    const float* v_w   = (const float*)d_in[8];
    const float* v_b   = (const float*)d_in[9];
    const float* o_w   = (const float*)d_in[10];
    const float* o_b   = (const float*)d_in[11];
    const float* lin1_w = (const float*)d_in[12];
    const float* lin1_b = (const float*)d_in[13];
    const float* lin2_w = (const float*)d_in[14];
    const float* lin2_b = (const float*)d_in[15];
    const float* n1_g = (const float*)d_in[16];
    const float* n1_b = (const float*)d_in[17];
    const float* n2_g = (const float*)d_in[18];
    const float* n2_b = (const float*)d_in[19];
    const float* qpe_w = (const float*)d_in[20];
    const float* qpe_b = (const float*)d_in[21];
    const float* kpe_w = (const float*)d_in[22];
    const float* kpe_b = (const float*)d_in[23];

    void *p_qin, *p_qh, *p_ao, *p_res1, *p_qtok, *p_x, *p_xr, *p_ff, *p_y;
    void *p_qwr, *p_owr, *p_l1r, *p_l2r;
    cudaGetSymbolAddress(&p_qin,  g_qin);
    cudaGetSymbolAddress(&p_qh,   g_qh);
    cudaGetSymbolAddress(&p_ao,   g_ao);
    cudaGetSymbolAddress(&p_res1, g_res1);
    cudaGetSymbolAddress(&p_qtok, g_qtok);
    cudaGetSymbolAddress(&p_x,    g_x);
    cudaGetSymbolAddress(&p_xr,   g_xr);
    cudaGetSymbolAddress(&p_ff,   g_ff);
    cudaGetSymbolAddress(&p_y,    g_y);
    cudaGetSymbolAddress(&p_qwr,  g_qwr);
    cudaGetSymbolAddress(&p_owr,  g_owr);
    cudaGetSymbolAddress(&p_l1r,  g_l1r);
    cudaGetSymbolAddress(&p_l2r,  g_l2r);

    const size_t SLICE = (size_t)BQTOT * CDIM;

    const int attn_smem = (8*16*CP + 8*8*CP + 8*256 + 8*128 + 4*256 + 32)*4 + 128*4;
    cudaFuncSetAttribute(k_attn, cudaFuncAttributeMaxDynamicSharedMemorySize, attn_smem);

    const int gemm_smem = 2 * STAGE_H * 2;    // 73,728 bytes (2 stages, bf16)
    cudaFuncSetAttribute(k_gemm_bf<0,0>, cudaFuncAttributeMaxDynamicSharedMemorySize, gemm_smem);
    cudaFuncSetAttribute(k_gemm_bf<1,1>, cudaFuncAttributeMaxDynamicSharedMemorySize, gemm_smem);

    // preprocessing
    k_transpose_key<<<dim3(NKD/32, CDIM/32, BATCH), dim3(32,8)>>>(key);
    k_build_q<<<dim3(NQD/32, CDIM/32, BATCH), dim3(32,8)>>>(query, query_pos, qpe_w, qpe_b);
    k_transpose_vw<<<dim3(CDIM/32, CDIM/32), dim3(32,8)>>>(v_w);
    k_boxquery<<<dim3(NQD/8, BATCH), 256>>>(key_pos, query_pos);

    // bf16 weight copies (round-to-nearest)
    k_round<<<CDIM*CDIM/256, 256>>>(q_w,    (bf16*)p_qwr, CDIM*CDIM);
    k_round<<<CDIM*CDIM/256, 256>>>(o_w,    (bf16*)p_owr, CDIM*CDIM);
    k_round<<<FFDIM*CDIM/256, 256>>>(lin1_w, (bf16*)p_l1r, FFDIM*CDIM);
    k_round<<<CDIM*FFDIM/256, 256>>>(lin2_w, (bf16*)p_l2r, CDIM*FFDIM);

    // q projection: qh = qin @ q_w^T + q_b   (split-K x2, 256 CTAs)
    k_gemm_bf<0,0><<<dim3(CDIM/128, BQTOT/128, 2), 256, gemm_smem>>>(
        (const bf16*)p_qin, (const bf16*)p_qwr, q_b, p_qh,
        CDIM, CDIM, 128, SLICE);

    // fused gather + attention -> ao (sums the two qh slices internally)
    k_attn<<<BQTOT/8, 512, attn_smem>>>(key_pos, query_pos, kpe_w, kpe_b, k_w, v_b);

    // o projection (split-K x2)
    k_gemm_bf<0,0><<<dim3(CDIM/128, BQTOT/128, 2), 256, gemm_smem>>>(
        (const bf16*)p_ao, (const bf16*)p_owr, o_b, p_res1,
        CDIM, CDIM, 128, SLICE);

    // LN1(qtok + res1a + res1b) -> x (f32) + xr (bf16)
    k_ln<<<BQTOT/8, 256>>>((const float*)p_qtok, (const float*)p_res1,
                           (const float*)p_res1 + SLICE, n1_g, n1_b,
                           (float*)p_x, (bf16*)p_xr);

    // FFN
    k_gemm_bf<1,1><<<dim3(FFDIM/128, BQTOT/128, 1), 256, gemm_smem>>>(
        (const bf16*)p_xr, (const bf16*)p_l1r, lin1_b, p_ff,
        FFDIM, CDIM, 256, 0);
    k_gemm_bf<0,0><<<dim3(CDIM/128, BQTOT/128, 2), 256, gemm_smem>>>(
        (const bf16*)p_ff, (const bf16*)p_l2r, lin2_b, p_y,
        CDIM, FFDIM, 1024, SLICE);

    // LN2(x + y0 + y1) + coalesced transpose out
    k_ln_out<<<BQTOT/32, 256>>>((const float*)p_x, (const float*)p_y,
                                (const float*)p_y + SLICE, n2_g, n2_b, (float*)d_out);
}

// round 9
// speedup vs baseline: 4.1499x; 1.0284x over previous
#include <cuda_runtime.h>
#include <cuda_bf16.h>
#include <math.h>
#include <stdint.h>

#define BATCH 8
#define CDIM  256
#define NQD   1024
#define NKD   4096
#define SKEYS 16
#define HEADS 8
#define FFDIM 2048
#define DHD   32
#define BQTOT (BATCH*NQD)
#define CP    260   // padded smem stride (attn kernel; 16B-aligned rows)

typedef __nv_bfloat16 bf16;

// ---------------- scratch (device globals; no allocation allowed) ----------------
__device__ float g_keyT[BATCH*NKD*CDIM];     // key transposed (B, NK, C)
__device__ float g_qtok[BQTOT*CDIM];         // transposed query tokens (residual)
__device__ bf16  g_qin [BQTOT*CDIM];         // qtok + qpe (bf16, GEMM A)
__device__ float g_qh  [2*BQTOT*CDIM];       // q projection (2 split-K slices)
__device__ int   g_sidx[BQTOT*SKEYS];        // gathered key indices (-1 = masked)
__device__ float g_vwT [CDIM*CDIM];          // v_w transposed
__device__ bf16  g_ao  [BQTOT*CDIM];         // attention output (bf16, GEMM A)
__device__ float g_res1[2*BQTOT*CDIM];       // o-proj output (2 slices)
__device__ float g_x   [BQTOT*CDIM];         // after LN1 (residual)
__device__ bf16  g_xr  [BQTOT*CDIM];         // after LN1 (bf16, GEMM A)
__device__ bf16  g_ff  [BQTOT*FFDIM];        // FFN hidden (bf16, GEMM A)
__device__ float g_y   [2*BQTOT*CDIM];       // FFN out (2 slices)
// bf16 weight copies
__device__ bf16  g_qwr [CDIM*CDIM];
__device__ bf16  g_owr [CDIM*CDIM];
__device__ bf16  g_l1r [FFDIM*CDIM];
__device__ bf16  g_l2r [CDIM*FFDIM];

// ---------------- small PTX helpers ----------------
__device__ __forceinline__ uint32_t smem_u32(const void* p) {
    uint32_t a;
    asm("{ .reg .u64 t; cvta.to.shared.u64 t, %1; cvt.u32.u64 %0, t; }" : "=r"(a) : "l"(p));
    return a;
}
__device__ __forceinline__ void cp16(uint32_t s, const void* g) {
    asm volatile("cp.async.cg.shared.global [%0], [%1], 16;" :: "r"(s), "l"(g));
}
#define CP_COMMIT() asm volatile("cp.async.commit_group;" ::: "memory")
#define CP_WAIT1()  asm volatile("cp.async.wait_group 1;" ::: "memory")

#define LDSM4(R0,R1,R2,R3, ADDR) \
    asm volatile("ldmatrix.sync.aligned.m8n8.x4.shared.b16 {%0,%1,%2,%3}, [%4];" \
        : "=r"(R0), "=r"(R1), "=r"(R2), "=r"(R3) : "r"(ADDR))

__device__ __forceinline__ void mma_bf16(float* d,
                                         uint32_t a0, uint32_t a1, uint32_t a2, uint32_t a3,
                                         uint32_t b0, uint32_t b1) {
    asm volatile(
        "mma.sync.aligned.m16n8k16.row.col.f32.bf16.bf16.f32 "
        "{%0,%1,%2,%3}, {%4,%5,%6,%7}, {%8,%9}, {%0,%1,%2,%3};"
        : "+f"(d[0]), "+f"(d[1]), "+f"(d[2]), "+f"(d[3])
        : "r"(a0), "r"(a1), "r"(a2), "r"(a3), "r"(b0), "r"(b1));
}

// ---------------- bf16 mma.sync GEMM: C = A(M,lda) @ W(N,lda)^T (+ bias on z=0) ----
#define PADB 72                  // bf16 elems per smem row (144B, conflict-free)
#define STAGE_H (2*128*PADB)     // bf16 elems per stage (A + B)

template<int RELU, int OUTBF>
__global__ void __launch_bounds__(256)
k_gemm_bf(const bf16* __restrict__ A, const bf16* __restrict__ W,
          const float* __restrict__ bias, void* __restrict__ Cout,
          int N, int lda, int KS, size_t outStride) {
    extern __shared__ bf16 smh[];
    int t = threadIdx.x, lane = t & 31, wid = t >> 5;
    int wm = wid >> 1, wn = wid & 1;          // warp tile origin (wm*32, wn*64)
    int bm = blockIdx.y * 128, bn = blockIdx.x * 128;
    int kb = blockIdx.z * KS;
    const int NC = KS >> 6;
    int qr = lane >> 2, qc = lane & 3;        // quad row / quad col (epilogue)

    // ldmatrix per-lane addressing
    int lrowA = (lane & 7) + ((lane >> 3) & 1) * 8;   // 0..15
    int lsegA = (lane >> 4) * 8;                      // 0 or 8 (bf16 elems)
    int lrowB = ((lane >> 4) * 8) + (lane & 7);       // 0..15
    int lsegB = ((lane >> 3) & 1) * 8;
    uint32_t smbase = smem_u32(smh);
    uint32_t aoff = (uint32_t)(((wm*32 + lrowA)*PADB + lsegA) * 2);
    uint32_t boff = (uint32_t)((128*PADB + (wn*64 + lrowB)*PADB + lsegB) * 2);

    float acc[2][8][4];
#pragma unroll
    for (int mi = 0; mi < 2; mi++)
#pragma unroll
        for (int ni = 0; ni < 8; ni++)
#pragma unroll
            for (int j = 0; j < 4; j++) acc[mi][ni][j] = 0.f;

    // stage 0 prologue: chunk 0 (64 bf16 per row = 8 segs of 8)
    {
        bf16* As = smh; bf16* Bs = smh + 128*PADB;
        for (int u = t; u < 1024; u += 256) {
            int row = u >> 3, seg = u & 7;
            cp16(smem_u32(As + row*PADB + seg*8), A + (size_t)(bm + row)*lda + kb + seg*8);
            cp16(smem_u32(Bs + row*PADB + seg*8), W + (size_t)(bn + row)*lda + kb + seg*8);
        }
    }
    CP_COMMIT();

    for (int c = 0; c < NC; c++) {
        __syncthreads();                       // stage (c+1)&1 free (compute c-1 done)
        if (c + 1 < NC) {
            bf16* As = smh + ((c+1)&1)*STAGE_H;
            bf16* Bs = As + 128*PADB;
            int k0 = kb + (c+1)*64;
            for (int u = t; u < 1024; u += 256) {
                int row = u >> 3, seg = u & 7;
                cp16(smem_u32(As + row*PADB + seg*8), A + (size_t)(bm + row)*lda + k0 + seg*8);
                cp16(smem_u32(Bs + row*PADB + seg*8), W + (size_t)(bn + row)*lda + k0 + seg*8);
            }
        }
        CP_COMMIT();
        CP_WAIT1();                            // stage c copies done (this thread)
        __syncthreads();                       // all threads' stage-c copies visible

        uint32_t sb = smbase + ((c & 1) ? (uint32_t)(STAGE_H*2) : 0u);
        uint32_t aB = sb + aoff, bB = sb + boff;
#pragma unroll
        for (int kk = 0; kk < 4; kk++) {
            uint32_t a0[4], a1[4], bf[8][2];
            LDSM4(a0[0], a0[1], a0[2], a0[3], aB + kk*32);
            LDSM4(a1[0], a1[1], a1[2], a1[3], aB + 16*PADB*2 + kk*32);
#pragma unroll
            for (int j = 0; j < 4; j++)
                LDSM4(bf[2*j][0], bf[2*j][1], bf[2*j+1][0], bf[2*j+1][1],
                      bB + j*16*PADB*2 + kk*32);
#pragma unroll
            for (int ni = 0; ni < 8; ni++) {
                mma_bf16(acc[0][ni], a0[0], a0[1], a0[2], a0[3], bf[ni][0], bf[ni][1]);
                mma_bf16(acc[1][ni], a1[0], a1[1], a1[2], a1[3], bf[ni][0], bf[ni][1]);
            }
        }
    }

    // epilogue: direct stores; bias only on z=0
    bool addb = (blockIdx.z == 0);
#pragma unroll
    for (int mi = 0; mi < 2; mi++) {
        int r0 = bm + wm*32 + mi*16 + qr;
#pragma unroll
        for (int ni = 0; ni < 8; ni++) {
            int cn = bn + wn*64 + ni*8 + qc*2;
            float b0 = addb ? bias[cn] : 0.f, b1 = addb ? bias[cn+1] : 0.f;
            float v0 = acc[mi][ni][0] + b0, v1 = acc[mi][ni][1] + b1;
            float v2 = acc[mi][ni][2] + b0, v3 = acc[mi][ni][3] + b1;
            if (RELU) { v0=fmaxf(v0,0.f); v1=fmaxf(v1,0.f); v2=fmaxf(v2,0.f); v3=fmaxf(v3,0.f); }
            if (OUTBF) {
                bf16* C = (bf16*)Cout;
                *(__nv_bfloat162*)&C[(size_t)r0*N + cn]     = __floats2bfloat162_rn(v0, v1);
                *(__nv_bfloat162*)&C[(size_t)(r0+8)*N + cn] = __floats2bfloat162_rn(v2, v3);
            } else {
                float* C = (float*)Cout + (size_t)blockIdx.z * outStride;
                *(float2*)&C[(size_t)r0*N + cn]     = make_float2(v0, v1);
                *(float2*)&C[(size_t)(r0+8)*N + cn] = make_float2(v2, v3);
            }
        }
    }
}

// ---------------- elementwise f32 -> bf16 ----------------
__global__ void k_round(const float* __restrict__ in, bf16* __restrict__ out, int n) {
    int i = blockIdx.x * 256 + threadIdx.x;
    if (i < n) out[i] = __float2bfloat16_rn(in[i]);
}

// ---------------- transpose key (B,C,NK) -> (B,NK,C) ----------------
__global__ void k_transpose_key(const float* __restrict__ key) {
    __shared__ float tile[32][33];
    int b = blockIdx.z;
    int c0 = blockIdx.y * 32, n0 = blockIdx.x * 32;
    int tx = threadIdx.x, ty = threadIdx.y;
#pragma unroll
    for (int j = 0; j < 4; j++)
        tile[ty + 8*j][tx] = key[(b*CDIM + c0 + ty + 8*j)*NKD + n0 + tx];
    __syncthreads();
#pragma unroll
    for (int j = 0; j < 4; j++)
        g_keyT[(b*NKD + n0 + ty + 8*j)*CDIM + c0 + tx] = tile[tx][ty + 8*j];
}

// ---------------- build qtok + qin (query transpose + qpe) ----------------
__global__ void k_build_q(const float* __restrict__ query,
                          const float* __restrict__ query_pos,
                          const float* __restrict__ qpe_w,
                          const float* __restrict__ qpe_b) {
    __shared__ float tile[32][33];
    int b = blockIdx.z;
    int c0 = blockIdx.y * 32, n0 = blockIdx.x * 32;
    int tx = threadIdx.x, ty = threadIdx.y;
#pragma unroll
    for (int j = 0; j < 4; j++)
        tile[ty + 8*j][tx] = query[(b*CDIM + c0 + ty + 8*j)*NQD + n0 + tx];
    __syncthreads();
#pragma unroll
    for (int j = 0; j < 4; j++) {
        int nq = n0 + ty + 8*j, c = c0 + tx;
        int bq = b*NQD + nq;
        float qt = tile[tx][ty + 8*j];
        const float* qp = query_pos + (size_t)bq*6;
        float pe = qpe_b[c];
#pragma unroll
        for (int jj = 0; jj < 6; jj++) pe += qp[jj] * qpe_w[c*6 + jj];
        g_qtok[bq*CDIM + c] = qt;
        g_qin [bq*CDIM + c] = __float2bfloat16_rn(qt + pe);
    }
}

// ---------------- transpose v_w (256x256) ----------------
__global__ void k_transpose_vw(const float* __restrict__ v_w) {
    __shared__ float tile[32][33];
    int n0 = blockIdx.y * 32, c0 = blockIdx.x * 32;
    int tx = threadIdx.x, ty = threadIdx.y;
#pragma unroll
    for (int j = 0; j < 4; j++)
        tile[ty + 8*j][tx] = v_w[(n0 + ty + 8*j)*CDIM + c0 + tx];
    __syncthreads();
#pragma unroll
    for (int j = 0; j < 4; j++)
        g_vwT[(c0 + ty + 8*j)*CDIM + n0 + tx] = tile[tx][ty + 8*j];
}

// ---------------- box query: 32 queries/block, first 16 inside keys ---------------
__global__ void __launch_bounds__(1024)
k_boxquery(const float* __restrict__ key_pos,
           const float* __restrict__ query_pos) {
    __shared__ float kp[NKD*3];   // exactly 48KB
    int b = blockIdx.y;
    int t = threadIdx.x;
#pragma unroll
    for (int i = 0; i < 12; i++)
        kp[t + 1024*i] = key_pos[(size_t)b*NKD*3 + t + 1024*i];
    __syncthreads();

    int w = t >> 5, lane = t & 31;
    int q = blockIdx.x * 32 + w;
    int bq = b*NQD + q;
    const float* qp = query_pos + (size_t)bq*6;
    float cx = qp[0], cy = qp[1], cz = qp[2];
    float hx = 0.5f*qp[3], hy = 0.5f*qp[4], hz = 0.5f*qp[5];

    int count = 0;
    for (int base = 0; base < NKD && count < SKEYS; base += 32) {
        int k = base + lane;
        float dx = fabsf(kp[k*3+0]-cx);
        float dy = fabsf(kp[k*3+1]-cy);
        float dz = fabsf(kp[k*3+2]-cz);
        bool inside = (dx <= hx) && (dy <= hy) && (dz <= hz);
        unsigned bal = __ballot_sync(0xffffffffu, inside);
        int nb = __popc(bal);
        if (inside) {
            int rank = __popc(bal & ((1u << lane) - 1u));
            if (count + rank < SKEYS) g_sidx[bq*SKEYS + count + rank] = k;
        }
        count += nb;
        if (count > SKEYS) count = SKEYS;
    }
    if (lane < SKEYS && lane >= count)
        g_sidx[bq*SKEYS + lane] = (lane == 0) ? 0 : -1;
}

// ---------------- fused gather + attention (8 queries, 512 threads) ----------------
__global__ void __launch_bounds__(512)
k_attn(const float* __restrict__ key_pos,
       const float* __restrict__ query_pos,
       const float* __restrict__ kpe_w,
       const float* __restrict__ kpe_b,
       const float* __restrict__ k_w,
       const float* __restrict__ v_b) {
    extern __shared__ float sm[];
    float* kv = sm;                     // [8][16][CP]
    float* mb = kv + 8*16*CP;           // [8][8][CP]   (m, later wkv)
    float* qs = mb + 8*8*CP;            // [8][256]
    float* at = qs + 8*256;             // [8][8][16]   (scores, then attn)
    float* pes = at + 8*128;            // [4][256]  kpe SoA: w0,w1,w2,b
    float* qc = pes + 4*256;            // [8][4]
    int*  sid = (int*)(qc + 32);        // [8][16]

    int t = threadIdx.x, lane = t & 31, w = t >> 5;   // 16 warps
    int bq0 = blockIdx.x * 8;
    int b = bq0 >> 10;   // NQ=1024

    if (t < 128) sid[t] = g_sidx[bq0*SKEYS + t];
    if (t < 24) { int g = t/3, j = t%3; qc[g*4 + j] = query_pos[(size_t)(bq0+g)*6 + j]; }
    if (t < 256) {   // kpe SoA staging
        pes[0*256 + t] = kpe_w[t*3 + 0];
        pes[1*256 + t] = kpe_w[t*3 + 1];
        pes[2*256 + t] = kpe_w[t*3 + 2];
        pes[3*256 + t] = kpe_b[t];
    }
#pragma unroll
    for (int i = 0; i < 4; i++)
        qs[t + 512*i] = g_qh[(size_t)bq0*CDIM + t + 512*i]
                      + g_qh[(size_t)BQTOT*CDIM + (size_t)bq0*CDIM + t + 512*i];
    __syncthreads();

    // phase 1: gather kv = keyT[idx] + kpe(gxyz)   (warp = (g, s-half))
    {
        int g = w >> 1, sh = w & 1;
        float qcx = qc[g*4+0], qcy = qc[g*4+1], qcz = qc[g*4+2];
        for (int si = 0; si < 8; si++) {
            int s = sh*8 + si;
            int v = sid[g*16 + s];
            int kidx = v < 0 ? 0 : v;
            int base = b*NKD + kidx;
            float gx = key_pos[base*3+0] - qcx;
            float gy = key_pos[base*3+1] - qcy;
            float gz = key_pos[base*3+2] - qcz;
            const float4* krow4 = (const float4*)(g_keyT + (size_t)base*CDIM);
            float* kvrow = kv + (g*16 + s)*CP;
#pragma unroll
            for (int i = 0; i < 2; i++) {
                int c4 = lane + 32*i;
                float4 kr = krow4[c4];
                float4 w0 = *(const float4*)&pes[0*256 + 4*c4];
                float4 w1 = *(const float4*)&pes[1*256 + 4*c4];
                float4 w2 = *(const float4*)&pes[2*256 + 4*c4];
                float4 bb = *(const float4*)&pes[3*256 + 4*c4];
                float4 r;
                r.x = kr.x + bb.x + gx*w0.x + gy*w1.x + gz*w2.x;
                r.y = kr.y + bb.y + gx*w0.y + gy*w1.y + gz*w2.y;
                r.z = kr.z + bb.z + gx*w0.z + gy*w1.z + gz*w2.z;
                r.w = kr.w + bb.w + gx*w0.w + gy*w1.w + gz*w2.w;
                *(float4*)&kvrow[4*c4] = r;
            }
        }
    }
    __syncthreads();

    // phase 2: m[g][h][c] = sum_d k_w[h*32+d, c] * qh[g][h*32+d]   (warp = (h, c-half))
    {
        int h = w >> 1, ch = w & 1;
        float acc[4][8];   // [cc][g]
#pragma unroll
        for (int i = 0; i < 4; i++)
#pragma unroll
            for (int j = 0; j < 8; j++) acc[i][j] = 0.f;
        for (int d = 0; d < 32; d++) {
            float qv[8];
#pragma unroll
            for (int g = 0; g < 8; g++) qv[g] = qs[g*256 + h*32 + d];
            const float* wr = k_w + (size_t)(h*32 + d)*CDIM;
#pragma unroll
            for (int cc = 0; cc < 4; cc++) {
                float wv = __ldg(wr + lane + 32*(ch*4 + cc));
#pragma unroll
                for (int g = 0; g < 8; g++) acc[cc][g] += wv * qv[g];
            }
        }
#pragma unroll
        for (int cc = 0; cc < 4; cc++)
#pragma unroll
            for (int g = 0; g < 8; g++)
                mb[(g*8 + h)*CP + lane + 32*(ch*4 + cc)] = acc[cc][g];
    }
    __syncthreads();

    // phase 3: scores[g][h][s] = m[g][h] . kv[g][s]  (warp = (g, h-half); lane = (h4, s0))
    {
        int g = w >> 1, hh = w & 1;
        int h = hh*4 + (lane >> 3), s0 = lane & 7;
        float sc[2] = {0.f, 0.f};
        const float4* m4 = (const float4*)(mb + (g*8 + h)*CP);
        const float4* kv0 = (const float4*)(kv + (g*16 + s0)*CP);
        const float4* kv1 = (const float4*)(kv + (g*16 + s0 + 8)*CP);
        for (int c4 = 0; c4 < 64; c4++) {
            float4 mv = m4[c4];
            float4 k0 = kv0[c4], k1 = kv1[c4];
            sc[0] += mv.x*k0.x + mv.y*k0.y + mv.z*k0.z + mv.w*k0.w;
            sc[1] += mv.x*k1.x + mv.y*k1.y + mv.z*k1.z + mv.w*k1.w;
        }
        at[(g*8 + h)*16 + s0]     = sc[0];
        at[(g*8 + h)*16 + s0 + 8] = sc[1];
    }
    __syncthreads();

    // phase 4: masked softmax (one thread per (g,h))
    if (t < 64) {
        int g = t >> 3, h = t & 7;
        float* row = at + (g*8 + h)*16;
        const int* sg = sid + g*16;
        const float scl = 0.17677669529663687f;   // 1/sqrt(32)
        float sv[16];
        float mx = -3.0e38f;
#pragma unroll
        for (int s = 0; s < 16; s++) {
            sv[s] = (sg[s] < 0) ? -3.0e38f : row[s]*scl;
            mx = fmaxf(mx, sv[s]);
        }
        float sum = 0.f;
#pragma unroll
        for (int s = 0; s < 16; s++) {
            float e = (sg[s] < 0) ? 0.f : expf(sv[s] - mx);
            sv[s] = e; sum += e;
        }
        float inv = 1.f/sum;
#pragma unroll
        for (int s = 0; s < 16; s++) row[s] = sv[s]*inv;
    }
    __syncthreads();

    // phase 5: wkv[g][h][c] = sum_s attn[g][h][s]*kv[g][s][c]  (warp = (g, c-half), v4)
    {
        int g = w >> 1, ch = w & 1;
        int cb = ch*128 + lane*4;
        float acc[8][4];   // [h][cc]
#pragma unroll
        for (int i = 0; i < 8; i++)
#pragma unroll
            for (int j = 0; j < 4; j++) acc[i][j] = 0.f;
        for (int s = 0; s < 16; s++) {
            float av[8];
#pragma unroll
            for (int h = 0; h < 8; h++) av[h] = at[(g*8 + h)*16 + s];
            float4 kk = *(const float4*)(kv + (g*16 + s)*CP + cb);
#pragma unroll
            for (int h = 0; h < 8; h++) {
                acc[h][0] += av[h]*kk.x; acc[h][1] += av[h]*kk.y;
                acc[h][2] += av[h]*kk.z; acc[h][3] += av[h]*kk.w;
            }
        }
#pragma unroll
        for (int h = 0; h < 8; h++)
            *(float4*)(mb + (g*8 + h)*CP + cb) =
                make_float4(acc[h][0], acc[h][1], acc[h][2], acc[h][3]);
    }
    __syncthreads();

    // phase 6: ao[g][h*32+d] = sum_c wkv[g][h][c]*v_wT[c][h*32+d] + v_b  (warp=(h,g-half))
    {
        int h = w >> 1, gh = w & 1, d = lane;
        float acc[4];
#pragma unroll
        for (int g = 0; g < 4; g++) acc[g] = 0.f;
        const float* wcol = g_vwT + h*32 + d;
        for (int c4 = 0; c4 < 64; c4++) {
            float w0 = __ldg(wcol + (size_t)(4*c4+0)*CDIM);
            float w1 = __ldg(wcol + (size_t)(4*c4+1)*CDIM);
            float w2 = __ldg(wcol + (size_t)(4*c4+2)*CDIM);
            float w3 = __ldg(wcol + (size_t)(4*c4+3)*CDIM);
#pragma unroll
            for (int g = 0; g < 4; g++) {
                float4 mv = *(const float4*)&mb[((gh*4 + g)*8 + h)*CP + 4*c4];
                acc[g] += mv.x*w0 + mv.y*w1 + mv.z*w2 + mv.w*w3;
            }
        }
        float vb = v_b[h*32 + d];
#pragma unroll
        for (int g = 0; g < 4; g++)
            g_ao[(size_t)(bq0 + gh*4 + g)*CDIM + h*32 + d] = __float2bfloat16_rn(acc[g] + vb);
    }
}

// ---------------- layernorm of (ra + rb + rc), writes full f32 + bf16 ----------
__global__ void k_ln(const float* __restrict__ ra, const float* __restrict__ rb,
                     const float* __restrict__ rc,
                     const float* __restrict__ gamma, const float* __restrict__ beta,
                     float* __restrict__ out, bf16* __restrict__ outr) {
    int bq = blockIdx.x * 8 + (threadIdx.x >> 5);
    int lane = threadIdx.x & 31;
    float v[8];
    float s = 0.f;
#pragma unroll
    for (int i = 0; i < 8; i++) {
        int c = lane + 32*i;
        v[i] = ra[(size_t)bq*CDIM + c] + rb[(size_t)bq*CDIM + c] + rc[(size_t)bq*CDIM + c];
        s += v[i];
    }
#pragma unroll
    for (int o = 16; o; o >>= 1) s += __shfl_xor_sync(0xffffffffu, s, o);
    float mean = s * (1.f/256.f);
    float vs = 0.f;
#pragma unroll
    for (int i = 0; i < 8; i++) { float d = v[i]-mean; vs += d*d; }
#pragma unroll
    for (int o = 16; o; o >>= 1) vs += __shfl_xor_sync(0xffffffffu, vs, o);
    float rstd = rsqrtf(vs*(1.f/256.f) + 1e-5f);
#pragma unroll
    for (int i = 0; i < 8; i++) {
        int c = lane + 32*i;
        float r = (v[i]-mean)*rstd*gamma[c] + beta[c];
        out [(size_t)bq*CDIM + c] = r;
        outr[(size_t)bq*CDIM + c] = __float2bfloat16_rn(r);
    }
}

// ---------------- final LN2 + coalesced transpose to (B, C, NQ): 32 bq/block ------
__global__ void __launch_bounds__(256)
k_ln_out(const float* __restrict__ ra, const float* __restrict__ rb,
         const float* __restrict__ rc,
         const float* __restrict__ gamma, const float* __restrict__ beta,
         float* __restrict__ out) {
    __shared__ float tile[256][33];
    int t = threadIdx.x, lane = t & 31, w = t >> 5;
    int bq0 = blockIdx.x * 32;
    int b = bq0 >> 10, nq0 = bq0 & 1023;

    // LN phase: warp w handles bq_local = w*4 .. w*4+3
    for (int rep = 0; rep < 4; rep++) {
        int bqL = w*4 + rep;
        size_t base = (size_t)(bq0 + bqL)*CDIM;
        float v[8];
        float s = 0.f;
#pragma unroll
        for (int i = 0; i < 8; i++) {
            int c = lane + 32*i;
            v[i] = ra[base + c] + rb[base + c] + rc[base + c];
            s += v[i];
        }
#pragma unroll
        for (int o = 16; o; o >>= 1) s += __shfl_xor_sync(0xffffffffu, s, o);
        float mean = s * (1.f/256.f);
        float vs = 0.f;
#pragma unroll
        for (int i = 0; i < 8; i++) { float d = v[i]-mean; vs += d*d; }
#pragma unroll
        for (int o = 16; o; o >>= 1) vs += __shfl_xor_sync(0xffffffffu, vs, o);
        float rstd = rsqrtf(vs*(1.f/256.f) + 1e-5f);
#pragma unroll
        for (int i = 0; i < 8; i++) {
            int c = lane + 32*i;
            tile[c][bqL] = (v[i]-mean)*rstd*gamma[c] + beta[c];
        }
    }
    __syncthreads();

    // write phase: warp w writes channels [w*32, w*32+32), 128B coalesced over nq
#pragma unroll
    for (int i = 0; i < 32; i++) {
        int c = w*32 + i;
        out[((size_t)b*CDIM + c)*NQD + nq0 + lane] = tile[c][lane];
    }
}

// ---------------- launch ----------------
extern "C" void kernel_launch(void* const* d_in, const int* in_sizes, int n_in,
                              void* d_out, int out_size) {
    const float* query     = (const float*)d_in[0];
    const float* key       = (const float*)d_in[1];
    const float* query_pos = (const float*)d_in[2];
    const float* key_pos   = (const float*)d_in[3];
    const float* q_w   = (const float*)d_in[4];
    const float* q_b   = (const float*)d_in[5];
    const float* k_w   = (const float*)d_in[6];
    // d_in[7] = k_b: cancels in softmax (uniform shift per (bq,h))
    const float* v_w   = (const float*)d_in[8];
    const float* v_b   = (const float*)d_in[9];
    const float* o_w   = (const float*)d_in[10];
    const float* o_b   = (const float*)d_in[11];
    const float* lin1_w = (const float*)d_in[12];
    const float* lin1_b = (const float*)d_in[13];
    const float* lin2_w = (const float*)d_in[14];
    const float* lin2_b = (const float*)d_in[15];
    const float* n1_g = (const float*)d_in[16];
    const float* n1_b = (const float*)d_in[17];
    const float* n2_g = (const float*)d_in[18];
    const float* n2_b = (const float*)d_in[19];
    const float* qpe_w = (const float*)d_in[20];
    const float* qpe_b = (const float*)d_in[21];
    const float* kpe_w = (const float*)d_in[22];
    const float* kpe_b = (const float*)d_in[23];

    void *p_qin, *p_qh, *p_ao, *p_res1, *p_qtok, *p_x, *p_xr, *p_ff, *p_y;
    void *p_qwr, *p_owr, *p_l1r, *p_l2r;
    cudaGetSymbolAddress(&p_qin,  g_qin);
    cudaGetSymbolAddress(&p_qh,   g_qh);
    cudaGetSymbolAddress(&p_ao,   g_ao);
    cudaGetSymbolAddress(&p_res1, g_res1);
    cudaGetSymbolAddress(&p_qtok, g_qtok);
    cudaGetSymbolAddress(&p_x,    g_x);
    cudaGetSymbolAddress(&p_xr,   g_xr);
    cudaGetSymbolAddress(&p_ff,   g_ff);
    cudaGetSymbolAddress(&p_y,    g_y);
    cudaGetSymbolAddress(&p_qwr,  g_qwr);
    cudaGetSymbolAddress(&p_owr,  g_owr);
    cudaGetSymbolAddress(&p_l1r,  g_l1r);
    cudaGetSymbolAddress(&p_l2r,  g_l2r);

    const size_t SLICE = (size_t)BQTOT * CDIM;

    const int attn_smem = (8*16*CP + 8*8*CP + 8*256 + 8*128 + 4*256 + 32)*4 + 128*4;
    cudaFuncSetAttribute(k_attn, cudaFuncAttributeMaxDynamicSharedMemorySize, attn_smem);

    const int gemm_smem = 2 * STAGE_H * 2;    // 73,728 bytes (2 stages, bf16)
    cudaFuncSetAttribute(k_gemm_bf<0,0>, cudaFuncAttributeMaxDynamicSharedMemorySize, gemm_smem);
    cudaFuncSetAttribute(k_gemm_bf<1,1>, cudaFuncAttributeMaxDynamicSharedMemorySize, gemm_smem);

    // preprocessing
    k_transpose_key<<<dim3(NKD/32, CDIM/32, BATCH), dim3(32,8)>>>(key);
    k_build_q<<<dim3(NQD/32, CDIM/32, BATCH), dim3(32,8)>>>(query, query_pos, qpe_w, qpe_b);
    k_transpose_vw<<<dim3(CDIM/32, CDIM/32), dim3(32,8)>>>(v_w);
    k_boxquery<<<dim3(NQD/32, BATCH), 1024>>>(key_pos, query_pos);

    // bf16 weight copies (round-to-nearest)
    k_round<<<CDIM*CDIM/256, 256>>>(q_w,    (bf16*)p_qwr, CDIM*CDIM);
    k_round<<<CDIM*CDIM/256, 256>>>(o_w,    (bf16*)p_owr, CDIM*CDIM);
    k_round<<<FFDIM*CDIM/256, 256>>>(lin1_w, (bf16*)p_l1r, FFDIM*CDIM);
    k_round<<<CDIM*FFDIM/256, 256>>>(lin2_w, (bf16*)p_l2r, CDIM*FFDIM);

    // q projection: qh = qin @ q_w^T + q_b   (split-K x2, 256 CTAs)
    k_gemm_bf<0,0><<<dim3(CDIM/128, BQTOT/128, 2), 256, gemm_smem>>>(
        (const bf16*)p_qin, (const bf16*)p_qwr, q_b, p_qh,
        CDIM, CDIM, 128, SLICE);

    // fused gather + attention -> ao (sums the two qh slices internally)
    k_attn<<<BQTOT/8, 512, attn_smem>>>(key_pos, query_pos, kpe_w, kpe_b, k_w, v_b);

    // o projection (split-K x2)
    k_gemm_bf<0,0><<<dim3(CDIM/128, BQTOT/128, 2), 256, gemm_smem>>>(
        (const bf16*)p_ao, (const bf16*)p_owr, o_b, p_res1,
        CDIM, CDIM, 128, SLICE);

    // LN1(qtok + res1a + res1b) -> x (f32) + xr (bf16)
    k_ln<<<BQTOT/8, 256>>>((const float*)p_qtok, (const float*)p_res1,
                           (const float*)p_res1 + SLICE, n1_g, n1_b,
                           (float*)p_x, (bf16*)p_xr);

    // FFN
    k_gemm_bf<1,1><<<dim3(FFDIM/128, BQTOT/128, 1), 256, gemm_smem>>>(
        (const bf16*)p_xr, (const bf16*)p_l1r, lin1_b, p_ff,
        FFDIM, CDIM, 256, 0);
    k_gemm_bf<0,0><<<dim3(CDIM/128, BQTOT/128, 2), 256, gemm_smem>>>(
        (const bf16*)p_ff, (const bf16*)p_l2r, lin2_b, p_y,
        CDIM, FFDIM, 1024, SLICE);

    // LN2(x + y0 + y1) + coalesced transpose out
    k_ln_out<<<BQTOT/32, 256>>>((const float*)p_x, (const float*)p_y,
                                (const float*)p_y + SLICE, n2_g, n2_b, (float*)d_out);
}

// round 10
// speedup vs baseline: 4.2787x; 1.0310x over previous
#include <cuda_runtime.h>
#include <cuda_bf16.h>
#include <math.h>
#include <stdint.h>

#define BATCH 8
#define CDIM  256
#define NQD   1024
#define NKD   4096
#define SKEYS 16
#define HEADS 8
#define FFDIM 2048
#define DHD   32
#define BQTOT (BATCH*NQD)
#define CP    260   // padded smem stride (attn kernel; 16B-aligned rows)

typedef __nv_bfloat16 bf16;

// ---------------- scratch (device globals; no allocation allowed) ----------------
__device__ float g_keyT[BATCH*NKD*CDIM];     // key transposed (B, NK, C)
__device__ float g_qtok[BQTOT*CDIM];         // transposed query tokens (residual)
__device__ bf16  g_qin [BQTOT*CDIM];         // qtok + qpe (bf16, GEMM A)
__device__ float g_qh  [2*BQTOT*CDIM];       // q projection (2 split-K slices)
__device__ int   g_sidx[BQTOT*SKEYS];        // gathered key indices (-1 = masked)
__device__ float g_vwT [CDIM*CDIM];          // v_w transposed
__device__ bf16  g_ao  [BQTOT*CDIM];         // attention output (bf16, GEMM A)
__device__ float g_res1[2*BQTOT*CDIM];       // o-proj output (2 slices)
__device__ float g_x   [BQTOT*CDIM];         // after LN1 (residual)
__device__ bf16  g_xr  [BQTOT*CDIM];         // after LN1 (bf16, GEMM A)
__device__ bf16  g_ff  [BQTOT*FFDIM];        // FFN hidden (bf16, GEMM A)
__device__ float g_y   [2*BQTOT*CDIM];       // FFN out (2 slices)
// bf16 weight copies
__device__ bf16  g_qwr [CDIM*CDIM];
__device__ bf16  g_owr [CDIM*CDIM];
__device__ bf16  g_l1r [FFDIM*CDIM];
__device__ bf16  g_l2r [CDIM*FFDIM];

// ---------------- small PTX helpers ----------------
__device__ __forceinline__ uint32_t smem_u32(const void* p) {
    uint32_t a;
    asm("{ .reg .u64 t; cvta.to.shared.u64 t, %1; cvt.u32.u64 %0, t; }" : "=r"(a) : "l"(p));
    return a;
}
__device__ __forceinline__ void cp16(uint32_t s, const void* g) {
    asm volatile("cp.async.cg.shared.global [%0], [%1], 16;" :: "r"(s), "l"(g));
}
#define CP_COMMIT() asm volatile("cp.async.commit_group;" ::: "memory")
#define CP_WAIT1()  asm volatile("cp.async.wait_group 1;" ::: "memory")

#define LDSM4(R0,R1,R2,R3, ADDR) \
    asm volatile("ldmatrix.sync.aligned.m8n8.x4.shared.b16 {%0,%1,%2,%3}, [%4];" \
        : "=r"(R0), "=r"(R1), "=r"(R2), "=r"(R3) : "r"(ADDR))

__device__ __forceinline__ void mma_bf16(float* d,
                                         uint32_t a0, uint32_t a1, uint32_t a2, uint32_t a3,
                                         uint32_t b0, uint32_t b1) {
    asm volatile(
        "mma.sync.aligned.m16n8k16.row.col.f32.bf16.bf16.f32 "
        "{%0,%1,%2,%3}, {%4,%5,%6,%7}, {%8,%9}, {%0,%1,%2,%3};"
        : "+f"(d[0]), "+f"(d[1]), "+f"(d[2]), "+f"(d[3])
        : "r"(a0), "r"(a1), "r"(a2), "r"(a3), "r"(b0), "r"(b1));
}

// ---------------- bf16 mma.sync GEMM: C = A(M,lda) @ W(N,lda)^T (+ bias on z=0) ----
#define PADB 72                  // bf16 elems per smem row (144B, conflict-free)
#define STAGE_H (2*128*PADB)     // bf16 elems per stage (A + B)

template<int RELU, int OUTBF>
__global__ void __launch_bounds__(256)
k_gemm_bf(const bf16* __restrict__ A, const bf16* __restrict__ W,
          const float* __restrict__ bias, void* __restrict__ Cout,
          int N, int lda, int KS, size_t outStride) {
    extern __shared__ bf16 smh[];
    int t = threadIdx.x, lane = t & 31, wid = t >> 5;
    int wm = wid >> 1, wn = wid & 1;          // warp tile origin (wm*32, wn*64)
    int bm = blockIdx.y * 128, bn = blockIdx.x * 128;
    int kb = blockIdx.z * KS;
    const int NC = KS >> 6;
    int qr = lane >> 2, qc = lane & 3;        // quad row / quad col (epilogue)

    // ldmatrix per-lane addressing
    int lrowA = (lane & 7) + ((lane >> 3) & 1) * 8;   // 0..15
    int lsegA = (lane >> 4) * 8;                      // 0 or 8 (bf16 elems)
    int lrowB = ((lane >> 4) * 8) + (lane & 7);       // 0..15
    int lsegB = ((lane >> 3) & 1) * 8;
    uint32_t smbase = smem_u32(smh);
    uint32_t aoff = (uint32_t)(((wm*32 + lrowA)*PADB + lsegA) * 2);
    uint32_t boff = (uint32_t)((128*PADB + (wn*64 + lrowB)*PADB + lsegB) * 2);

    float acc[2][8][4];
#pragma unroll
    for (int mi = 0; mi < 2; mi++)
#pragma unroll
        for (int ni = 0; ni < 8; ni++)
#pragma unroll
            for (int j = 0; j < 4; j++) acc[mi][ni][j] = 0.f;

    // stage 0 prologue: chunk 0 (64 bf16 per row = 8 segs of 8)
    {
        bf16* As = smh; bf16* Bs = smh + 128*PADB;
        for (int u = t; u < 1024; u += 256) {
            int row = u >> 3, seg = u & 7;
            cp16(smem_u32(As + row*PADB + seg*8), A + (size_t)(bm + row)*lda + kb + seg*8);
            cp16(smem_u32(Bs + row*PADB + seg*8), W + (size_t)(bn + row)*lda + kb + seg*8);
        }
    }
    CP_COMMIT();

    for (int c = 0; c < NC; c++) {
        __syncthreads();                       // stage (c+1)&1 free (compute c-1 done)
        if (c + 1 < NC) {
            bf16* As = smh + ((c+1)&1)*STAGE_H;
            bf16* Bs = As + 128*PADB;
            int k0 = kb + (c+1)*64;
            for (int u = t; u < 1024; u += 256) {
                int row = u >> 3, seg = u & 7;
                cp16(smem_u32(As + row*PADB + seg*8), A + (size_t)(bm + row)*lda + k0 + seg*8);
                cp16(smem_u32(Bs + row*PADB + seg*8), W + (size_t)(bn + row)*lda + k0 + seg*8);
            }
        }
        CP_COMMIT();
        CP_WAIT1();                            // stage c copies done (this thread)
        __syncthreads();                       // all threads' stage-c copies visible

        uint32_t sb = smbase + ((c & 1) ? (uint32_t)(STAGE_H*2) : 0u);
        uint32_t aB = sb + aoff, bB = sb + boff;
#pragma unroll
        for (int kk = 0; kk < 4; kk++) {
            uint32_t a0[4], a1[4], bf[8][2];
            LDSM4(a0[0], a0[1], a0[2], a0[3], aB + kk*32);
            LDSM4(a1[0], a1[1], a1[2], a1[3], aB + 16*PADB*2 + kk*32);
#pragma unroll
            for (int j = 0; j < 4; j++)
                LDSM4(bf[2*j][0], bf[2*j][1], bf[2*j+1][0], bf[2*j+1][1],
                      bB + j*16*PADB*2 + kk*32);
#pragma unroll
            for (int ni = 0; ni < 8; ni++) {
                mma_bf16(acc[0][ni], a0[0], a0[1], a0[2], a0[3], bf[ni][0], bf[ni][1]);
                mma_bf16(acc[1][ni], a1[0], a1[1], a1[2], a1[3], bf[ni][0], bf[ni][1]);
            }
        }
    }

    // epilogue: direct stores; bias only on z=0
    bool addb = (blockIdx.z == 0);
#pragma unroll
    for (int mi = 0; mi < 2; mi++) {
        int r0 = bm + wm*32 + mi*16 + qr;
#pragma unroll
        for (int ni = 0; ni < 8; ni++) {
            int cn = bn + wn*64 + ni*8 + qc*2;
            float b0 = addb ? bias[cn] : 0.f, b1 = addb ? bias[cn+1] : 0.f;
            float v0 = acc[mi][ni][0] + b0, v1 = acc[mi][ni][1] + b1;
            float v2 = acc[mi][ni][2] + b0, v3 = acc[mi][ni][3] + b1;
            if (RELU) { v0=fmaxf(v0,0.f); v1=fmaxf(v1,0.f); v2=fmaxf(v2,0.f); v3=fmaxf(v3,0.f); }
            if (OUTBF) {
                bf16* C = (bf16*)Cout;
                *(__nv_bfloat162*)&C[(size_t)r0*N + cn]     = __floats2bfloat162_rn(v0, v1);
                *(__nv_bfloat162*)&C[(size_t)(r0+8)*N + cn] = __floats2bfloat162_rn(v2, v3);
            } else {
                float* C = (float*)Cout + (size_t)blockIdx.z * outStride;
                *(float2*)&C[(size_t)r0*N + cn]     = make_float2(v0, v1);
                *(float2*)&C[(size_t)(r0+8)*N + cn] = make_float2(v2, v3);
            }
        }
    }
}

// ---------------- elementwise f32 -> bf16 ----------------
__global__ void k_round(const float* __restrict__ in, bf16* __restrict__ out, int n) {
    int i = blockIdx.x * 256 + threadIdx.x;
    if (i < n) out[i] = __float2bfloat16_rn(in[i]);
}

// ---------------- transpose key (B,C,NK) -> (B,NK,C) ----------------
__global__ void k_transpose_key(const float* __restrict__ key) {
    __shared__ float tile[32][33];
    int b = blockIdx.z;
    int c0 = blockIdx.y * 32, n0 = blockIdx.x * 32;
    int tx = threadIdx.x, ty = threadIdx.y;
#pragma unroll
    for (int j = 0; j < 4; j++)
        tile[ty + 8*j][tx] = key[(b*CDIM + c0 + ty + 8*j)*NKD + n0 + tx];
    __syncthreads();
#pragma unroll
    for (int j = 0; j < 4; j++)
        g_keyT[(b*NKD + n0 + ty + 8*j)*CDIM + c0 + tx] = tile[tx][ty + 8*j];
}

// ---------------- build qtok + qin (query transpose + qpe) ----------------
__global__ void k_build_q(const float* __restrict__ query,
                          const float* __restrict__ query_pos,
                          const float* __restrict__ qpe_w,
                          const float* __restrict__ qpe_b) {
    __shared__ float tile[32][33];
    int b = blockIdx.z;
    int c0 = blockIdx.y * 32, n0 = blockIdx.x * 32;
    int tx = threadIdx.x, ty = threadIdx.y;
#pragma unroll
    for (int j = 0; j < 4; j++)
        tile[ty + 8*j][tx] = query[(b*CDIM + c0 + ty + 8*j)*NQD + n0 + tx];
    __syncthreads();
#pragma unroll
    for (int j = 0; j < 4; j++) {
        int nq = n0 + ty + 8*j, c = c0 + tx;
        int bq = b*NQD + nq;
        float qt = tile[tx][ty + 8*j];
        const float* qp = query_pos + (size_t)bq*6;
        float pe = qpe_b[c];
#pragma unroll
        for (int jj = 0; jj < 6; jj++) pe += qp[jj] * qpe_w[c*6 + jj];
        g_qtok[bq*CDIM + c] = qt;
        g_qin [bq*CDIM + c] = __float2bfloat16_rn(qt + pe);
    }
}

// ---------------- transpose v_w (256x256) ----------------
__global__ void k_transpose_vw(const float* __restrict__ v_w) {
    __shared__ float tile[32][33];
    int n0 = blockIdx.y * 32, c0 = blockIdx.x * 32;
    int tx = threadIdx.x, ty = threadIdx.y;
#pragma unroll
    for (int j = 0; j < 4; j++)
        tile[ty + 8*j][tx] = v_w[(n0 + ty + 8*j)*CDIM + c0 + tx];
    __syncthreads();
#pragma unroll
    for (int j = 0; j < 4; j++)
        g_vwT[(c0 + ty + 8*j)*CDIM + n0 + tx] = tile[tx][ty + 8*j];
}

// ---------------- box query: 32 queries/block, first 16 inside keys ---------------
__global__ void __launch_bounds__(1024)
k_boxquery(const float* __restrict__ key_pos,
           const float* __restrict__ query_pos) {
    __shared__ float kp[NKD*3];   // exactly 48KB
    int b = blockIdx.y;
    int t = threadIdx.x;
#pragma unroll
    for (int i = 0; i < 12; i++)
        kp[t + 1024*i] = key_pos[(size_t)b*NKD*3 + t + 1024*i];
    __syncthreads();

    int w = t >> 5, lane = t & 31;
    int q = blockIdx.x * 32 + w;
    int bq = b*NQD + q;
    const float* qp = query_pos + (size_t)bq*6;
    float cx = qp[0], cy = qp[1], cz = qp[2];
    float hx = 0.5f*qp[3], hy = 0.5f*qp[4], hz = 0.5f*qp[5];

    int count = 0;
    for (int base = 0; base < NKD && count < SKEYS; base += 32) {
        int k = base + lane;
        float dx = fabsf(kp[k*3+0]-cx);
        float dy = fabsf(kp[k*3+1]-cy);
        float dz = fabsf(kp[k*3+2]-cz);
        bool inside = (dx <= hx) && (dy <= hy) && (dz <= hz);
        unsigned bal = __ballot_sync(0xffffffffu, inside);
        int nb = __popc(bal);
        if (inside) {
            int rank = __popc(bal & ((1u << lane) - 1u));
            if (count + rank < SKEYS) g_sidx[bq*SKEYS + count + rank] = k;
        }
        count += nb;
        if (count > SKEYS) count = SKEYS;
    }
    if (lane < SKEYS && lane >= count)
        g_sidx[bq*SKEYS + lane] = (lane == 0) ? 0 : -1;
}

// ---------------- fused gather + attention (8 queries, 512 threads) ----------------
__global__ void __launch_bounds__(512)
k_attn(const float* __restrict__ key_pos,
       const float* __restrict__ query_pos,
       const float* __restrict__ kpe_w,
       const float* __restrict__ kpe_b,
       const float* __restrict__ k_w,
       const float* __restrict__ v_b) {
    extern __shared__ float sm[];
    float* kv = sm;                     // [8][16][CP]
    float* mb = kv + 8*16*CP;           // [8][8][CP]   (m, later wkv)
    float* qs = mb + 8*8*CP;            // [8][256]
    float* at = qs + 8*256;             // [8][8][16]   (scores, then attn)
    float* pes = at + 8*128;            // [4][256]  kpe SoA: w0,w1,w2,b
    float* qc = pes + 4*256;            // [8][4]
    int*  sid = (int*)(qc + 32);        // [8][16]

    int t = threadIdx.x, lane = t & 31, w = t >> 5;   // 16 warps
    int bq0 = blockIdx.x * 8;
    int b = bq0 >> 10;   // NQ=1024

    if (t < 128) sid[t] = g_sidx[bq0*SKEYS + t];
    if (t < 24) { int g = t/3, j = t%3; qc[g*4 + j] = query_pos[(size_t)(bq0+g)*6 + j]; }
    if (t < 256) {   // kpe SoA staging
        pes[0*256 + t] = kpe_w[t*3 + 0];
        pes[1*256 + t] = kpe_w[t*3 + 1];
        pes[2*256 + t] = kpe_w[t*3 + 2];
        pes[3*256 + t] = kpe_b[t];
    }
#pragma unroll
    for (int i = 0; i < 4; i++)
        qs[t + 512*i] = g_qh[(size_t)bq0*CDIM + t + 512*i]
                      + g_qh[(size_t)BQTOT*CDIM + (size_t)bq0*CDIM + t + 512*i];
    __syncthreads();

    // phase 1: gather kv = keyT[idx] + kpe(gxyz)   (warp = (g, s-half))
    {
        int g = w >> 1, sh = w & 1;
        float qcx = qc[g*4+0], qcy = qc[g*4+1], qcz = qc[g*4+2];
        for (int si = 0; si < 8; si++) {
            int s = sh*8 + si;
            int v = sid[g*16 + s];
            int kidx = v < 0 ? 0 : v;
            int base = b*NKD + kidx;
            float gx = key_pos[base*3+0] - qcx;
            float gy = key_pos[base*3+1] - qcy;
            float gz = key_pos[base*3+2] - qcz;
            const float4* krow4 = (const float4*)(g_keyT + (size_t)base*CDIM);
            float* kvrow = kv + (g*16 + s)*CP;
#pragma unroll
            for (int i = 0; i < 2; i++) {
                int c4 = lane + 32*i;
                float4 kr = krow4[c4];
                float4 w0 = *(const float4*)&pes[0*256 + 4*c4];
                float4 w1 = *(const float4*)&pes[1*256 + 4*c4];
                float4 w2 = *(const float4*)&pes[2*256 + 4*c4];
                float4 bb = *(const float4*)&pes[3*256 + 4*c4];
                float4 r;
                r.x = kr.x + bb.x + gx*w0.x + gy*w1.x + gz*w2.x;
                r.y = kr.y + bb.y + gx*w0.y + gy*w1.y + gz*w2.y;
                r.z = kr.z + bb.z + gx*w0.z + gy*w1.z + gz*w2.z;
                r.w = kr.w + bb.w + gx*w0.w + gy*w1.w + gz*w2.w;
                *(float4*)&kvrow[4*c4] = r;
            }
        }
    }
    __syncthreads();

    // phase 2: m[g][h][c] = sum_d k_w[h*32+d, c] * qh[g][h*32+d]   (warp = (h, c-half))
    {
        int h = w >> 1, ch = w & 1;
        float acc[4][8];   // [cc][g]
#pragma unroll
        for (int i = 0; i < 4; i++)
#pragma unroll
            for (int j = 0; j < 8; j++) acc[i][j] = 0.f;
        for (int d = 0; d < 32; d++) {
            float qv[8];
#pragma unroll
            for (int g = 0; g < 8; g++) qv[g] = qs[g*256 + h*32 + d];
            const float* wr = k_w + (size_t)(h*32 + d)*CDIM;
#pragma unroll
            for (int cc = 0; cc < 4; cc++) {
                float wv = __ldg(wr + lane + 32*(ch*4 + cc));
#pragma unroll
                for (int g = 0; g < 8; g++) acc[cc][g] += wv * qv[g];
            }
        }
#pragma unroll
        for (int cc = 0; cc < 4; cc++)
#pragma unroll
            for (int g = 0; g < 8; g++)
                mb[(g*8 + h)*CP + lane + 32*(ch*4 + cc)] = acc[cc][g];
    }
    __syncthreads();

    // phase 3: scores[g][h][s] = m[g][h] . kv[g][s]  (warp = (g, h-half); lane = (h4, s0))
    {
        int g = w >> 1, hh = w & 1;
        int h = hh*4 + (lane >> 3), s0 = lane & 7;
        float sc[2] = {0.f, 0.f};
        const float4* m4 = (const float4*)(mb + (g*8 + h)*CP);
        const float4* kv0 = (const float4*)(kv + (g*16 + s0)*CP);
        const float4* kv1 = (const float4*)(kv + (g*16 + s0 + 8)*CP);
        for (int c4 = 0; c4 < 64; c4++) {
            float4 mv = m4[c4];
            float4 k0 = kv0[c4], k1 = kv1[c4];
            sc[0] += mv.x*k0.x + mv.y*k0.y + mv.z*k0.z + mv.w*k0.w;
            sc[1] += mv.x*k1.x + mv.y*k1.y + mv.z*k1.z + mv.w*k1.w;
        }
        at[(g*8 + h)*16 + s0]     = sc[0];
        at[(g*8 + h)*16 + s0 + 8] = sc[1];
    }
    __syncthreads();

    // phase 4: masked softmax (one thread per (g,h))
    if (t < 64) {
        int g = t >> 3, h = t & 7;
        float* row = at + (g*8 + h)*16;
        const int* sg = sid + g*16;
        const float scl = 0.17677669529663687f;   // 1/sqrt(32)
        float sv[16];
        float mx = -3.0e38f;
#pragma unroll
        for (int s = 0; s < 16; s++) {
            sv[s] = (sg[s] < 0) ? -3.0e38f : row[s]*scl;
            mx = fmaxf(mx, sv[s]);
        }
        float sum = 0.f;
#pragma unroll
        for (int s = 0; s < 16; s++) {
            float e = (sg[s] < 0) ? 0.f : __expf(sv[s] - mx);
            sv[s] = e; sum += e;
        }
        float inv = 1.f/sum;
#pragma unroll
        for (int s = 0; s < 16; s++) row[s] = sv[s]*inv;
    }
    __syncthreads();

    // phase 5: wkv[g][h][c] = sum_s attn[g][h][s]*kv[g][s][c]  (warp = (g, c-half), v4)
    {
        int g = w >> 1, ch = w & 1;
        int cb = ch*128 + lane*4;
        float acc[8][4];   // [h][cc]
#pragma unroll
        for (int i = 0; i < 8; i++)
#pragma unroll
            for (int j = 0; j < 4; j++) acc[i][j] = 0.f;
        for (int s = 0; s < 16; s++) {
            float av[8];
#pragma unroll
            for (int h = 0; h < 8; h++) av[h] = at[(g*8 + h)*16 + s];
            float4 kk = *(const float4*)(kv + (g*16 + s)*CP + cb);
#pragma unroll
            for (int h = 0; h < 8; h++) {
                acc[h][0] += av[h]*kk.x; acc[h][1] += av[h]*kk.y;
                acc[h][2] += av[h]*kk.z; acc[h][3] += av[h]*kk.w;
            }
        }
#pragma unroll
        for (int h = 0; h < 8; h++)
            *(float4*)(mb + (g*8 + h)*CP + cb) =
                make_float4(acc[h][0], acc[h][1], acc[h][2], acc[h][3]);
    }
    __syncthreads();

    // phase 6: ao[g][h*32+d] = sum_c wkv[g][h][c]*v_wT[c][h*32+d] + v_b  (warp=(h,g-half))
    {
        int h = w >> 1, gh = w & 1, d = lane;
        float acc[4];
#pragma unroll
        for (int g = 0; g < 4; g++) acc[g] = 0.f;
        const float* wcol = g_vwT + h*32 + d;
        for (int c4 = 0; c4 < 64; c4++) {
            float w0 = __ldg(wcol + (size_t)(4*c4+0)*CDIM);
            float w1 = __ldg(wcol + (size_t)(4*c4+1)*CDIM);
            float w2 = __ldg(wcol + (size_t)(4*c4+2)*CDIM);
            float w3 = __ldg(wcol + (size_t)(4*c4+3)*CDIM);
#pragma unroll
            for (int g = 0; g < 4; g++) {
                float4 mv = *(const float4*)&mb[((gh*4 + g)*8 + h)*CP + 4*c4];
                acc[g] += mv.x*w0 + mv.y*w1 + mv.z*w2 + mv.w*w3;
            }
        }
        float vb = v_b[h*32 + d];
#pragma unroll
        for (int g = 0; g < 4; g++)
            g_ao[(size_t)(bq0 + gh*4 + g)*CDIM + h*32 + d] = __float2bfloat16_rn(acc[g] + vb);
    }
}

// ---------------- layernorm of (ra + rb + rc), writes full f32 + bf16 ----------
__global__ void k_ln(const float* __restrict__ ra, const float* __restrict__ rb,
                     const float* __restrict__ rc,
                     const float* __restrict__ gamma, const float* __restrict__ beta,
                     float* __restrict__ out, bf16* __restrict__ outr) {
    int bq = blockIdx.x * 8 + (threadIdx.x >> 5);
    int lane = threadIdx.x & 31;
    float v[8];
    float s = 0.f;
#pragma unroll
    for (int i = 0; i < 8; i++) {
        int c = lane + 32*i;
        v[i] = ra[(size_t)bq*CDIM + c] + rb[(size_t)bq*CDIM + c] + rc[(size_t)bq*CDIM + c];
        s += v[i];
    }
#pragma unroll
    for (int o = 16; o; o >>= 1) s += __shfl_xor_sync(0xffffffffu, s, o);
    float mean = s * (1.f/256.f);
    float vs = 0.f;
#pragma unroll
    for (int i = 0; i < 8; i++) { float d = v[i]-mean; vs += d*d; }
#pragma unroll
    for (int o = 16; o; o >>= 1) vs += __shfl_xor_sync(0xffffffffu, vs, o);
    float rstd = rsqrtf(vs*(1.f/256.f) + 1e-5f);
#pragma unroll
    for (int i = 0; i < 8; i++) {
        int c = lane + 32*i;
        float r = (v[i]-mean)*rstd*gamma[c] + beta[c];
        out [(size_t)bq*CDIM + c] = r;
        outr[(size_t)bq*CDIM + c] = __float2bfloat16_rn(r);
    }
}

// ---------------- final LN2 + coalesced transpose to (B, C, NQ): 32 bq/block ------
__global__ void __launch_bounds__(256)
k_ln_out(const float* __restrict__ ra, const float* __restrict__ rb,
         const float* __restrict__ rc,
         const float* __restrict__ gamma, const float* __restrict__ beta,
         float* __restrict__ out) {
    __shared__ float tile[256][33];
    int t = threadIdx.x, lane = t & 31, w = t >> 5;
    int bq0 = blockIdx.x * 32;
    int b = bq0 >> 10, nq0 = bq0 & 1023;

    // LN phase: warp w handles bq_local = w*4 .. w*4+3
    for (int rep = 0; rep < 4; rep++) {
        int bqL = w*4 + rep;
        size_t base = (size_t)(bq0 + bqL)*CDIM;
        float v[8];
        float s = 0.f;
#pragma unroll
        for (int i = 0; i < 8; i++) {
            int c = lane + 32*i;
            v[i] = ra[base + c] + rb[base + c] + rc[base + c];
            s += v[i];
        }
#pragma unroll
        for (int o = 16; o; o >>= 1) s += __shfl_xor_sync(0xffffffffu, s, o);
        float mean = s * (1.f/256.f);
        float vs = 0.f;
#pragma unroll
        for (int i = 0; i < 8; i++) { float d = v[i]-mean; vs += d*d; }
#pragma unroll
        for (int o = 16; o; o >>= 1) vs += __shfl_xor_sync(0xffffffffu, vs, o);
        float rstd = rsqrtf(vs*(1.f/256.f) + 1e-5f);
#pragma unroll
        for (int i = 0; i < 8; i++) {
            int c = lane + 32*i;
            tile[c][bqL] = (v[i]-mean)*rstd*gamma[c] + beta[c];
        }
    }
    __syncthreads();

    // write phase: warp w writes channels [w*32, w*32+32), 128B coalesced over nq
#pragma unroll
    for (int i = 0; i < 32; i++) {
        int c = w*32 + i;
        out[((size_t)b*CDIM + c)*NQD + nq0 + lane] = tile[c][lane];
    }
}

// ---------------- launch ----------------
extern "C" void kernel_launch(void* const* d_in, const int* in_sizes, int n_in,
                              void* d_out, int out_size) {
    const float* query     = (const float*)d_in[0];
    const float* key       = (const float*)d_in[1];
    const float* query_pos = (const float*)d_in[2];
    const float* key_pos   = (const float*)d_in[3];
    const float* q_w   = (const float*)d_in[4];
    const float* q_b   = (const float*)d_in[5];
    const float* k_w   = (const float*)d_in[6];
    // d_in[7] = k_b: cancels in softmax (uniform shift per (bq,h))
    const float* v_w   = (const float*)d_in[8];
    const float* v_b   = (const float*)d_in[9];
    const float* o_w   = (const float*)d_in[10];
    const float* o_b   = (const float*)d_in[11];
    const float* lin1_w = (const float*)d_in[12];
    const float* lin1_b = (const float*)d_in[13];
    const float* lin2_w = (const float*)d_in[14];
    const float* lin2_b = (const float*)d_in[15];
    const float* n1_g = (const float*)d_in[16];
    const float* n1_b = (const float*)d_in[17];
    const float* n2_g = (const float*)d_in[18];
    const float* n2_b = (const float*)d_in[19];
    const float* qpe_w = (const float*)d_in[20];
    const float* qpe_b = (const float*)d_in[21];
    const float* kpe_w = (const float*)d_in[22];
    const float* kpe_b = (const float*)d_in[23];

    void *p_qin, *p_qh, *p_ao, *p_res1, *p_qtok, *p_x, *p_xr, *p_ff, *p_y;
    void *p_qwr, *p_owr, *p_l1r, *p_l2r;
    cudaGetSymbolAddress(&p_qin,  g_qin);
    cudaGetSymbolAddress(&p_qh,   g_qh);
    cudaGetSymbolAddress(&p_ao,   g_ao);
    cudaGetSymbolAddress(&p_res1, g_res1);
    cudaGetSymbolAddress(&p_qtok, g_qtok);
    cudaGetSymbolAddress(&p_x,    g_x);
    cudaGetSymbolAddress(&p_xr,   g_xr);
    cudaGetSymbolAddress(&p_ff,   g_ff);
    cudaGetSymbolAddress(&p_y,    g_y);
    cudaGetSymbolAddress(&p_qwr,  g_qwr);
    cudaGetSymbolAddress(&p_owr,  g_owr);
    cudaGetSymbolAddress(&p_l1r,  g_l1r);
    cudaGetSymbolAddress(&p_l2r,  g_l2r);

    const size_t SLICE = (size_t)BQTOT * CDIM;

    const int attn_smem = (8*16*CP + 8*8*CP + 8*256 + 8*128 + 4*256 + 32)*4 + 128*4;
    cudaFuncSetAttribute(k_attn, cudaFuncAttributeMaxDynamicSharedMemorySize, attn_smem);

    const int gemm_smem = 2 * STAGE_H * 2;    // 73,728 bytes (2 stages, bf16)
    cudaFuncSetAttribute(k_gemm_bf<0,0>, cudaFuncAttributeMaxDynamicSharedMemorySize, gemm_smem);
    cudaFuncSetAttribute(k_gemm_bf<1,1>, cudaFuncAttributeMaxDynamicSharedMemorySize, gemm_smem);

    // streams/events for capturable fork-join (host resources only; created once)
    static cudaStream_t s1 = nullptr, s2 = nullptr, s3 = nullptr;
    static cudaEvent_t  evR = nullptr, e1 = nullptr, e2 = nullptr, e3 = nullptr;
    if (!s1) {
        cudaStreamCreateWithFlags(&s1, cudaStreamNonBlocking);
        cudaStreamCreateWithFlags(&s2, cudaStreamNonBlocking);
        cudaStreamCreateWithFlags(&s3, cudaStreamNonBlocking);
        cudaEventCreateWithFlags(&evR, cudaEventDisableTiming);
        cudaEventCreateWithFlags(&e1,  cudaEventDisableTiming);
        cudaEventCreateWithFlags(&e2,  cudaEventDisableTiming);
        cudaEventCreateWithFlags(&e3,  cudaEventDisableTiming);
    }

    // ---- fork ----
    cudaEventRecord(evR, 0);
    cudaStreamWaitEvent(s1, evR, 0);
    cudaStreamWaitEvent(s2, evR, 0);
    cudaStreamWaitEvent(s3, evR, 0);

    // s1: key transpose
    k_transpose_key<<<dim3(NKD/32, CDIM/32, BATCH), dim3(32,8), 0, s1>>>(key);
    // s3: box query
    k_boxquery<<<dim3(NQD/32, BATCH), 1024, 0, s3>>>(key_pos, query_pos);
    // s2: v_w transpose + weight rounds for o/lin1/lin2
    k_transpose_vw<<<dim3(CDIM/32, CDIM/32), dim3(32,8), 0, s2>>>(v_w);
    k_round<<<CDIM*CDIM/256, 256, 0, s2>>>(o_w,     (bf16*)p_owr, CDIM*CDIM);
    k_round<<<FFDIM*CDIM/256, 256, 0, s2>>>(lin1_w, (bf16*)p_l1r, FFDIM*CDIM);
    k_round<<<CDIM*FFDIM/256, 256, 0, s2>>>(lin2_w, (bf16*)p_l2r, CDIM*FFDIM);
    // default: build_q -> round(q_w) -> q-projection
    k_build_q<<<dim3(NQD/32, CDIM/32, BATCH), dim3(32,8)>>>(query, query_pos, qpe_w, qpe_b);
    k_round<<<CDIM*CDIM/256, 256>>>(q_w, (bf16*)p_qwr, CDIM*CDIM);
    k_gemm_bf<0,0><<<dim3(CDIM/128, BQTOT/128, 2), 256, gemm_smem>>>(
        (const bf16*)p_qin, (const bf16*)p_qwr, q_b, p_qh,
        CDIM, CDIM, 128, SLICE);

    // ---- join ----
    cudaEventRecord(e1, s1);
    cudaEventRecord(e2, s2);
    cudaEventRecord(e3, s3);
    cudaStreamWaitEvent(0, e1, 0);
    cudaStreamWaitEvent(0, e2, 0);
    cudaStreamWaitEvent(0, e3, 0);

    // fused gather + attention -> ao (sums the two qh slices internally)
    k_attn<<<BQTOT/8, 512, attn_smem>>>(key_pos, query_pos, kpe_w, kpe_b, k_w, v_b);

    // o projection (split-K x2)
    k_gemm_bf<0,0><<<dim3(CDIM/128, BQTOT/128, 2), 256, gemm_smem>>>(
        (const bf16*)p_ao, (const bf16*)p_owr, o_b, p_res1,
        CDIM, CDIM, 128, SLICE);

    // LN1(qtok + res1a + res1b) -> x (f32) + xr (bf16)
    k_ln<<<BQTOT/8, 256>>>((const float*)p_qtok, (const float*)p_res1,
                           (const float*)p_res1 + SLICE, n1_g, n1_b,
                           (float*)p_x, (bf16*)p_xr);

    // FFN
    k_gemm_bf<1,1><<<dim3(FFDIM/128, BQTOT/128, 1), 256, gemm_smem>>>(
        (const bf16*)p_xr, (const bf16*)p_l1r, lin1_b, p_ff,
        FFDIM, CDIM, 256, 0);
    k_gemm_bf<0,0><<<dim3(CDIM/128, BQTOT/128, 2), 256, gemm_smem>>>(
        (const bf16*)p_ff, (const bf16*)p_l2r, lin2_b, p_y,
        CDIM, FFDIM, 1024, SLICE);

    // LN2(x + y0 + y1) + coalesced transpose out
    k_ln_out<<<BQTOT/32, 256>>>((const float*)p_x, (const float*)p_y,
                                (const float*)p_y + SLICE, n2_g, n2_b, (float*)d_out);
}

// round 13
// speedup vs baseline: 4.6810x; 1.0940x over previous
#include <cuda_runtime.h>
#include <cuda_bf16.h>
#include <math.h>
#include <stdint.h>

#define BATCH 8
#define CDIM  256
#define NQD   1024
#define NKD   4096
#define SKEYS 16
#define HEADS 8
#define FFDIM 2048
#define DHD   32
#define BQTOT (BATCH*NQD)
#define CP    260   // padded smem stride (attn kernel; 16B-aligned rows)
#define HC    2048  // HEADS*CDIM

typedef __nv_bfloat16 bf16;

// ---------------- scratch (device globals; no allocation allowed) ----------------
__device__ float g_keyT[BATCH*NKD*CDIM];     // key transposed (B, NK, C)
__device__ float g_qtok[BQTOT*CDIM];         // transposed query tokens (residual)
__device__ bf16  g_qin [BQTOT*CDIM];         // qtok + qpe (bf16, GEMM A)
__device__ float g_m   [(size_t)BQTOT*HC];   // fused q*W2 scores operand (f32)
__device__ int   g_sidx[BQTOT*SKEYS];        // gathered key indices (-1 = masked)
__device__ bf16  g_wkv [(size_t)BQTOT*HC];   // attn-weighted kv, flat (bf16)
__device__ float g_res1[2*BQTOT*CDIM];       // fused o-proj output (2 split-K slices)
__device__ float g_x   [BQTOT*CDIM];         // after LN1 (residual)
__device__ bf16  g_xr  [BQTOT*CDIM];         // after LN1 (bf16, GEMM A)
__device__ bf16  g_ff  [BQTOT*FFDIM];        // FFN hidden (bf16, GEMM A)
__device__ float g_y   [2*BQTOT*CDIM];       // FFN out (2 slices)
// fused / rounded weights
__device__ bf16  g_w2  [HC*CDIM];            // W2[h*256+c][e]
__device__ float g_mbias[HC];                // k_w^T q_b
__device__ bf16  g_w3  [CDIM*HC];            // W3[n][h*256+c]
__device__ float g_b3  [CDIM];               // o_b + o_w @ v_b
__device__ bf16  g_l1r [FFDIM*CDIM];
__device__ bf16  g_l2r [CDIM*FFDIM];

// ---------------- small PTX helpers ----------------
__device__ __forceinline__ uint32_t smem_u32(const void* p) {
    uint32_t a;
    asm("{ .reg .u64 t; cvta.to.shared.u64 t, %1; cvt.u32.u64 %0, t; }" : "=r"(a) : "l"(p));
    return a;
}
__device__ __forceinline__ void cp16(uint32_t s, const void* g) {
    asm volatile("cp.async.cg.shared.global [%0], [%1], 16;" :: "r"(s), "l"(g));
}
#define CP_COMMIT() asm volatile("cp.async.commit_group;" ::: "memory")
#define CP_WAIT1()  asm volatile("cp.async.wait_group 1;" ::: "memory")

#define LDSM4(R0,R1,R2,R3, ADDR) \
    asm volatile("ldmatrix.sync.aligned.m8n8.x4.shared.b16 {%0,%1,%2,%3}, [%4];" \
        : "=r"(R0), "=r"(R1), "=r"(R2), "=r"(R3) : "r"(ADDR))

__device__ __forceinline__ void mma_bf16(float* d,
                                         uint32_t a0, uint32_t a1, uint32_t a2, uint32_t a3,
                                         uint32_t b0, uint32_t b1) {
    asm volatile(
        "mma.sync.aligned.m16n8k16.row.col.f32.bf16.bf16.f32 "
        "{%0,%1,%2,%3}, {%4,%5,%6,%7}, {%8,%9}, {%0,%1,%2,%3};"
        : "+f"(d[0]), "+f"(d[1]), "+f"(d[2]), "+f"(d[3])
        : "r"(a0), "r"(a1), "r"(a2), "r"(a3), "r"(b0), "r"(b1));
}

// ---------------- bf16 mma.sync GEMM: C = A(M,lda) @ W(N,lda)^T (+ bias on z=0) ----
#define PADB 72                  // bf16 elems per smem row (144B, conflict-free)
#define STAGE_H (2*128*PADB)     // bf16 elems per stage (A + B)

template<int RELU, int OUTBF>
__global__ void __launch_bounds__(256)
k_gemm_bf(const bf16* __restrict__ A, const bf16* __restrict__ W,
          const float* __restrict__ bias, void* __restrict__ Cout,
          int N, int lda, int KS, size_t outStride) {
    extern __shared__ bf16 smh[];
    int t = threadIdx.x, lane = t & 31, wid = t >> 5;
    int wm = wid >> 1, wn = wid & 1;          // warp tile origin (wm*32, wn*64)
    int bm = blockIdx.y * 128, bn = blockIdx.x * 128;
    int kb = blockIdx.z * KS;
    const int NC = KS >> 6;
    int qr = lane >> 2, qc = lane & 3;        // quad row / quad col (epilogue)

    // ldmatrix per-lane addressing
    int lrowA = (lane & 7) + ((lane >> 3) & 1) * 8;   // 0..15
    int lsegA = (lane >> 4) * 8;                      // 0 or 8 (bf16 elems)
    int lrowB = ((lane >> 4) * 8) + (lane & 7);       // 0..15
    int lsegB = ((lane >> 3) & 1) * 8;
    uint32_t smbase = smem_u32(smh);
    uint32_t aoff = (uint32_t)(((wm*32 + lrowA)*PADB + lsegA) * 2);
    uint32_t boff = (uint32_t)((128*PADB + (wn*64 + lrowB)*PADB + lsegB) * 2);

    float acc[2][8][4];
#pragma unroll
    for (int mi = 0; mi < 2; mi++)
#pragma unroll
        for (int ni = 0; ni < 8; ni++)
#pragma unroll
            for (int j = 0; j < 4; j++) acc[mi][ni][j] = 0.f;

    // stage 0 prologue: chunk 0 (64 bf16 per row = 8 segs of 8)
    {
        bf16* As = smh; bf16* Bs = smh + 128*PADB;
        for (int u = t; u < 1024; u += 256) {
            int row = u >> 3, seg = u & 7;
            cp16(smem_u32(As + row*PADB + seg*8), A + (size_t)(bm + row)*lda + kb + seg*8);
            cp16(smem_u32(Bs + row*PADB + seg*8), W + (size_t)(bn + row)*lda + kb + seg*8);
        }
    }
    CP_COMMIT();

    for (int c = 0; c < NC; c++) {
        __syncthreads();                       // stage (c+1)&1 free (compute c-1 done)
        if (c + 1 < NC) {
            bf16* As = smh + ((c+1)&1)*STAGE_H;
            bf16* Bs = As + 128*PADB;
            int k0 = kb + (c+1)*64;
            for (int u = t; u < 1024; u += 256) {
                int row = u >> 3, seg = u & 7;
                cp16(smem_u32(As + row*PADB + seg*8), A + (size_t)(bm + row)*lda + k0 + seg*8);
                cp16(smem_u32(Bs + row*PADB + seg*8), W + (size_t)(bn + row)*lda + k0 + seg*8);
            }
        }
        CP_COMMIT();
        CP_WAIT1();                            // stage c copies done (this thread)
        __syncthreads();                       // all threads' stage-c copies visible

        uint32_t sb = smbase + ((c & 1) ? (uint32_t)(STAGE_H*2) : 0u);
        uint32_t aB = sb + aoff, bB = sb + boff;
#pragma unroll
        for (int kk = 0; kk < 4; kk++) {
            uint32_t a0[4], a1[4], bf[8][2];
            LDSM4(a0[0], a0[1], a0[2], a0[3], aB + kk*32);
            LDSM4(a1[0], a1[1], a1[2], a1[3], aB + 16*PADB*2 + kk*32);
#pragma unroll
            for (int j = 0; j < 4; j++)
                LDSM4(bf[2*j][0], bf[2*j][1], bf[2*j+1][0], bf[2*j+1][1],
                      bB + j*16*PADB*2 + kk*32);
#pragma unroll
            for (int ni = 0; ni < 8; ni++) {
                mma_bf16(acc[0][ni], a0[0], a0[1], a0[2], a0[3], bf[ni][0], bf[ni][1]);
                mma_bf16(acc[1][ni], a1[0], a1[1], a1[2], a1[3], bf[ni][0], bf[ni][1]);
            }
        }
    }

    // epilogue: direct stores; bias only on z=0
    bool addb = (blockIdx.z == 0);
#pragma unroll
    for (int mi = 0; mi < 2; mi++) {
        int r0 = bm + wm*32 + mi*16 + qr;
#pragma unroll
        for (int ni = 0; ni < 8; ni++) {
            int cn = bn + wn*64 + ni*8 + qc*2;
            float b0 = addb ? bias[cn] : 0.f, b1 = addb ? bias[cn+1] : 0.f;
            float v0 = acc[mi][ni][0] + b0, v1 = acc[mi][ni][1] + b1;
            float v2 = acc[mi][ni][2] + b0, v3 = acc[mi][ni][3] + b1;
            if (RELU) { v0=fmaxf(v0,0.f); v1=fmaxf(v1,0.f); v2=fmaxf(v2,0.f); v3=fmaxf(v3,0.f); }
            if (OUTBF) {
                bf16* C = (bf16*)Cout;
                *(__nv_bfloat162*)&C[(size_t)r0*N + cn]     = __floats2bfloat162_rn(v0, v1);
                *(__nv_bfloat162*)&C[(size_t)(r0+8)*N + cn] = __floats2bfloat162_rn(v2, v3);
            } else {
                float* C = (float*)Cout + (size_t)blockIdx.z * outStride;
                *(float2*)&C[(size_t)r0*N + cn]     = make_float2(v0, v1);
                *(float2*)&C[(size_t)(r0+8)*N + cn] = make_float2(v2, v3);
            }
        }
    }
}

// ---------------- elementwise f32 -> bf16 ----------------
__global__ void k_round(const float* __restrict__ in, bf16* __restrict__ out, int n) {
    int i = blockIdx.x * 256 + threadIdx.x;
    if (i < n) out[i] = __float2bfloat16_rn(in[i]);
}

// ---------------- W2 prep: W2[h*256+c][e] = sum_d q_w[hd,e]*k_w[hd,c]; mbias = k_w^T q_b
__global__ void __launch_bounds__(256)
k_prep_w2(const float* __restrict__ qw, const float* __restrict__ kw,
          const float* __restrict__ qb) {
    __shared__ float kc[32][33];
    __shared__ float qbs[32];
    int h = blockIdx.x >> 3, c0 = (blockIdx.x & 7) * 32;
    int t = threadIdx.x;
    for (int u = t; u < 1024; u += 256) {
        int d = u >> 5, cl = u & 31;
        kc[d][cl] = kw[(size_t)(h*32 + d)*CDIM + c0 + cl];
    }
    if (t < 32) qbs[t] = qb[h*32 + t];
    __syncthreads();
    float qe[32];
#pragma unroll
    for (int d = 0; d < 32; d++) qe[d] = qw[(size_t)(h*32 + d)*CDIM + t];
    for (int cl = 0; cl < 32; cl++) {
        float s = 0.f;
#pragma unroll
        for (int d = 0; d < 32; d++) s += qe[d]*kc[d][cl];
        g_w2[(size_t)(h*256 + c0 + cl)*CDIM + t] = __float2bfloat16_rn(s);
    }
    if (t < 32) {
        float s = 0.f;
#pragma unroll
        for (int d = 0; d < 32; d++) s += kc[d][t]*qbs[d];
        g_mbias[h*256 + c0 + t] = s;
    }
}

// ---------------- W3 prep: W3[n][h*256+c] = sum_d o_w[n,hd]*v_w[hd,c] ----------------
__global__ void __launch_bounds__(256)
k_prep_w3(const float* __restrict__ ow, const float* __restrict__ vw) {
    __shared__ float os[64][33];
    int h = blockIdx.x >> 2, n0 = (blockIdx.x & 3) * 64;
    int t = threadIdx.x;
    for (int u = t; u < 2048; u += 256) {
        int nl = u >> 5, d = u & 31;
        os[nl][d] = ow[(size_t)(n0 + nl)*CDIM + h*32 + d];
    }
    float vd[32];
#pragma unroll
    for (int d = 0; d < 32; d++) vd[d] = vw[(size_t)(h*32 + d)*CDIM + t];
    __syncthreads();
    for (int nl = 0; nl < 64; nl++) {
        float s = 0.f;
#pragma unroll
        for (int d = 0; d < 32; d++) s += os[nl][d]*vd[d];
        g_w3[(size_t)(n0 + nl)*HC + h*256 + t] = __float2bfloat16_rn(s);
    }
}

// ---------------- b3 prep: b3[n] = o_b[n] + o_w[n,:] @ v_b ----------------
__global__ void __launch_bounds__(256)
k_prep_b3(const float* __restrict__ ow, const float* __restrict__ ob,
          const float* __restrict__ vb) {
    __shared__ float vbs[256];
    int t = threadIdx.x;
    vbs[t] = vb[t];
    __syncthreads();
    float s = ob[t];
    for (int k = 0; k < 256; k++) s += ow[(size_t)t*CDIM + k]*vbs[k];
    g_b3[t] = s;
}

// ---------------- transpose key (B,C,NK) -> (B,NK,C) ----------------
__global__ void k_transpose_key(const float* __restrict__ key) {
    __shared__ float tile[32][33];
    int b = blockIdx.z;
    int c0 = blockIdx.y * 32, n0 = blockIdx.x * 32;
    int tx = threadIdx.x, ty = threadIdx.y;
#pragma unroll
    for (int j = 0; j < 4; j++)
        tile[ty + 8*j][tx] = key[(b*CDIM + c0 + ty + 8*j)*NKD + n0 + tx];
    __syncthreads();
#pragma unroll
    for (int j = 0; j < 4; j++)
        g_keyT[(b*NKD + n0 + ty + 8*j)*CDIM + c0 + tx] = tile[tx][ty + 8*j];
}

// ---------------- build qtok + qin (query transpose + qpe) ----------------
__global__ void k_build_q(const float* __restrict__ query,
                          const float* __restrict__ query_pos,
                          const float* __restrict__ qpe_w,
                          const float* __restrict__ qpe_b) {
    __shared__ float tile[32][33];
    int b = blockIdx.z;
    int c0 = blockIdx.y * 32, n0 = blockIdx.x * 32;
    int tx = threadIdx.x, ty = threadIdx.y;
#pragma unroll
    for (int j = 0; j < 4; j++)
        tile[ty + 8*j][tx] = query[(b*CDIM + c0 + ty + 8*j)*NQD + n0 + tx];
    __syncthreads();
#pragma unroll
    for (int j = 0; j < 4; j++) {
        int nq = n0 + ty + 8*j, c = c0 + tx;
        int bq = b*NQD + nq;
        float qt = tile[tx][ty + 8*j];
        const float* qp = query_pos + (size_t)bq*6;
        float pe = qpe_b[c];
#pragma unroll
        for (int jj = 0; jj < 6; jj++) pe += qp[jj] * qpe_w[c*6 + jj];
        g_qtok[bq*CDIM + c] = qt;
        g_qin [bq*CDIM + c] = __float2bfloat16_rn(qt + pe);
    }
}

// ---------------- box query: 32 queries/block, first 16 inside keys ---------------
__global__ void __launch_bounds__(1024)
k_boxquery(const float* __restrict__ key_pos,
           const float* __restrict__ query_pos) {
    __shared__ float kp[NKD*3];   // exactly 48KB
    int b = blockIdx.y;
    int t = threadIdx.x;
#pragma unroll
    for (int i = 0; i < 12; i++)
        kp[t + 1024*i] = key_pos[(size_t)b*NKD*3 + t + 1024*i];
    __syncthreads();

    int w = t >> 5, lane = t & 31;
    int q = blockIdx.x * 32 + w;
    int bq = b*NQD + q;
    const float* qp = query_pos + (size_t)bq*6;
    float cx = qp[0], cy = qp[1], cz = qp[2];
    float hx = 0.5f*qp[3], hy = 0.5f*qp[4], hz = 0.5f*qp[5];

    int count = 0;
    for (int base = 0; base < NKD && count < SKEYS; base += 32) {
        int k = base + lane;
        float dx = fabsf(kp[k*3+0]-cx);
        float dy = fabsf(kp[k*3+1]-cy);
        float dz = fabsf(kp[k*3+2]-cz);
        bool inside = (dx <= hx) && (dy <= hy) && (dz <= hz);
        unsigned bal = __ballot_sync(0xffffffffu, inside);
        int nb = __popc(bal);
        if (inside) {
            int rank = __popc(bal & ((1u << lane) - 1u));
            if (count + rank < SKEYS) g_sidx[bq*SKEYS + count + rank] = k;
        }
        count += nb;
        if (count > SKEYS) count = SKEYS;
    }
    if (lane < SKEYS && lane >= count)
        g_sidx[bq*SKEYS + lane] = (lane == 0) ? 0 : -1;
}

// ---------------- fused gather + attention core (8 queries, 512 threads) ------------
// Reads g_m (pre-fused scores operand); writes g_wkv (attn-weighted kv, bf16 flat).
__global__ void __launch_bounds__(512)
k_attn(const float* __restrict__ key_pos,
       const float* __restrict__ query_pos,
       const float* __restrict__ kpe_w,
       const float* __restrict__ kpe_b) {
    extern __shared__ float sm[];
    float* kv = sm;                     // [8][16][CP]
    float* mb = kv + 8*16*CP;           // [8][8][CP]   (m rows from g_m)
    float* at = mb + 8*8*CP;            // [8][8][16]   (scores, then attn)
    float* pes = at + 8*128;            // [4][256]  kpe SoA: w0,w1,w2,b
    float* qc = pes + 4*256;            // [8][4]
    int*  sid = (int*)(qc + 32);        // [8][16]

    int t = threadIdx.x, lane = t & 31, w = t >> 5;   // 16 warps
    int bq0 = blockIdx.x * 8;
    int b = bq0 >> 10;   // NQ=1024

    if (t < 128) sid[t] = g_sidx[bq0*SKEYS + t];
    if (t < 24) { int g = t/3, j = t%3; qc[g*4 + j] = query_pos[(size_t)(bq0+g)*6 + j]; }
    if (t < 256) {   // kpe SoA staging
        pes[0*256 + t] = kpe_w[t*3 + 0];
        pes[1*256 + t] = kpe_w[t*3 + 1];
        pes[2*256 + t] = kpe_w[t*3 + 2];
        pes[3*256 + t] = kpe_b[t];
    }
    // load m rows: 4096 float4 (g_m[(bq0+g)][h*256 + c]) -> mb[(g*8+h)*CP + c]
#pragma unroll
    for (int i = 0; i < 8; i++) {
        int v = t + 512*i;
        int g = v >> 9, rem = v & 511;       // rem = h*64 + c4
        int h = rem >> 6, c4 = rem & 63;
        *(float4*)&mb[(g*8 + h)*CP + c4*4] =
            *(const float4*)&g_m[(size_t)(bq0 + g)*HC + rem*4];
    }
    __syncthreads();

    // phase 1: gather kv = keyT[idx] + kpe(gxyz)   (warp = (g, s-half))
    {
        int g = w >> 1, sh = w & 1;
        float qcx = qc[g*4+0], qcy = qc[g*4+1], qcz = qc[g*4+2];
        for (int si = 0; si < 8; si++) {
            int s = sh*8 + si;
            int v = sid[g*16 + s];
            int kidx = v < 0 ? 0 : v;
            int base = b*NKD + kidx;
            float gx = key_pos[base*3+0] - qcx;
            float gy = key_pos[base*3+1] - qcy;
            float gz = key_pos[base*3+2] - qcz;
            const float4* krow4 = (const float4*)(g_keyT + (size_t)base*CDIM);
            float* kvrow = kv + (g*16 + s)*CP;
#pragma unroll
            for (int i = 0; i < 2; i++) {
                int c4 = lane + 32*i;
                float4 kr = krow4[c4];
                float4 w0 = *(const float4*)&pes[0*256 + 4*c4];
                float4 w1 = *(const float4*)&pes[1*256 + 4*c4];
                float4 w2 = *(const float4*)&pes[2*256 + 4*c4];
                float4 bb = *(const float4*)&pes[3*256 + 4*c4];
                float4 r;
                r.x = kr.x + bb.x + gx*w0.x + gy*w1.x + gz*w2.x;
                r.y = kr.y + bb.y + gx*w0.y + gy*w1.y + gz*w2.y;
                r.z = kr.z + bb.z + gx*w0.z + gy*w1.z + gz*w2.z;
                r.w = kr.w + bb.w + gx*w0.w + gy*w1.w + gz*w2.w;
                *(float4*)&kvrow[4*c4] = r;
            }
        }
    }
    __syncthreads();

    // phase 3: scores[g][h][s] = m[g][h] . kv[g][s]  (warp = (g, h-half); lane = (h4, s0))
    {
        int g = w >> 1, hh = w & 1;
        int h = hh*4 + (lane >> 3), s0 = lane & 7;
        float sc[2] = {0.f, 0.f};
        const float4* m4 = (const float4*)(mb + (g*8 + h)*CP);
        const float4* kv0 = (const float4*)(kv + (g*16 + s0)*CP);
        const float4* kv1 = (const float4*)(kv + (g*16 + s0 + 8)*CP);
        for (int c4 = 0; c4 < 64; c4++) {
            float4 mv = m4[c4];
            float4 k0 = kv0[c4], k1 = kv1[c4];
            sc[0] += mv.x*k0.x + mv.y*k0.y + mv.z*k0.z + mv.w*k0.w;
            sc[1] += mv.x*k1.x + mv.y*k1.y + mv.z*k1.z + mv.w*k1.w;
        }
        at[(g*8 + h)*16 + s0]     = sc[0];
        at[(g*8 + h)*16 + s0 + 8] = sc[1];
    }
    __syncthreads();

    // phase 4: masked softmax (one thread per (g,h))
    if (t < 64) {
        int g = t >> 3, h = t & 7;
        float* row = at + (g*8 + h)*16;
        const int* sg = sid + g*16;
        const float scl = 0.17677669529663687f;   // 1/sqrt(32)
        float sv[16];
        float mx = -3.0e38f;
#pragma unroll
        for (int s = 0; s < 16; s++) {
            sv[s] = (sg[s] < 0) ? -3.0e38f : row[s]*scl;
            mx = fmaxf(mx, sv[s]);
        }
        float sum = 0.f;
#pragma unroll
        for (int s = 0; s < 16; s++) {
            float e = (sg[s] < 0) ? 0.f : __expf(sv[s] - mx);
            sv[s] = e; sum += e;
        }
        float inv = 1.f/sum;
#pragma unroll
        for (int s = 0; s < 16; s++) row[s] = sv[s]*inv;
    }
    __syncthreads();

    // phase 5: wkv[g][h*256+c] = sum_s attn[g][h][s]*kv[g][s][c] -> g_wkv (bf16)
    {
        int g = w >> 1, ch = w & 1;
        int cb = ch*128 + lane*4;
        float acc[8][4];   // [h][cc]
#pragma unroll
        for (int i = 0; i < 8; i++)
#pragma unroll
            for (int j = 0; j < 4; j++) acc[i][j] = 0.f;
        for (int s = 0; s < 16; s++) {
            float av[8];
#pragma unroll
            for (int h = 0; h < 8; h++) av[h] = at[(g*8 + h)*16 + s];
            float4 kk = *(const float4*)(kv + (g*16 + s)*CP + cb);
#pragma unroll
            for (int h = 0; h < 8; h++) {
                acc[h][0] += av[h]*kk.x; acc[h][1] += av[h]*kk.y;
                acc[h][2] += av[h]*kk.z; acc[h][3] += av[h]*kk.w;
            }
        }
        bf16* dst = g_wkv + (size_t)(bq0 + g)*HC + cb;
#pragma unroll
        for (int h = 0; h < 8; h++) {
            __nv_bfloat162 lo = __floats2bfloat162_rn(acc[h][0], acc[h][1]);
            __nv_bfloat162 hi = __floats2bfloat162_rn(acc[h][2], acc[h][3]);
            uint2 u;
            u.x = *(uint32_t*)&lo; u.y = *(uint32_t*)&hi;
            *(uint2*)(dst + h*256) = u;
        }
    }
}

// ---------------- layernorm of (ra + rb + rc), writes full f32 + bf16 ----------
__global__ void k_ln(const float* __restrict__ ra, const float* __restrict__ rb,
                     const float* __restrict__ rc,
                     const float* __restrict__ gamma, const float* __restrict__ beta,
                     float* __restrict__ out, bf16* __restrict__ outr) {
    int bq = blockIdx.x * 8 + (threadIdx.x >> 5);
    int lane = threadIdx.x & 31;
    float v[8];
    float s = 0.f;
#pragma unroll
    for (int i = 0; i < 8; i++) {
        int c = lane + 32*i;
        v[i] = ra[(size_t)bq*CDIM + c] + rb[(size_t)bq*CDIM + c] + rc[(size_t)bq*CDIM + c];
        s += v[i];
    }
#pragma unroll
    for (int o = 16; o; o >>= 1) s += __shfl_xor_sync(0xffffffffu, s, o);
    float mean = s * (1.f/256.f);
    float vs = 0.f;
#pragma unroll
    for (int i = 0; i < 8; i++) { float d = v[i]-mean; vs += d*d; }
#pragma unroll
    for (int o = 16; o; o >>= 1) vs += __shfl_xor_sync(0xffffffffu, vs, o);
    float rstd = rsqrtf(vs*(1.f/256.f) + 1e-5f);
#pragma unroll
    for (int i = 0; i < 8; i++) {
        int c = lane + 32*i;
        float r = (v[i]-mean)*rstd*gamma[c] + beta[c];
        out [(size_t)bq*CDIM + c] = r;
        outr[(size_t)bq*CDIM + c] = __float2bfloat16_rn(r);
    }
}

// ---------------- final LN2 + coalesced transpose to (B, C, NQ): 32 bq/block ------
__global__ void __launch_bounds__(256)
k_ln_out(const float* __restrict__ ra, const float* __restrict__ rb,
         const float* __restrict__ rc,
         const float* __restrict__ gamma, const float* __restrict__ beta,
         float* __restrict__ out) {
    __shared__ float tile[256][33];
    int t = threadIdx.x, lane = t & 31, w = t >> 5;
    int bq0 = blockIdx.x * 32;
    int b = bq0 >> 10, nq0 = bq0 & 1023;

    for (int rep = 0; rep < 4; rep++) {
        int bqL = w*4 + rep;
        size_t base = (size_t)(bq0 + bqL)*CDIM;
        float v[8];
        float s = 0.f;
#pragma unroll
        for (int i = 0; i < 8; i++) {
            int c = lane + 32*i;
            v[i] = ra[base + c] + rb[base + c] + rc[base + c];
            s += v[i];
        }
#pragma unroll
        for (int o = 16; o; o >>= 1) s += __shfl_xor_sync(0xffffffffu, s, o);
        float mean = s * (1.f/256.f);
        float vs = 0.f;
#pragma unroll
        for (int i = 0; i < 8; i++) { float d = v[i]-mean; vs += d*d; }
#pragma unroll
        for (int o = 16; o; o >>= 1) vs += __shfl_xor_sync(0xffffffffu, vs, o);
        float rstd = rsqrtf(vs*(1.f/256.f) + 1e-5f);
#pragma unroll
        for (int i = 0; i < 8; i++) {
            int c = lane + 32*i;
            tile[c][bqL] = (v[i]-mean)*rstd*gamma[c] + beta[c];
        }
    }
    __syncthreads();

#pragma unroll
    for (int i = 0; i < 32; i++) {
        int c = w*32 + i;
        out[((size_t)b*CDIM + c)*NQD + nq0 + lane] = tile[c][lane];
    }
}

// ---------------- launch ----------------
extern "C" void kernel_launch(void* const* d_in, const int* in_sizes, int n_in,
                              void* d_out, int out_size) {
    const float* query     = (const float*)d_in[0];
    const float* key       = (const float*)d_in[1];
    const float* query_pos = (const float*)d_in[2];
    const float* key_pos   = (const float*)d_in[3];
    const float* q_w   = (const float*)d_in[4];
    const float* q_b   = (const float*)d_in[5];
    const float* k_w   = (const float*)d_in[6];
    // d_in[7] = k_b: cancels in softmax (uniform shift per (bq,h))
    const float* v_w   = (const float*)d_in[8];
    const float* v_b   = (const float*)d_in[9];
    const float* o_w   = (const float*)d_in[10];
    const float* o_b   = (const float*)d_in[11];
    const float* lin1_w = (const float*)d_in[12];
    const float* lin1_b = (const float*)d_in[13];
    const float* lin2_w = (const float*)d_in[14];
    const float* lin2_b = (const float*)d_in[15];
    const float* n1_g = (const float*)d_in[16];
    const float* n1_b = (const float*)d_in[17];
    const float* n2_g = (const float*)d_in[18];
    const float* n2_b = (const float*)d_in[19];
    const float* qpe_w = (const float*)d_in[20];
    const float* qpe_b = (const float*)d_in[21];
    const float* kpe_w = (const float*)d_in[22];
    const float* kpe_b = (const float*)d_in[23];

    void *p_qin, *p_m, *p_wkv, *p_res1, *p_qtok, *p_x, *p_xr, *p_ff, *p_y;
    void *p_w2, *p_w3, *p_mbias, *p_b3, *p_l1r, *p_l2r;
    cudaGetSymbolAddress(&p_qin,  g_qin);
    cudaGetSymbolAddress(&p_m,    g_m);
    cudaGetSymbolAddress(&p_wkv,  g_wkv);
    cudaGetSymbolAddress(&p_res1, g_res1);
    cudaGetSymbolAddress(&p_qtok, g_qtok);
    cudaGetSymbolAddress(&p_x,    g_x);
    cudaGetSymbolAddress(&p_xr,   g_xr);
    cudaGetSymbolAddress(&p_ff,   g_ff);
    cudaGetSymbolAddress(&p_y,    g_y);
    cudaGetSymbolAddress(&p_w2,   g_w2);
    cudaGetSymbolAddress(&p_w3,   g_w3);
    cudaGetSymbolAddress(&p_mbias, g_mbias);
    cudaGetSymbolAddress(&p_b3,   g_b3);
    cudaGetSymbolAddress(&p_l1r,  g_l1r);
    cudaGetSymbolAddress(&p_l2r,  g_l2r);

    const size_t SLICE = (size_t)BQTOT * CDIM;

    const int attn_smem = (8*16*CP + 8*8*CP + 8*128 + 4*256 + 32)*4 + 128*4;
    cudaFuncSetAttribute(k_attn, cudaFuncAttributeMaxDynamicSharedMemorySize, attn_smem);

    const int gemm_smem = 2 * STAGE_H * 2;    // 73,728 bytes (2 stages, bf16)
    cudaFuncSetAttribute(k_gemm_bf<0,0>, cudaFuncAttributeMaxDynamicSharedMemorySize, gemm_smem);
    cudaFuncSetAttribute(k_gemm_bf<1,1>, cudaFuncAttributeMaxDynamicSharedMemorySize, gemm_smem);

    // streams/events: SAME topology as the R10 passing run (3 side streams, 4 events)
    static cudaStream_t s1 = nullptr, s2 = nullptr, s3 = nullptr;
    static cudaEvent_t  evR = nullptr, e1 = nullptr, e2 = nullptr, e3 = nullptr;
    if (!s1) {
        cudaStreamCreateWithFlags(&s1, cudaStreamNonBlocking);
        cudaStreamCreateWithFlags(&s2, cudaStreamNonBlocking);
        cudaStreamCreateWithFlags(&s3, cudaStreamNonBlocking);
        cudaEventCreateWithFlags(&evR, cudaEventDisableTiming);
        cudaEventCreateWithFlags(&e1,  cudaEventDisableTiming);
        cudaEventCreateWithFlags(&e2,  cudaEventDisableTiming);
        cudaEventCreateWithFlags(&e3,  cudaEventDisableTiming);
    }

    // ---- fork ----
    cudaEventRecord(evR, 0);
    cudaStreamWaitEvent(s1, evR, 0);
    cudaStreamWaitEvent(s2, evR, 0);
    cudaStreamWaitEvent(s3, evR, 0);

    // s1: key transpose
    k_transpose_key<<<dim3(NKD/32, CDIM/32, BATCH), dim3(32,8), 0, s1>>>(key);
    // s3: box query
    k_boxquery<<<dim3(NQD/32, BATCH), 1024, 0, s3>>>(key_pos, query_pos);
    // s2: FFN weight rounds + fused W3/b3 prep
    k_round<<<FFDIM*CDIM/256, 256, 0, s2>>>(lin1_w, (bf16*)p_l1r, FFDIM*CDIM);
    k_round<<<CDIM*FFDIM/256, 256, 0, s2>>>(lin2_w, (bf16*)p_l2r, CDIM*FFDIM);
    k_prep_w3<<<32, 256, 0, s2>>>(o_w, v_w);
    k_prep_b3<<<1, 256, 0, s2>>>(o_w, o_b, v_b);
    // default: build_q -> W2 prep -> m-GEMM (m = qin @ W2^T + mbias)
    k_build_q<<<dim3(NQD/32, CDIM/32, BATCH), dim3(32,8)>>>(query, query_pos, qpe_w, qpe_b);
    k_prep_w2<<<64, 256>>>(q_w, k_w, q_b);
    k_gemm_bf<0,0><<<dim3(HC/128, BQTOT/128, 1), 256, gemm_smem>>>(
        (const bf16*)p_qin, (const bf16*)p_w2, (const float*)p_mbias, p_m,
        HC, CDIM, 256, 0);

    // ---- join s1, s3 -> attn ----
    cudaEventRecord(e1, s1);
    cudaEventRecord(e3, s3);
    cudaStreamWaitEvent(0, e1, 0);
    cudaStreamWaitEvent(0, e3, 0);
    k_attn<<<BQTOT/8, 512, attn_smem>>>(key_pos, query_pos, kpe_w, kpe_b);

    // ---- join s2 -> fused o-projection: res1 = wkv @ W3^T + b3 (split-K x2) ----
    cudaEventRecord(e2, s2);
    cudaStreamWaitEvent(0, e2, 0);
    k_gemm_bf<0,0><<<dim3(CDIM/128, BQTOT/128, 2), 256, gemm_smem>>>(
        (const bf16*)p_wkv, (const bf16*)p_w3, (const float*)p_b3, p_res1,
        CDIM, HC, 1024, SLICE);

    // LN1(qtok + res1a + res1b) -> x (f32) + xr (bf16)
    k_ln<<<BQTOT/8, 256>>>((const float*)p_qtok, (const float*)p_res1,
                           (const float*)p_res1 + SLICE, n1_g, n1_b,
                           (float*)p_x, (bf16*)p_xr);

    // FFN
    k_gemm_bf<1,1><<<dim3(FFDIM/128, BQTOT/128, 1), 256, gemm_smem>>>(
        (const bf16*)p_xr, (const bf16*)p_l1r, lin1_b, p_ff,
        FFDIM, CDIM, 256, 0);
    k_gemm_bf<0,0><<<dim3(CDIM/128, BQTOT/128, 2), 256, gemm_smem>>>(
        (const bf16*)p_ff, (const bf16*)p_l2r, lin2_b, p_y,
        CDIM, FFDIM, 1024, SLICE);

    // LN2(x + y0 + y1) + coalesced transpose out
    k_ln_out<<<BQTOT/32, 256>>>((const float*)p_x, (const float*)p_y,
                                (const float*)p_y + SLICE, n2_g, n2_b, (float*)d_out);
}

// round 16
// speedup vs baseline: 4.9379x; 1.0549x over previous
#include <cuda_runtime.h>
#include <cuda_bf16.h>
#include <math.h>
#include <stdint.h>

#define BATCH 8
#define CDIM  256
#define NQD   1024
#define NKD   4096
#define SKEYS 16
#define HEADS 8
#define FFDIM 2048
#define DHD   32
#define BQTOT (BATCH*NQD)
#define CP    260   // padded smem stride (attn kernel; 16B-aligned rows)
#define HC    2048  // HEADS*CDIM
#define QB    4     // queries per attn block

typedef __nv_bfloat16 bf16;

// ---------------- scratch (device globals; no allocation allowed) ----------------
__device__ float g_keyT[BATCH*NKD*CDIM];     // key transposed (B, NK, C)
__device__ float g_qtok[BQTOT*CDIM];         // transposed query tokens (residual)
__device__ bf16  g_qin [BQTOT*CDIM];         // qtok + qpe (bf16, GEMM A)
__device__ bf16  g_m   [(size_t)BQTOT*HC];   // fused q*W2 scores operand (bf16)
__device__ int   g_sidx[BQTOT*SKEYS];        // gathered key indices (-1 = masked)
__device__ bf16  g_wkv [(size_t)BQTOT*HC];   // attn-weighted kv, flat (bf16)
__device__ float g_res1[2*BQTOT*CDIM];       // fused o-proj output (2 split-K slices)
__device__ float g_x   [BQTOT*CDIM];         // after LN1 (residual)
__device__ bf16  g_xr  [BQTOT*CDIM];         // after LN1 (bf16, GEMM A)
__device__ bf16  g_ff  [BQTOT*FFDIM];        // FFN hidden (bf16, GEMM A)
__device__ float g_y   [2*BQTOT*CDIM];       // FFN out (2 slices)
// fused / rounded weights
__device__ bf16  g_w2  [HC*CDIM];            // W2[h*256+c][e]
__device__ float g_mbias[HC];                // k_w^T q_b
__device__ bf16  g_w3  [CDIM*HC];            // W3[n][h*256+c]
__device__ float g_b3  [CDIM];               // o_b + o_w @ v_b
__device__ bf16  g_l1r [FFDIM*CDIM];
__device__ bf16  g_l2r [CDIM*FFDIM];

// ---------------- small PTX helpers ----------------
__device__ __forceinline__ uint32_t smem_u32(const void* p) {
    uint32_t a;
    asm("{ .reg .u64 t; cvta.to.shared.u64 t, %1; cvt.u32.u64 %0, t; }" : "=r"(a) : "l"(p));
    return a;
}
__device__ __forceinline__ void cp16(uint32_t s, const void* g) {
    asm volatile("cp.async.cg.shared.global [%0], [%1], 16;" :: "r"(s), "l"(g));
}
#define CP_COMMIT() asm volatile("cp.async.commit_group;" ::: "memory")
#define CP_WAIT1()  asm volatile("cp.async.wait_group 1;" ::: "memory")

#define LDSM4(R0,R1,R2,R3, ADDR) \
    asm volatile("ldmatrix.sync.aligned.m8n8.x4.shared.b16 {%0,%1,%2,%3}, [%4];" \
        : "=r"(R0), "=r"(R1), "=r"(R2), "=r"(R3) : "r"(ADDR))

__device__ __forceinline__ void mma_bf16(float* d,
                                         uint32_t a0, uint32_t a1, uint32_t a2, uint32_t a3,
                                         uint32_t b0, uint32_t b1) {
    asm volatile(
        "mma.sync.aligned.m16n8k16.row.col.f32.bf16.bf16.f32 "
        "{%0,%1,%2,%3}, {%4,%5,%6,%7}, {%8,%9}, {%0,%1,%2,%3};"
        : "+f"(d[0]), "+f"(d[1]), "+f"(d[2]), "+f"(d[3])
        : "r"(a0), "r"(a1), "r"(a2), "r"(a3), "r"(b0), "r"(b1));
}

// ---------------- bf16 mma.sync GEMM: C = A(M,lda) @ W(N,lda)^T (+ bias on z=0) ----
#define PADB 72                  // bf16 elems per smem row (144B, conflict-free)
#define STAGE_H (2*128*PADB)     // bf16 elems per stage (A + B)

template<int RELU, int OUTBF>
__global__ void __launch_bounds__(256)
k_gemm_bf(const bf16* __restrict__ A, const bf16* __restrict__ W,
          const float* __restrict__ bias, void* __restrict__ Cout,
          int N, int lda, int KS, size_t outStride) {
    extern __shared__ bf16 smh[];
    int t = threadIdx.x, lane = t & 31, wid = t >> 5;
    int wm = wid >> 1, wn = wid & 1;          // warp tile origin (wm*32, wn*64)
    int bm = blockIdx.y * 128, bn = blockIdx.x * 128;
    int kb = blockIdx.z * KS;
    const int NC = KS >> 6;
    int qr = lane >> 2, qc = lane & 3;        // quad row / quad col (epilogue)

    // ldmatrix per-lane addressing
    int lrowA = (lane & 7) + ((lane >> 3) & 1) * 8;   // 0..15
    int lsegA = (lane >> 4) * 8;                      // 0 or 8 (bf16 elems)
    int lrowB = ((lane >> 4) * 8) + (lane & 7);       // 0..15
    int lsegB = ((lane >> 3) & 1) * 8;
    uint32_t smbase = smem_u32(smh);
    uint32_t aoff = (uint32_t)(((wm*32 + lrowA)*PADB + lsegA) * 2);
    uint32_t boff = (uint32_t)((128*PADB + (wn*64 + lrowB)*PADB + lsegB) * 2);

    float acc[2][8][4];
#pragma unroll
    for (int mi = 0; mi < 2; mi++)
#pragma unroll
        for (int ni = 0; ni < 8; ni++)
#pragma unroll
            for (int j = 0; j < 4; j++) acc[mi][ni][j] = 0.f;

    // stage 0 prologue: chunk 0 (64 bf16 per row = 8 segs of 8)
    {
        bf16* As = smh; bf16* Bs = smh + 128*PADB;
        for (int u = t; u < 1024; u += 256) {
            int row = u >> 3, seg = u & 7;
            cp16(smem_u32(As + row*PADB + seg*8), A + (size_t)(bm + row)*lda + kb + seg*8);
            cp16(smem_u32(Bs + row*PADB + seg*8), W + (size_t)(bn + row)*lda + kb + seg*8);
        }
    }
    CP_COMMIT();

    for (int c = 0; c < NC; c++) {
        __syncthreads();                       // stage (c+1)&1 free (compute c-1 done)
        if (c + 1 < NC) {
            bf16* As = smh + ((c+1)&1)*STAGE_H;
            bf16* Bs = As + 128*PADB;
            int k0 = kb + (c+1)*64;
            for (int u = t; u < 1024; u += 256) {
                int row = u >> 3, seg = u & 7;
                cp16(smem_u32(As + row*PADB + seg*8), A + (size_t)(bm + row)*lda + k0 + seg*8);
                cp16(smem_u32(Bs + row*PADB + seg*8), W + (size_t)(bn + row)*lda + k0 + seg*8);
            }
        }
        CP_COMMIT();
        CP_WAIT1();                            // stage c copies done (this thread)
        __syncthreads();                       // all threads' stage-c copies visible

        uint32_t sb = smbase + ((c & 1) ? (uint32_t)(STAGE_H*2) : 0u);
        uint32_t aB = sb + aoff, bB = sb + boff;
#pragma unroll
        for (int kk = 0; kk < 4; kk++) {
            uint32_t a0[4], a1[4], bf[8][2];
            LDSM4(a0[0], a0[1], a0[2], a0[3], aB + kk*32);
            LDSM4(a1[0], a1[1], a1[2], a1[3], aB + 16*PADB*2 + kk*32);
#pragma unroll
            for (int j = 0; j < 4; j++)
                LDSM4(bf[2*j][0], bf[2*j][1], bf[2*j+1][0], bf[2*j+1][1],
                      bB + j*16*PADB*2 + kk*32);
#pragma unroll
            for (int ni = 0; ni < 8; ni++) {
                mma_bf16(acc[0][ni], a0[0], a0[1], a0[2], a0[3], bf[ni][0], bf[ni][1]);
                mma_bf16(acc[1][ni], a1[0], a1[1], a1[2], a1[3], bf[ni][0], bf[ni][1]);
            }
        }
    }

    // epilogue: direct stores; bias only on z=0
    bool addb = (blockIdx.z == 0);
#pragma unroll
    for (int mi = 0; mi < 2; mi++) {
        int r0 = bm + wm*32 + mi*16 + qr;
#pragma unroll
        for (int ni = 0; ni < 8; ni++) {
            int cn = bn + wn*64 + ni*8 + qc*2;
            float b0 = addb ? bias[cn] : 0.f, b1 = addb ? bias[cn+1] : 0.f;
            float v0 = acc[mi][ni][0] + b0, v1 = acc[mi][ni][1] + b1;
            float v2 = acc[mi][ni][2] + b0, v3 = acc[mi][ni][3] + b1;
            if (RELU) { v0=fmaxf(v0,0.f); v1=fmaxf(v1,0.f); v2=fmaxf(v2,0.f); v3=fmaxf(v3,0.f); }
            if (OUTBF) {
                bf16* C = (bf16*)Cout;
                *(__nv_bfloat162*)&C[(size_t)r0*N + cn]     = __floats2bfloat162_rn(v0, v1);
                *(__nv_bfloat162*)&C[(size_t)(r0+8)*N + cn] = __floats2bfloat162_rn(v2, v3);
            } else {
                float* C = (float*)Cout + (size_t)blockIdx.z * outStride;
                *(float2*)&C[(size_t)r0*N + cn]     = make_float2(v0, v1);
                *(float2*)&C[(size_t)(r0+8)*N + cn] = make_float2(v2, v3);
            }
        }
    }
}

// ---------------- elementwise f32 -> bf16 (vectorized x4) ----------------
__global__ void k_round(const float* __restrict__ in, bf16* __restrict__ out, int n4) {
    int i = blockIdx.x * 256 + threadIdx.x;
    if (i < n4) {
        float4 v = ((const float4*)in)[i];
        __nv_bfloat162 lo = __floats2bfloat162_rn(v.x, v.y);
        __nv_bfloat162 hi = __floats2bfloat162_rn(v.z, v.w);
        uint2 u; u.x = *(uint32_t*)&lo; u.y = *(uint32_t*)&hi;
        ((uint2*)out)[i] = u;
    }
}

// ---------------- W2 prep: W2[h*256+c][e] = sum_d q_w[hd,e]*k_w[hd,c]; mbias = k_w^T q_b
__global__ void __launch_bounds__(256)
k_prep_w2(const float* __restrict__ qw, const float* __restrict__ kw,
          const float* __restrict__ qb) {
    __shared__ float kc[32][33];
    __shared__ float qbs[32];
    int h = blockIdx.x >> 3, c0 = (blockIdx.x & 7) * 32;
    int t = threadIdx.x;
    for (int u = t; u < 1024; u += 256) {
        int d = u >> 5, cl = u & 31;
        kc[d][cl] = kw[(size_t)(h*32 + d)*CDIM + c0 + cl];
    }
    if (t < 32) qbs[t] = qb[h*32 + t];
    __syncthreads();
    float qe[32];
#pragma unroll
    for (int d = 0; d < 32; d++) qe[d] = qw[(size_t)(h*32 + d)*CDIM + t];
    for (int cl = 0; cl < 32; cl++) {
        float s = 0.f;
#pragma unroll
        for (int d = 0; d < 32; d++) s += qe[d]*kc[d][cl];
        g_w2[(size_t)(h*256 + c0 + cl)*CDIM + t] = __float2bfloat16_rn(s);
    }
    if (t < 32) {
        float s = 0.f;
#pragma unroll
        for (int d = 0; d < 32; d++) s += kc[d][t]*qbs[d];
        g_mbias[h*256 + c0 + t] = s;
    }
}

// ---------------- W3 prep: W3[n][h*256+c] = sum_d o_w[n,hd]*v_w[hd,c] ----------------
__global__ void __launch_bounds__(256)
k_prep_w3(const float* __restrict__ ow, const float* __restrict__ vw) {
    __shared__ float os[64][33];
    int h = blockIdx.x >> 2, n0 = (blockIdx.x & 3) * 64;
    int t = threadIdx.x;
    for (int u = t; u < 2048; u += 256) {
        int nl = u >> 5, d = u & 31;
        os[nl][d] = ow[(size_t)(n0 + nl)*CDIM + h*32 + d];
    }
    float vd[32];
#pragma unroll
    for (int d = 0; d < 32; d++) vd[d] = vw[(size_t)(h*32 + d)*CDIM + t];
    __syncthreads();
    for (int nl = 0; nl < 64; nl++) {
        float s = 0.f;
#pragma unroll
        for (int d = 0; d < 32; d++) s += os[nl][d]*vd[d];
        g_w3[(size_t)(n0 + nl)*HC + h*256 + t] = __float2bfloat16_rn(s);
    }
}

// ---------------- b3 prep: b3[n] = o_b[n] + o_w[n,:] @ v_b ----------------
__global__ void __launch_bounds__(256)
k_prep_b3(const float* __restrict__ ow, const float* __restrict__ ob,
          const float* __restrict__ vb) {
    __shared__ float vbs[256];
    int t = threadIdx.x;
    vbs[t] = vb[t];
    __syncthreads();
    float s = ob[t];
    for (int k = 0; k < 256; k++) s += ow[(size_t)t*CDIM + k]*vbs[k];
    g_b3[t] = s;
}

// ---------------- transpose key (B,C,NK) -> (B,NK,C) ----------------
__global__ void k_transpose_key(const float* __restrict__ key) {
    __shared__ float tile[32][33];
    int b = blockIdx.z;
    int c0 = blockIdx.y * 32, n0 = blockIdx.x * 32;
    int tx = threadIdx.x, ty = threadIdx.y;
#pragma unroll
    for (int j = 0; j < 4; j++)
        tile[ty + 8*j][tx] = key[(b*CDIM + c0 + ty + 8*j)*NKD + n0 + tx];
    __syncthreads();
#pragma unroll
    for (int j = 0; j < 4; j++)
        g_keyT[(b*NKD + n0 + ty + 8*j)*CDIM + c0 + tx] = tile[tx][ty + 8*j];
}

// ---------------- build qtok + qin (query transpose + qpe) ----------------
__global__ void k_build_q(const float* __restrict__ query,
                          const float* __restrict__ query_pos,
                          const float* __restrict__ qpe_w,
                          const float* __restrict__ qpe_b) {
    __shared__ float tile[32][33];
    int b = blockIdx.z;
    int c0 = blockIdx.y * 32, n0 = blockIdx.x * 32;
    int tx = threadIdx.x, ty = threadIdx.y;
#pragma unroll
    for (int j = 0; j < 4; j++)
        tile[ty + 8*j][tx] = query[(b*CDIM + c0 + ty + 8*j)*NQD + n0 + tx];
    __syncthreads();
#pragma unroll
    for (int j = 0; j < 4; j++) {
        int nq = n0 + ty + 8*j, c = c0 + tx;
        int bq = b*NQD + nq;
        float qt = tile[tx][ty + 8*j];
        const float* qp = query_pos + (size_t)bq*6;
        float pe = qpe_b[c];
#pragma unroll
        for (int jj = 0; jj < 6; jj++) pe += qp[jj] * qpe_w[c*6 + jj];
        g_qtok[bq*CDIM + c] = qt;
        g_qin [bq*CDIM + c] = __float2bfloat16_rn(qt + pe);
    }
}

// ---------------- box query: 32 queries/block, first 16 inside keys ---------------
__global__ void __launch_bounds__(1024)
k_boxquery(const float* __restrict__ key_pos,
           const float* __restrict__ query_pos) {
    __shared__ float kp[NKD*3];   // exactly 48KB
    int b = blockIdx.y;
    int t = threadIdx.x;
#pragma unroll
    for (int i = 0; i < 12; i++)
        kp[t + 1024*i] = key_pos[(size_t)b*NKD*3 + t + 1024*i];
    __syncthreads();

    int w = t >> 5, lane = t & 31;
    int q = blockIdx.x * 32 + w;
    int bq = b*NQD + q;
    const float* qp = query_pos + (size_t)bq*6;
    float cx = qp[0], cy = qp[1], cz = qp[2];
    float hx = 0.5f*qp[3], hy = 0.5f*qp[4], hz = 0.5f*qp[5];

    int count = 0;
    for (int base = 0; base < NKD && count < SKEYS; base += 32) {
        int k = base + lane;
        float dx = fabsf(kp[k*3+0]-cx);
        float dy = fabsf(kp[k*3+1]-cy);
        float dz = fabsf(kp[k*3+2]-cz);
        bool inside = (dx <= hx) && (dy <= hy) && (dz <= hz);
        unsigned bal = __ballot_sync(0xffffffffu, inside);
        int nb = __popc(bal);
        if (inside) {
            int rank = __popc(bal & ((1u << lane) - 1u));
            if (count + rank < SKEYS) g_sidx[bq*SKEYS + count + rank] = k;
        }
        count += nb;
        if (count > SKEYS) count = SKEYS;
    }
    if (lane < SKEYS && lane >= count)
        g_sidx[bq*SKEYS + lane] = (lane == 0) ? 0 : -1;
}

// ---------------- fused gather + attention core (4 queries, 256 threads) ------------
// Reads g_m (bf16 scores operand); writes g_wkv (attn-weighted kv, bf16 flat).
__global__ void __launch_bounds__(256)
k_attn(const float* __restrict__ key_pos,
       const float* __restrict__ query_pos,
       const float* __restrict__ kpe_w,
       const float* __restrict__ kpe_b) {
    extern __shared__ float sm[];
    float* kv = sm;                     // [QB][16][CP]
    float* mb = kv + QB*16*CP;          // [QB][8][CP]   (m rows from g_m)
    float* at = mb + QB*8*CP;           // [QB][8][16]   (scores, then attn)
    float* pes = at + QB*128;           // [4][256]  kpe SoA: w0,w1,w2,b
    float* qc = pes + 4*256;            // [QB][4]
    int*  sid = (int*)(qc + 4*QB);      // [QB][16]

    int t = threadIdx.x, lane = t & 31, w = t >> 5;   // 8 warps
    int bq0 = blockIdx.x * QB;
    int b = bq0 >> 10;   // NQ=1024

    if (t < QB*SKEYS) sid[t] = g_sidx[bq0*SKEYS + t];
    if (t < QB*3) { int g = t/3, j = t%3; qc[g*4 + j] = query_pos[(size_t)(bq0+g)*6 + j]; }
    {   // kpe SoA staging
        pes[0*256 + t] = kpe_w[t*3 + 0];
        pes[1*256 + t] = kpe_w[t*3 + 1];
        pes[2*256 + t] = kpe_w[t*3 + 2];
        pes[3*256 + t] = kpe_b[t];
    }
    // load m rows (bf16 x8): QB*8*32 = 1024 uint4 loads
#pragma unroll
    for (int i = 0; i < 4; i++) {
        int v = t + 256*i;
        int g = v >> 8, rem = v & 255;       // rem = h*32 + c8
        int h = rem >> 5, c8 = rem & 31;
        uint4 u = *(const uint4*)&g_m[(size_t)(bq0 + g)*HC + h*256 + c8*8];
        float* dst = mb + (g*8 + h)*CP + c8*8;
        float2 f0 = __bfloat1622float2(*(__nv_bfloat162*)&u.x);
        float2 f1 = __bfloat1622float2(*(__nv_bfloat162*)&u.y);
        float2 f2 = __bfloat1622float2(*(__nv_bfloat162*)&u.z);
        float2 f3 = __bfloat1622float2(*(__nv_bfloat162*)&u.w);
        dst[0] = f0.x; dst[1] = f0.y; dst[2] = f1.x; dst[3] = f1.y;
        dst[4] = f2.x; dst[5] = f2.y; dst[6] = f3.x; dst[7] = f3.y;
    }
    __syncthreads();

    // phase 1: gather kv = keyT[idx] + kpe(gxyz)   (warp = (g, s-half))
    {
        int g = w >> 1, sh = w & 1;
        float qcx = qc[g*4+0], qcy = qc[g*4+1], qcz = qc[g*4+2];
        for (int si = 0; si < 8; si++) {
            int s = sh*8 + si;
            int v = sid[g*16 + s];
            int kidx = v < 0 ? 0 : v;
            int base = b*NKD + kidx;
            float gx = key_pos[base*3+0] - qcx;
            float gy = key_pos[base*3+1] - qcy;
            float gz = key_pos[base*3+2] - qcz;
            const float4* krow4 = (const float4*)(g_keyT + (size_t)base*CDIM);
            float* kvrow = kv + (g*16 + s)*CP;
#pragma unroll
            for (int i = 0; i < 2; i++) {
                int c4 = lane + 32*i;
                float4 kr = krow4[c4];
                float4 w0 = *(const float4*)&pes[0*256 + 4*c4];
                float4 w1 = *(const float4*)&pes[1*256 + 4*c4];
                float4 w2 = *(const float4*)&pes[2*256 + 4*c4];
                float4 bb = *(const float4*)&pes[3*256 + 4*c4];
                float4 r;
                r.x = kr.x + bb.x + gx*w0.x + gy*w1.x + gz*w2.x;
                r.y = kr.y + bb.y + gx*w0.y + gy*w1.y + gz*w2.y;
                r.z = kr.z + bb.z + gx*w0.z + gy*w1.z + gz*w2.z;
                r.w = kr.w + bb.w + gx*w0.w + gy*w1.w + gz*w2.w;
                *(float4*)&kvrow[4*c4] = r;
            }
        }
    }
    __syncthreads();

    // phase 3: scores[g][h][s] = m[g][h] . kv[g][s]  (warp = (g, h-half); lane = (h4, s0))
    {
        int g = w >> 1, hh = w & 1;
        int h = hh*4 + (lane >> 3), s0 = lane & 7;
        float sc[2] = {0.f, 0.f};
        const float4* m4 = (const float4*)(mb + (g*8 + h)*CP);
        const float4* kv0 = (const float4*)(kv + (g*16 + s0)*CP);
        const float4* kv1 = (const float4*)(kv + (g*16 + s0 + 8)*CP);
        for (int c4 = 0; c4 < 64; c4++) {
            float4 mv = m4[c4];
            float4 k0 = kv0[c4], k1 = kv1[c4];
            sc[0] += mv.x*k0.x + mv.y*k0.y + mv.z*k0.z + mv.w*k0.w;
            sc[1] += mv.x*k1.x + mv.y*k1.y + mv.z*k1.z + mv.w*k1.w;
        }
        at[(g*8 + h)*16 + s0]     = sc[0];
        at[(g*8 + h)*16 + s0 + 8] = sc[1];
    }
    __syncthreads();

    // phase 4: masked softmax (one thread per (g,h))
    if (t < QB*8) {
        int g = t >> 3, h = t & 7;
        float* row = at + (g*8 + h)*16;
        const int* sg = sid + g*16;
        const float scl = 0.17677669529663687f;   // 1/sqrt(32)
        float sv[16];
        float mx = -3.0e38f;
#pragma unroll
        for (int s = 0; s < 16; s++) {
            sv[s] = (sg[s] < 0) ? -3.0e38f : row[s]*scl;
            mx = fmaxf(mx, sv[s]);
        }
        float sum = 0.f;
#pragma unroll
        for (int s = 0; s < 16; s++) {
            float e = (sg[s] < 0) ? 0.f : __expf(sv[s] - mx);
            sv[s] = e; sum += e;
        }
        float inv = 1.f/sum;
#pragma unroll
        for (int s = 0; s < 16; s++) row[s] = sv[s]*inv;
    }
    __syncthreads();

    // phase 5: wkv[g][h*256+c] = sum_s attn[g][h][s]*kv[g][s][c] -> g_wkv (bf16)
    {
        int g = w >> 1, ch = w & 1;
        int cb = ch*128 + lane*4;
        float acc[8][4];   // [h][cc]
#pragma unroll
        for (int i = 0; i < 8; i++)
#pragma unroll
            for (int j = 0; j < 4; j++) acc[i][j] = 0.f;
        for (int s = 0; s < 16; s++) {
            float av[8];
#pragma unroll
            for (int h = 0; h < 8; h++) av[h] = at[(g*8 + h)*16 + s];
            float4 kk = *(const float4*)(kv + (g*16 + s)*CP + cb);
#pragma unroll
            for (int h = 0; h < 8; h++) {
                acc[h][0] += av[h]*kk.x; acc[h][1] += av[h]*kk.y;
                acc[h][2] += av[h]*kk.z; acc[h][3] += av[h]*kk.w;
            }
        }
        bf16* dst = g_wkv + (size_t)(bq0 + g)*HC + cb;
#pragma unroll
        for (int h = 0; h < 8; h++) {
            __nv_bfloat162 lo = __floats2bfloat162_rn(acc[h][0], acc[h][1]);
            __nv_bfloat162 hi = __floats2bfloat162_rn(acc[h][2], acc[h][3]);
            uint2 u;
            u.x = *(uint32_t*)&lo; u.y = *(uint32_t*)&hi;
            *(uint2*)(dst + h*256) = u;
        }
    }
}

// ---------------- layernorm of (ra + rb + rc), writes full f32 + bf16 ----------
__global__ void k_ln(const float* __restrict__ ra, const float* __restrict__ rb,
                     const float* __restrict__ rc,
                     const float* __restrict__ gamma, const float* __restrict__ beta,
                     float* __restrict__ out, bf16* __restrict__ outr) {
    int bq = blockIdx.x * 8 + (threadIdx.x >> 5);
    int lane = threadIdx.x & 31;
    float v[8];
    float s = 0.f;
#pragma unroll
    for (int i = 0; i < 8; i++) {
        int c = lane + 32*i;
        v[i] = ra[(size_t)bq*CDIM + c] + rb[(size_t)bq*CDIM + c] + rc[(size_t)bq*CDIM + c];
        s += v[i];
    }
#pragma unroll
    for (int o = 16; o; o >>= 1) s += __shfl_xor_sync(0xffffffffu, s, o);
    float mean = s * (1.f/256.f);
    float vs = 0.f;
#pragma unroll
    for (int i = 0; i < 8; i++) { float d = v[i]-mean; vs += d*d; }
#pragma unroll
    for (int o = 16; o; o >>= 1) vs += __shfl_xor_sync(0xffffffffu, vs, o);
    float rstd = rsqrtf(vs*(1.f/256.f) + 1e-5f);
#pragma unroll
    for (int i = 0; i < 8; i++) {
        int c = lane + 32*i;
        float r = (v[i]-mean)*rstd*gamma[c] + beta[c];
        out [(size_t)bq*CDIM + c] = r;
        outr[(size_t)bq*CDIM + c] = __float2bfloat16_rn(r);
    }
}

// ---------------- final LN2 + coalesced transpose to (B, C, NQ): 32 bq/block ------
__global__ void __launch_bounds__(256)
k_ln_out(const float* __restrict__ ra, const float* __restrict__ rb,
         const float* __restrict__ rc,
         const float* __restrict__ gamma, const float* __restrict__ beta,
         float* __restrict__ out) {
    __shared__ float tile[256][33];
    int t = threadIdx.x, lane = t & 31, w = t >> 5;
    int bq0 = blockIdx.x * 32;
    int b = bq0 >> 10, nq0 = bq0 & 1023;

    for (int rep = 0; rep < 4; rep++) {
        int bqL = w*4 + rep;
        size_t base = (size_t)(bq0 + bqL)*CDIM;
        float v[8];
        float s = 0.f;
#pragma unroll
        for (int i = 0; i < 8; i++) {
            int c = lane + 32*i;
            v[i] = ra[base + c] + rb[base + c] + rc[base + c];
            s += v[i];
        }
#pragma unroll
        for (int o = 16; o; o >>= 1) s += __shfl_xor_sync(0xffffffffu, s, o);
        float mean = s * (1.f/256.f);
        float vs = 0.f;
#pragma unroll
        for (int i = 0; i < 8; i++) { float d = v[i]-mean; vs += d*d; }
#pragma unroll
        for (int o = 16; o; o >>= 1) vs += __shfl_xor_sync(0xffffffffu, vs, o);
        float rstd = rsqrtf(vs*(1.f/256.f) + 1e-5f);
#pragma unroll
        for (int i = 0; i < 8; i++) {
            int c = lane + 32*i;
            tile[c][bqL] = (v[i]-mean)*rstd*gamma[c] + beta[c];
        }
    }
    __syncthreads();

#pragma unroll
    for (int i = 0; i < 32; i++) {
        int c = w*32 + i;
        out[((size_t)b*CDIM + c)*NQD + nq0 + lane] = tile[c][lane];
    }
}

// ---------------- launch ----------------
extern "C" void kernel_launch(void* const* d_in, const int* in_sizes, int n_in,
                              void* d_out, int out_size) {
    const float* query     = (const float*)d_in[0];
    const float* key       = (const float*)d_in[1];
    const float* query_pos = (const float*)d_in[2];
    const float* key_pos   = (const float*)d_in[3];
    const float* q_w   = (const float*)d_in[4];
    const float* q_b   = (const float*)d_in[5];
    const float* k_w   = (const float*)d_in[6];
    // d_in[7] = k_b: cancels in softmax (uniform shift per (bq,h))
    const float* v_w   = (const float*)d_in[8];
    const float* v_b   = (const float*)d_in[9];
    const float* o_w   = (const float*)d_in[10];
    const float* o_b   = (const float*)d_in[11];
    const float* lin1_w = (const float*)d_in[12];
    const float* lin1_b = (const float*)d_in[13];
    const float* lin2_w = (const float*)d_in[14];
    const float* lin2_b = (const float*)d_in[15];
    const float* n1_g = (const float*)d_in[16];
    const float* n1_b = (const float*)d_in[17];
    const float* n2_g = (const float*)d_in[18];
    const float* n2_b = (const float*)d_in[19];
    const float* qpe_w = (const float*)d_in[20];
    const float* qpe_b = (const float*)d_in[21];
    const float* kpe_w = (const float*)d_in[22];
    const float* kpe_b = (const float*)d_in[23];

    void *p_qin, *p_m, *p_wkv, *p_res1, *p_qtok, *p_x, *p_xr, *p_ff, *p_y;
    void *p_w2, *p_w3, *p_mbias, *p_b3, *p_l1r, *p_l2r;
    cudaGetSymbolAddress(&p_qin,  g_qin);
    cudaGetSymbolAddress(&p_m,    g_m);
    cudaGetSymbolAddress(&p_wkv,  g_wkv);
    cudaGetSymbolAddress(&p_res1, g_res1);
    cudaGetSymbolAddress(&p_qtok, g_qtok);
    cudaGetSymbolAddress(&p_x,    g_x);
    cudaGetSymbolAddress(&p_xr,   g_xr);
    cudaGetSymbolAddress(&p_ff,   g_ff);
    cudaGetSymbolAddress(&p_y,    g_y);
    cudaGetSymbolAddress(&p_w2,   g_w2);
    cudaGetSymbolAddress(&p_w3,   g_w3);
    cudaGetSymbolAddress(&p_mbias, g_mbias);
    cudaGetSymbolAddress(&p_b3,   g_b3);
    cudaGetSymbolAddress(&p_l1r,  g_l1r);
    cudaGetSymbolAddress(&p_l2r,  g_l2r);

    const size_t SLICE = (size_t)BQTOT * CDIM;

    const int attn_smem = (QB*16*CP + QB*8*CP + QB*128 + 4*256 + 4*QB)*4 + QB*16*4;
    cudaFuncSetAttribute(k_attn, cudaFuncAttributeMaxDynamicSharedMemorySize, attn_smem);

    const int gemm_smem = 2 * STAGE_H * 2;    // 73,728 bytes (2 stages, bf16)
    cudaFuncSetAttribute(k_gemm_bf<0,0>, cudaFuncAttributeMaxDynamicSharedMemorySize, gemm_smem);
    cudaFuncSetAttribute(k_gemm_bf<0,1>, cudaFuncAttributeMaxDynamicSharedMemorySize, gemm_smem);
    cudaFuncSetAttribute(k_gemm_bf<1,1>, cudaFuncAttributeMaxDynamicSharedMemorySize, gemm_smem);

    // streams/events: 3 side streams (R10/R13 passing topology)
    static cudaStream_t s1 = nullptr, s2 = nullptr, s3 = nullptr;
    static cudaEvent_t  evR = nullptr, e1 = nullptr, e2 = nullptr, e3 = nullptr;
    if (!s1) {
        cudaStreamCreateWithFlags(&s1, cudaStreamNonBlocking);
        cudaStreamCreateWithFlags(&s2, cudaStreamNonBlocking);
        cudaStreamCreateWithFlags(&s3, cudaStreamNonBlocking);
        cudaEventCreateWithFlags(&evR, cudaEventDisableTiming);
        cudaEventCreateWithFlags(&e1,  cudaEventDisableTiming);
        cudaEventCreateWithFlags(&e2,  cudaEventDisableTiming);
        cudaEventCreateWithFlags(&e3,  cudaEventDisableTiming);
    }

    // ---- fork ----
    cudaEventRecord(evR, 0);
    cudaStreamWaitEvent(s1, evR, 0);
    cudaStreamWaitEvent(s2, evR, 0);
    cudaStreamWaitEvent(s3, evR, 0);

    // s1: key transpose
    k_transpose_key<<<dim3(NKD/32, CDIM/32, BATCH), dim3(32,8), 0, s1>>>(key);
    // s3: box query
    k_boxquery<<<dim3(NQD/32, BATCH), 1024, 0, s3>>>(key_pos, query_pos);
    // s2: FFN weight rounds + fused W3/b3 prep
    k_round<<<FFDIM*CDIM/1024, 256, 0, s2>>>(lin1_w, (bf16*)p_l1r, FFDIM*CDIM/4);
    k_round<<<CDIM*FFDIM/1024, 256, 0, s2>>>(lin2_w, (bf16*)p_l2r, CDIM*FFDIM/4);
    k_prep_w3<<<32, 256, 0, s2>>>(o_w, v_w);
    k_prep_b3<<<1, 256, 0, s2>>>(o_w, o_b, v_b);
    // default: build_q -> W2 prep -> m-GEMM (m = qin @ W2^T + mbias, bf16 out)
    k_build_q<<<dim3(NQD/32, CDIM/32, BATCH), dim3(32,8)>>>(query, query_pos, qpe_w, qpe_b);
    k_prep_w2<<<64, 256>>>(q_w, k_w, q_b);
    k_gemm_bf<0,1><<<dim3(HC/128, BQTOT/128, 1), 256, gemm_smem>>>(
        (const bf16*)p_qin, (const bf16*)p_w2, (const float*)p_mbias, p_m,
        HC, CDIM, 256, 0);

    // ---- join s1, s3 -> attn ----
    cudaEventRecord(e1, s1);
    cudaEventRecord(e3, s3);
    cudaStreamWaitEvent(0, e1, 0);
    cudaStreamWaitEvent(0, e3, 0);
    k_attn<<<BQTOT/QB, 256, attn_smem>>>(key_pos, query_pos, kpe_w, kpe_b);

    // ---- join s2 -> fused o-projection: res1 = wkv @ W3^T + b3 (split-K x2) ----
    cudaEventRecord(e2, s2);
    cudaStreamWaitEvent(0, e2, 0);
    k_gemm_bf<0,0><<<dim3(CDIM/128, BQTOT/128, 2), 256, gemm_smem>>>(
        (const bf16*)p_wkv, (const bf16*)p_w3, (const float*)p_b3, p_res1,
        CDIM, HC, 1024, SLICE);

    // LN1(qtok + res1a + res1b) -> x (f32) + xr (bf16)
    k_ln<<<BQTOT/8, 256>>>((const float*)p_qtok, (const float*)p_res1,
                           (const float*)p_res1 + SLICE, n1_g, n1_b,
                           (float*)p_x, (bf16*)p_xr);

    // FFN
    k_gemm_bf<1,1><<<dim3(FFDIM/128, BQTOT/128, 1), 256, gemm_smem>>>(
        (const bf16*)p_xr, (const bf16*)p_l1r, lin1_b, p_ff,
        FFDIM, CDIM, 256, 0);
    k_gemm_bf<0,0><<<dim3(CDIM/128, BQTOT/128, 2), 256, gemm_smem>>>(
        (const bf16*)p_ff, (const bf16*)p_l2r, lin2_b, p_y,
        CDIM, FFDIM, 1024, SLICE);

    // LN2(x + y0 + y1) + coalesced transpose out
    k_ln_out<<<BQTOT/32, 256>>>((const float*)p_x, (const float*)p_y,
                                (const float*)p_y + SLICE, n2_g, n2_b, (float*)d_out);
}